// round 4
// baseline (speedup 1.0000x reference)
#include <cuda_runtime.h>
#include <math.h>

#define BATCH 1024
#define MDIM  64
#define NDIM  8192
#define TM2   128                 // 2*M
#define KSPLIT 32
#define KCHUNK (NDIM / KSPLIT)    // 256

// ---------------- scratch (static device globals; no runtime alloc) --------
__device__ float g_X[BATCH * NDIM];                       // 32 MB, x real part
__device__ float g_part[(size_t)KSPLIT * BATCH * TM2];    // 16 MB split-K partials
__device__ float g_P [BATCH * TM2];                       // [Ax_r ; Ax_i]
__device__ float g_Pa[BATCH * TM2];
__device__ float g_Pb[BATCH * TM2];
__device__ float g_c [BATCH * TM2];                       // A @ r_n (block form)
__device__ float g_z [BATCH * TM2];
__device__ float g_u [BATCH * TM2];
__device__ float g_s [BATCH * TM2];
__device__ float g_M   [TM2 * TM2];                       // W W^T
__device__ float g_G   [TM2 * TM2];                       // block(A A^H)
__device__ float g_Sinv[TM2 * TM2];
__device__ float g_work[TM2 * 256];                       // Gauss-Jordan [S | I]

// ---------------- GEMM2: out[r,j] = sum_k X[r,k] * W[j,k]  (split-K) -------
// grid (rows/64, KSPLIT), 256 thr. Each block: 64 rows x 128 cols, K-chunk 256.
__global__ void gemm2_partial(const float* __restrict__ X, int ldx,
                              const float* __restrict__ W) {
    __shared__ float Xs[16][65];
    __shared__ float Ws[16][129];
    int tid = threadIdx.x;
    int ty = tid >> 5, tx = tid & 31;
    int r0 = blockIdx.x * 64;
    int k0 = blockIdx.y * KCHUNK;
    float acc[8][4];
#pragma unroll
    for (int i = 0; i < 8; i++)
#pragma unroll
        for (int l = 0; l < 4; l++) acc[i][l] = 0.f;

    for (int kb = 0; kb < KCHUNK; kb += 16) {
#pragma unroll
        for (int i = 0; i < 4; i++) {          // 64x16 X tile
            int e = tid + i * 256;
            int r = e >> 4, k = e & 15;
            Xs[k][r] = X[(size_t)(r0 + r) * ldx + k0 + kb + k];
        }
#pragma unroll
        for (int i = 0; i < 8; i++) {          // 128x16 W tile
            int e = tid + i * 256;
            int j = e >> 4, k = e & 15;
            Ws[k][j] = W[(size_t)j * NDIM + k0 + kb + k];
        }
        __syncthreads();
#pragma unroll
        for (int kk = 0; kk < 16; kk++) {
            float xr[8], wv[4];
#pragma unroll
            for (int i = 0; i < 8; i++) xr[i] = Xs[kk][ty * 8 + i];
#pragma unroll
            for (int l = 0; l < 4; l++) wv[l] = Ws[kk][tx + l * 32];
#pragma unroll
            for (int i = 0; i < 8; i++)
#pragma unroll
                for (int l = 0; l < 4; l++)
                    acc[i][l] = fmaf(xr[i], wv[l], acc[i][l]);
        }
        __syncthreads();
    }
    size_t base = ((size_t)blockIdx.y * BATCH + r0) * TM2;
#pragma unroll
    for (int i = 0; i < 8; i++)
#pragma unroll
        for (int l = 0; l < 4; l++)
            g_part[base + (size_t)(ty * 8 + i) * TM2 + tx + l * 32] = acc[i][l];
}

// deterministic fixed-order reduction of split-K partials
__global__ void reduce_part(float* __restrict__ out, int count) {
    int i = blockIdx.x * blockDim.x + threadIdx.x;
    if (i < count) {
        float s = 0.f;
#pragma unroll
        for (int ks = 0; ks < KSPLIT; ks++)
            s += g_part[(size_t)ks * BATCH * TM2 + i];
        out[i] = s;
    }
}

// ---------------- build block(A A^H), S_block, init [S|I] ------------------
// Gblock[p][q] = W[p].W[q] + sgn * W[p^64].W[q^64],  sgn = +1 same half else -1
__global__ void build_S(const float* __restrict__ log_rho) {
    int idx = blockIdx.x * blockDim.x + threadIdx.x;   // 16384
    float inv_rho = 1.f / (expf(log_rho[0]) + 1e-12f);
    int p = idx >> 7, q = idx & 127;
    float sgn = ((p < 64) == (q < 64)) ? 1.f : -1.f;
    float g = g_M[idx] + sgn * g_M[((p ^ 64) << 7) + (q ^ 64)];
    g_G[idx] = g;
    g_work[p * 256 + q]       = g + ((p == q) ? inv_rho : 0.f);
    g_work[p * 256 + 128 + q] = (p == q) ? 1.f : 0.f;
}

// one-block Gauss-Jordan (SPD, no pivoting needed; 128-wide active band)
__global__ void gauss_jordan() {
    int tid  = threadIdx.x;        // 256 threads
    int row  = tid >> 1;
    int half = tid & 1;
    for (int k = 0; k < 128; k++) {
        float pinv = 1.f / g_work[k * 256 + k];
        __syncthreads();
        if (tid <= 128) g_work[k * 256 + k + tid] *= pinv;   // cols k..k+128
        __syncthreads();
        if (row != k) {
            float f = g_work[row * 256 + k];
            int jbase = k + 1 + half * 64;
#pragma unroll 8
            for (int t = 0; t < 64; t++) {
                int j = jbase + t;                           // k+1 .. k+128
                g_work[row * 256 + j] -= f * g_work[k * 256 + j];
            }
        }
        __syncthreads();
    }
    for (int e = tid; e < 128 * 128; e += 256) {
        int p = e >> 7, q = e & 127;
        g_Sinv[e] = g_work[p * 256 + 128 + q];
    }
}

__global__ void init_zu(const float* __restrict__ y,
                        const float* __restrict__ u_in) {
    int i = blockIdx.x * blockDim.x + threadIdx.x;
    if (i < BATCH * TM2) { g_z[i] = y[i]; g_u[i] = u_in[i]; }
}

// c[b,j] = (j<64) ? Pa[j] - Pb[j+64] : Pa[j] + Pb[j-64]
__global__ void combine_c() {
    int i = blockIdx.x * blockDim.x + threadIdx.x;
    if (i < BATCH * TM2) {
        int j = i & 127;
        float pa = g_Pa[i];
        float pb = g_Pb[(i & ~127) | (j ^ 64)];
        g_c[i] = (j < 64) ? pa - pb : pa + pb;
    }
}

// ---------------- per-iteration small kernels ------------------------------
// s = rho*(z-u) - Sinv @ (c + rho * G @ (z-u)); 8 batches per 128-thread block
__global__ void s_kernel(const float* __restrict__ log_rho) {
    __shared__ float w[8][TM2];
    __shared__ float Ab[8][TM2];
    int tid = threadIdx.x;
    int b0 = blockIdx.x * 8;
    float rho = expf(log_rho[0]);
#pragma unroll
    for (int bb = 0; bb < 8; bb++)
        w[bb][tid] = g_z[(b0 + bb) * TM2 + tid] - g_u[(b0 + bb) * TM2 + tid];
    __syncthreads();
    float acc[8];
#pragma unroll
    for (int bb = 0; bb < 8; bb++) acc[bb] = 0.f;
    for (int k = 0; k < TM2; k++) {
        float g = g_G[k * TM2 + tid];          // symmetric -> coalesced
#pragma unroll
        for (int bb = 0; bb < 8; bb++) acc[bb] = fmaf(g, w[bb][k], acc[bb]);
    }
#pragma unroll
    for (int bb = 0; bb < 8; bb++)
        Ab[bb][tid] = g_c[(b0 + bb) * TM2 + tid] + rho * acc[bb];
    __syncthreads();
    float acc2[8];
#pragma unroll
    for (int bb = 0; bb < 8; bb++) acc2[bb] = 0.f;
    for (int k = 0; k < TM2; k++) {
        float sv = g_Sinv[k * TM2 + tid];      // Sinv symmetric
#pragma unroll
        for (int bb = 0; bb < 8; bb++) acc2[bb] = fmaf(sv, Ab[bb][k], acc2[bb]);
    }
#pragma unroll
    for (int bb = 0; bb < 8; bb++)
        g_s[(b0 + bb) * TM2 + tid] = rho * w[bb][tid] - acc2[bb];
}

// GEMM1: X[b,n] = relu(rn_r[b,n] + sum_k s[b,k] * W[k,n]); K=128
// grid (NDIM/64, BATCH/64), 256 thr, 4x4 microtile
__global__ void gemm1_relu(const float* __restrict__ W,
                           const float* __restrict__ rn) {
    __shared__ float As[16][65];
    __shared__ float Bs[16][65];
    int tid = threadIdx.x;
    int ty = tid >> 4, tx = tid & 15;
    int n0 = blockIdx.x * 64;
    int r0 = blockIdx.y * 64;
    float acc[4][4];
#pragma unroll
    for (int i = 0; i < 4; i++)
#pragma unroll
        for (int l = 0; l < 4; l++) acc[i][l] = 0.f;

    for (int kb = 0; kb < TM2; kb += 16) {
#pragma unroll
        for (int i = 0; i < 4; i++) {          // 64x16 s tile
            int e = tid + i * 256;
            int r = e >> 4, k = e & 15;
            As[k][r] = g_s[(r0 + r) * TM2 + kb + k];
        }
#pragma unroll
        for (int i = 0; i < 4; i++) {          // 16x64 W tile
            int e = tid + i * 256;
            int k = e >> 6, n = e & 63;
            Bs[k][n] = W[(size_t)(kb + k) * NDIM + n0 + n];
        }
        __syncthreads();
#pragma unroll
        for (int kk = 0; kk < 16; kk++) {
            float sr[4], wv[4];
#pragma unroll
            for (int i = 0; i < 4; i++) sr[i] = As[kk][ty * 4 + i];
#pragma unroll
            for (int l = 0; l < 4; l++) wv[l] = Bs[kk][tx + l * 16];
#pragma unroll
            for (int i = 0; i < 4; i++)
#pragma unroll
                for (int l = 0; l < 4; l++)
                    acc[i][l] = fmaf(sr[i], wv[l], acc[i][l]);
        }
        __syncthreads();
    }
#pragma unroll
    for (int i = 0; i < 4; i++) {
        int r = r0 + ty * 4 + i;
#pragma unroll
        for (int l = 0; l < 4; l++) {
            int n = n0 + tx + l * 16;
            float v = acc[i][l] + rn[(size_t)r * (2 * NDIM) + n];  // + rn real
            g_X[(size_t)r * NDIM + n] = fmaxf(v, 0.f);
        }
    }
}

// z/u update: v = P + u - y; z = y + v*min(1, eps/(|v|+1e-12)); u += P - z
__global__ void zu_update(const float* __restrict__ y,
                          const float* __restrict__ log_eps) {
    __shared__ float red[4];
    int b = blockIdx.x;
    int j = threadIdx.x;    // 128
    float eps = expf(log_eps[0]);
    float Pv = g_P[b * TM2 + j];
    float uv = g_u[b * TM2 + j];
    float yv = y[b * TM2 + j];
    float v = Pv + uv - yv;
    float t = v * v;
#pragma unroll
    for (int o = 16; o > 0; o >>= 1) t += __shfl_down_sync(0xffffffffu, t, o);
    if ((j & 31) == 0) red[j >> 5] = t;
    __syncthreads();
    float nrm = sqrtf(red[0] + red[1] + red[2] + red[3]);
    float scale = fminf(1.f, eps / (nrm + 1e-12f));
    float zv = yv + v * scale;
    g_z[b * TM2 + j] = zv;
    g_u[b * TM2 + j] = uv + Pv - zv;
}

// ---------------- output ---------------------------------------------------
__global__ void write_x(float* __restrict__ out) {
    int i = blockIdx.x * blockDim.x + threadIdx.x;
    if (i < BATCH * NDIM) {
        int b = i >> 13, n = i & (NDIM - 1);
        size_t base = ((size_t)b << 14);
        out[base + n] = g_X[i];          // real part (already relu'd)
        out[base + NDIM + n] = 0.f;      // imag part zero after projection
    }
}
__global__ void write_u(float* __restrict__ out) {
    int i = blockIdx.x * blockDim.x + threadIdx.x;
    if (i < BATCH * TM2)
        out[(size_t)BATCH * 2 * NDIM + i] = g_u[i];
}

// ---------------- launch ----------------------------------------------------
extern "C" void kernel_launch(void* const* d_in, const int* in_sizes, int n_in,
                              void* d_out, int out_size) {
    const float* rn   = (const float*)d_in[0];   // (1024, 2, 8192)
    const float* y    = (const float*)d_in[1];   // (1024, 2, 64) == (1024,128)
    const float* u_in = (const float*)d_in[2];   // (1024, 2, 64)
    const float* A    = (const float*)d_in[3];   // (2, 64, 8192) == W(128,8192)
    const float* lrho = (const float*)d_in[4];
    const float* leps = (const float*)d_in[5];
    float* out = (float*)d_out;
    (void)in_sizes; (void)n_in; (void)out_size;

    float *dX, *dM, *dPa, *dPb, *dP;
    cudaGetSymbolAddress((void**)&dX,  g_X);
    cudaGetSymbolAddress((void**)&dM,  g_M);
    cudaGetSymbolAddress((void**)&dPa, g_Pa);
    cudaGetSymbolAddress((void**)&dPb, g_Pb);
    cudaGetSymbolAddress((void**)&dP,  g_P);

    // M = W W^T  (rows = 128)
    gemm2_partial<<<dim3(2, KSPLIT), 256>>>(A, NDIM, A);
    reduce_part<<<(TM2 * TM2 + 255) / 256, 256>>>(dM, TM2 * TM2);
    build_S<<<64, 256>>>(lrho);
    gauss_jordan<<<1, 256>>>();
    init_zu<<<(BATCH * TM2 + 255) / 256, 256>>>(y, u_in);

    // c = A @ r_n  (loop-invariant): Pa = rn_r . W, Pb = rn_i . W
    gemm2_partial<<<dim3(BATCH / 64, KSPLIT), 256>>>(rn, 2 * NDIM, A);
    reduce_part<<<(BATCH * TM2 + 255) / 256, 256>>>(dPa, BATCH * TM2);
    gemm2_partial<<<dim3(BATCH / 64, KSPLIT), 256>>>(rn + NDIM, 2 * NDIM, A);
    reduce_part<<<(BATCH * TM2 + 255) / 256, 256>>>(dPb, BATCH * TM2);
    combine_c<<<(BATCH * TM2 + 255) / 256, 256>>>();

    for (int it = 0; it < 3; it++) {
        s_kernel<<<BATCH / 8, 128>>>(lrho);
        gemm1_relu<<<dim3(NDIM / 64, BATCH / 64), 256>>>(A, rn);
        gemm2_partial<<<dim3(BATCH / 64, KSPLIT), 256>>>(dX, NDIM, A);
        reduce_part<<<(BATCH * TM2 + 255) / 256, 256>>>(dP, BATCH * TM2);
        zu_update<<<BATCH, 128>>>(y, leps);
    }

    write_x<<<(BATCH * NDIM + 255) / 256, 256>>>(out);
    write_u<<<(BATCH * TM2 + 255) / 256, 256>>>(out);
}

// round 5
// speedup vs baseline: 1.0095x; 1.0095x over previous
#include <cuda_runtime.h>
#include <math.h>

#define BATCH 1024
#define MDIM  64
#define NDIM  8192
#define TM2   128                 // 2*M
#define KS2   32                  // split-K for gemm2
#define KCH   (NDIM / KS2)        // 256

// ---------------- scratch (static device globals; no runtime alloc) --------
__device__ float g_X[BATCH * NDIM];                        // 32 MB
__device__ float g_part[(size_t)KS2 * 2048 * TM2];         // split-K partials (33.5 MB)
__device__ float g_P [BATCH * TM2];
__device__ float g_R [2048 * TM2];                         // A-projections of rn (real/imag rows)
__device__ float g_c [BATCH * TM2];
__device__ float g_z [BATCH * TM2];
__device__ float g_u [BATCH * TM2];
__device__ float g_s [BATCH * TM2];
__device__ float g_M   [TM2 * TM2];
__device__ float g_G   [TM2 * TM2];
__device__ float g_Sinv[TM2 * TM2];
__device__ float g_work[TM2 * 256];

// ============================================================================
// GEMM2: part[ks][r][j] = sum_{k in chunk} X[r,k] * W[j,k]
// grid (rows/128, KS2), 256 threads, 128x128 tile, 8x8 micro, double-buffered.
// ============================================================================
__global__ void __launch_bounds__(256, 2)
gemm2_tile(const float* __restrict__ X, int ldx,
           const float* __restrict__ W,
           float* __restrict__ part, int rows, int kchunk) {
    __shared__ float Xs[2][8][132];
    __shared__ float Ws[2][8][132];
    int tid = threadIdx.x;
    int r0 = blockIdx.x * 128;
    int k0 = blockIdx.y * kchunk;
    int lr = tid >> 1;             // 0..127
    int lk = (tid & 1) << 2;       // 0 or 4
    int ty = tid >> 4;             // 0..15  -> rows ty*8..+7
    int tx = tid & 15;             // 0..15  -> cols tx*4..+3 and 64+tx*4..+3

    const float* Xp = X + (size_t)(r0 + lr) * ldx + k0 + lk;
    const float* Wp = W + (size_t)lr * NDIM + k0 + lk;

    float acc[8][8];
#pragma unroll
    for (int i = 0; i < 8; i++)
#pragma unroll
        for (int j = 0; j < 8; j++) acc[i][j] = 0.f;

    float4 xa = *(const float4*)Xp;
    float4 wa = *(const float4*)Wp;
    int buf = 0;
    Xs[0][lk + 0][lr] = xa.x; Xs[0][lk + 1][lr] = xa.y;
    Xs[0][lk + 2][lr] = xa.z; Xs[0][lk + 3][lr] = xa.w;
    Ws[0][lk + 0][lr] = wa.x; Ws[0][lk + 1][lr] = wa.y;
    Ws[0][lk + 2][lr] = wa.z; Ws[0][lk + 3][lr] = wa.w;
    __syncthreads();

    int nkb = kchunk >> 3;
    for (int ib = 0; ib < nkb; ib++) {
        if (ib + 1 < nkb) {
            xa = *(const float4*)(Xp + (ib + 1) * 8);
            wa = *(const float4*)(Wp + (ib + 1) * 8);
        }
#pragma unroll
        for (int kk = 0; kk < 8; kk++) {
            float4 a0 = *(const float4*)&Xs[buf][kk][ty * 8];
            float4 a1 = *(const float4*)&Xs[buf][kk][ty * 8 + 4];
            float4 b0 = *(const float4*)&Ws[buf][kk][tx * 4];
            float4 b1 = *(const float4*)&Ws[buf][kk][tx * 4 + 64];
            float a[8] = {a0.x, a0.y, a0.z, a0.w, a1.x, a1.y, a1.z, a1.w};
            float b[8] = {b0.x, b0.y, b0.z, b0.w, b1.x, b1.y, b1.z, b1.w};
#pragma unroll
            for (int i = 0; i < 8; i++)
#pragma unroll
                for (int j = 0; j < 8; j++)
                    acc[i][j] = fmaf(a[i], b[j], acc[i][j]);
        }
        if (ib + 1 < nkb) {
            int nb = buf ^ 1;
            Xs[nb][lk + 0][lr] = xa.x; Xs[nb][lk + 1][lr] = xa.y;
            Xs[nb][lk + 2][lr] = xa.z; Xs[nb][lk + 3][lr] = xa.w;
            Ws[nb][lk + 0][lr] = wa.x; Ws[nb][lk + 1][lr] = wa.y;
            Ws[nb][lk + 2][lr] = wa.z; Ws[nb][lk + 3][lr] = wa.w;
            __syncthreads();
            buf = nb;
        }
    }

    float* pb = part + ((size_t)blockIdx.y * rows + r0) * TM2;
#pragma unroll
    for (int i = 0; i < 8; i++) {
        float4 v0 = make_float4(acc[i][0], acc[i][1], acc[i][2], acc[i][3]);
        float4 v1 = make_float4(acc[i][4], acc[i][5], acc[i][6], acc[i][7]);
        *(float4*)&pb[(size_t)(ty * 8 + i) * TM2 + tx * 4]      = v0;
        *(float4*)&pb[(size_t)(ty * 8 + i) * TM2 + 64 + tx * 4] = v1;
    }
}

// deterministic fixed-order reduction of split-K partials
__global__ void reduce_part(float* __restrict__ out, int count, int nsplit) {
    int i = blockIdx.x * blockDim.x + threadIdx.x;
    if (i < count) {
        float s = 0.f;
        for (int ks = 0; ks < nsplit; ks++)
            s += g_part[(size_t)ks * count + i];
        out[i] = s;
    }
}

// ============================================================================
// GEMM1: X[b,n] = relu(rn_r[b,n] + sum_k s[b,k]*W[k,n]); K=128
// grid (NDIM/128, BATCH/128), 256 threads, 128x128 tile, 8x8 micro.
// If final: write to out interleaved (real at b*16384+n, imag zeroed).
// ============================================================================
__global__ void __launch_bounds__(256, 2)
gemm1_relu(const float* __restrict__ W, const float* __restrict__ rn,
           float* __restrict__ outx, int final_out) {
    __shared__ float As[2][8][132];
    __shared__ float Bs[2][8][132];
    int tid = threadIdx.x;
    int n0 = blockIdx.x * 128;
    int r0 = blockIdx.y * 128;
    int lr = tid >> 1;             // A loader: row
    int lk = (tid & 1) << 2;       // A loader: k offset
    int bk = tid >> 5;             // B loader: k row (0..7)
    int bn = (tid & 31) << 2;      // B loader: col (0..124)
    int ty = tid >> 4;
    int tx = tid & 15;

    const float* Ap = g_s + (size_t)(r0 + lr) * TM2 + lk;
    const float* Bp = W + (size_t)bk * NDIM + n0 + bn;

    float acc[8][8];
#pragma unroll
    for (int i = 0; i < 8; i++)
#pragma unroll
        for (int j = 0; j < 8; j++) acc[i][j] = 0.f;

    float4 aa = *(const float4*)Ap;
    float4 bb = *(const float4*)Bp;
    int buf = 0;
    As[0][lk + 0][lr] = aa.x; As[0][lk + 1][lr] = aa.y;
    As[0][lk + 2][lr] = aa.z; As[0][lk + 3][lr] = aa.w;
    *(float4*)&Bs[0][bk][bn] = bb;
    __syncthreads();

    const int nkb = TM2 >> 3;   // 16
    for (int ib = 0; ib < nkb; ib++) {
        if (ib + 1 < nkb) {
            aa = *(const float4*)(Ap + (ib + 1) * 8);
            bb = *(const float4*)(Bp + (size_t)(ib + 1) * 8 * NDIM);
        }
#pragma unroll
        for (int kk = 0; kk < 8; kk++) {
            float4 a0 = *(const float4*)&As[buf][kk][ty * 8];
            float4 a1 = *(const float4*)&As[buf][kk][ty * 8 + 4];
            float4 b0 = *(const float4*)&Bs[buf][kk][tx * 4];
            float4 b1 = *(const float4*)&Bs[buf][kk][tx * 4 + 64];
            float a[8] = {a0.x, a0.y, a0.z, a0.w, a1.x, a1.y, a1.z, a1.w};
            float b[8] = {b0.x, b0.y, b0.z, b0.w, b1.x, b1.y, b1.z, b1.w};
#pragma unroll
            for (int i = 0; i < 8; i++)
#pragma unroll
                for (int j = 0; j < 8; j++)
                    acc[i][j] = fmaf(a[i], b[j], acc[i][j]);
        }
        if (ib + 1 < nkb) {
            int nb = buf ^ 1;
            As[nb][lk + 0][lr] = aa.x; As[nb][lk + 1][lr] = aa.y;
            As[nb][lk + 2][lr] = aa.z; As[nb][lk + 3][lr] = aa.w;
            *(float4*)&Bs[nb][bk][bn] = bb;
            __syncthreads();
            buf = nb;
        }
    }

    float4 zero4 = make_float4(0.f, 0.f, 0.f, 0.f);
#pragma unroll
    for (int i = 0; i < 8; i++) {
        int r = r0 + ty * 8 + i;
        float4 rn0 = *(const float4*)&rn[(size_t)r * (2 * NDIM) + n0 + tx * 4];
        float4 rn1 = *(const float4*)&rn[(size_t)r * (2 * NDIM) + n0 + 64 + tx * 4];
        float4 v0, v1;
        v0.x = fmaxf(acc[i][0] + rn0.x, 0.f); v0.y = fmaxf(acc[i][1] + rn0.y, 0.f);
        v0.z = fmaxf(acc[i][2] + rn0.z, 0.f); v0.w = fmaxf(acc[i][3] + rn0.w, 0.f);
        v1.x = fmaxf(acc[i][4] + rn1.x, 0.f); v1.y = fmaxf(acc[i][5] + rn1.y, 0.f);
        v1.z = fmaxf(acc[i][6] + rn1.z, 0.f); v1.w = fmaxf(acc[i][7] + rn1.w, 0.f);
        if (final_out) {
            size_t base = (size_t)r * (2 * NDIM);
            *(float4*)&outx[base + n0 + tx * 4]              = v0;
            *(float4*)&outx[base + n0 + 64 + tx * 4]         = v1;
            *(float4*)&outx[base + NDIM + n0 + tx * 4]       = zero4;
            *(float4*)&outx[base + NDIM + n0 + 64 + tx * 4]  = zero4;
        } else {
            *(float4*)&g_X[(size_t)r * NDIM + n0 + tx * 4]      = v0;
            *(float4*)&g_X[(size_t)r * NDIM + n0 + 64 + tx * 4] = v1;
        }
    }
}

// ---------------- build block(A A^H), S_block, init [S|I] ------------------
__global__ void build_S(const float* __restrict__ log_rho) {
    int idx = blockIdx.x * blockDim.x + threadIdx.x;   // 16384
    float inv_rho = 1.f / (expf(log_rho[0]) + 1e-12f);
    int p = idx >> 7, q = idx & 127;
    float sgn = ((p < 64) == (q < 64)) ? 1.f : -1.f;
    float g = g_M[idx] + sgn * g_M[((p ^ 64) << 7) + (q ^ 64)];
    g_G[idx] = g;
    g_work[p * 256 + q]       = g + ((p == q) ? inv_rho : 0.f);
    g_work[p * 256 + 128 + q] = (p == q) ? 1.f : 0.f;
}

// one-block Gauss-Jordan (SPD, no pivoting; 128-wide active band)
__global__ void gauss_jordan() {
    int tid  = threadIdx.x;        // 256 threads
    int row  = tid >> 1;
    int half = tid & 1;
    for (int k = 0; k < 128; k++) {
        float pinv = 1.f / g_work[k * 256 + k];
        __syncthreads();
        if (tid <= 128) g_work[k * 256 + k + tid] *= pinv;
        __syncthreads();
        if (row != k) {
            float f = g_work[row * 256 + k];
            int jbase = k + 1 + half * 64;
#pragma unroll 8
            for (int t = 0; t < 64; t++) {
                int j = jbase + t;
                g_work[row * 256 + j] -= f * g_work[k * 256 + j];
            }
        }
        __syncthreads();
    }
    for (int e = tid; e < 128 * 128; e += 256) {
        int p = e >> 7, q = e & 127;
        g_Sinv[e] = g_work[p * 256 + 128 + q];
    }
}

__global__ void init_zu(const float* __restrict__ y,
                        const float* __restrict__ u_in) {
    int i = blockIdx.x * blockDim.x + threadIdx.x;
    if (i < BATCH * TM2) { g_z[i] = y[i]; g_u[i] = u_in[i]; }
}

// c from interleaved projections: row 2b = real-row proj, row 2b+1 = imag
__global__ void combine_c() {
    int i = blockIdx.x * blockDim.x + threadIdx.x;
    if (i < BATCH * TM2) {
        int b = i >> 7, j = i & 127;
        float pa = g_R[(size_t)(2 * b) * TM2 + j];
        float pb = g_R[(size_t)(2 * b + 1) * TM2 + (j ^ 64)];
        g_c[i] = (j < 64) ? pa - pb : pa + pb;
    }
}

// ---------------- per-iteration small kernels ------------------------------
__global__ void s_kernel(const float* __restrict__ log_rho) {
    __shared__ float w[8][TM2];
    __shared__ float Ab[8][TM2];
    int tid = threadIdx.x;
    int b0 = blockIdx.x * 8;
    float rho = expf(log_rho[0]);
#pragma unroll
    for (int bb = 0; bb < 8; bb++)
        w[bb][tid] = g_z[(b0 + bb) * TM2 + tid] - g_u[(b0 + bb) * TM2 + tid];
    __syncthreads();
    float acc[8];
#pragma unroll
    for (int bb = 0; bb < 8; bb++) acc[bb] = 0.f;
    for (int k = 0; k < TM2; k++) {
        float g = g_G[k * TM2 + tid];
#pragma unroll
        for (int bb = 0; bb < 8; bb++) acc[bb] = fmaf(g, w[bb][k], acc[bb]);
    }
#pragma unroll
    for (int bb = 0; bb < 8; bb++)
        Ab[bb][tid] = g_c[(b0 + bb) * TM2 + tid] + rho * acc[bb];
    __syncthreads();
    float acc2[8];
#pragma unroll
    for (int bb = 0; bb < 8; bb++) acc2[bb] = 0.f;
    for (int k = 0; k < TM2; k++) {
        float sv = g_Sinv[k * TM2 + tid];
#pragma unroll
        for (int bb = 0; bb < 8; bb++) acc2[bb] = fmaf(sv, Ab[bb][k], acc2[bb]);
    }
#pragma unroll
    for (int bb = 0; bb < 8; bb++)
        g_s[(b0 + bb) * TM2 + tid] = rho * w[bb][tid] - acc2[bb];
}

__global__ void zu_update(const float* __restrict__ y,
                          const float* __restrict__ log_eps) {
    __shared__ float red[4];
    int b = blockIdx.x;
    int j = threadIdx.x;    // 128
    float eps = expf(log_eps[0]);
    float Pv = g_P[b * TM2 + j];
    float uv = g_u[b * TM2 + j];
    float yv = y[b * TM2 + j];
    float v = Pv + uv - yv;
    float t = v * v;
#pragma unroll
    for (int o = 16; o > 0; o >>= 1) t += __shfl_down_sync(0xffffffffu, t, o);
    if ((j & 31) == 0) red[j >> 5] = t;
    __syncthreads();
    float nrm = sqrtf(red[0] + red[1] + red[2] + red[3]);
    float scale = fminf(1.f, eps / (nrm + 1e-12f));
    float zv = yv + v * scale;
    g_z[b * TM2 + j] = zv;
    g_u[b * TM2 + j] = uv + Pv - zv;
}

__global__ void write_u(float* __restrict__ out) {
    int i = blockIdx.x * blockDim.x + threadIdx.x;
    if (i < BATCH * TM2)
        out[(size_t)BATCH * 2 * NDIM + i] = g_u[i];
}

// ---------------- launch ----------------------------------------------------
extern "C" void kernel_launch(void* const* d_in, const int* in_sizes, int n_in,
                              void* d_out, int out_size) {
    const float* rn   = (const float*)d_in[0];   // (1024, 2, 8192)
    const float* y    = (const float*)d_in[1];   // (1024, 2, 64)
    const float* u_in = (const float*)d_in[2];   // (1024, 2, 64)
    const float* A    = (const float*)d_in[3];   // (2, 64, 8192) = W(128,8192)
    const float* lrho = (const float*)d_in[4];
    const float* leps = (const float*)d_in[5];
    float* out = (float*)d_out;
    (void)in_sizes; (void)n_in; (void)out_size;

    float *dX, *dM, *dR, *dP, *dPart;
    cudaGetSymbolAddress((void**)&dX,    g_X);
    cudaGetSymbolAddress((void**)&dM,    g_M);
    cudaGetSymbolAddress((void**)&dR,    g_R);
    cudaGetSymbolAddress((void**)&dP,    g_P);
    cudaGetSymbolAddress((void**)&dPart, g_part);

    // M = W W^T
    gemm2_tile<<<dim3(1, KS2), 256>>>(A, NDIM, A, dPart, 128, KCH);
    reduce_part<<<(TM2 * TM2 + 255) / 256, 256>>>(dM, TM2 * TM2, KS2);
    build_S<<<64, 256>>>(lrho);
    gauss_jordan<<<1, 256>>>();
    init_zu<<<(BATCH * TM2 + 255) / 256, 256>>>(y, u_in);

    // projections of all 2048 rn rows (real/imag interleaved), then combine
    gemm2_tile<<<dim3(16, KS2), 256>>>(rn, NDIM, A, dPart, 2048, KCH);
    reduce_part<<<(2048 * TM2 + 255) / 256, 256>>>(dR, 2048 * TM2, KS2);
    combine_c<<<(BATCH * TM2 + 255) / 256, 256>>>();

    for (int it = 0; it < 3; it++) {
        int fin = (it == 2);
        s_kernel<<<BATCH / 8, 128>>>(lrho);
        gemm1_relu<<<dim3(NDIM / 128, BATCH / 128), 256>>>(A, rn, out, fin);
        const float* xsrc = fin ? (const float*)out : (const float*)dX;
        int ldx = fin ? 2 * NDIM : NDIM;
        gemm2_tile<<<dim3(BATCH / 128, KS2), 256>>>(xsrc, ldx, A, dPart, BATCH, KCH);
        reduce_part<<<(BATCH * TM2 + 255) / 256, 256>>>(dP, BATCH * TM2, KS2);
        zu_update<<<BATCH, 128>>>(y, leps);
    }

    write_u<<<(BATCH * TM2 + 255) / 256, 256>>>(out);
}

// round 6
// speedup vs baseline: 3.5925x; 3.5585x over previous
#include <cuda_runtime.h>
#include <math.h>

#define BATCH 1024
#define NDIM  8192
#define TM2   128

// ---------------- scratch (static device globals; no runtime alloc) --------
__device__ float g_X[BATCH * NDIM];                        // 32 MB
__device__ float g_part[(size_t)64 * 2048 * TM2];          // split-K partials
__device__ float g_P [BATCH * TM2];
__device__ float g_R [2048 * TM2];
__device__ float g_c [BATCH * TM2];
__device__ float g_d [BATCH * TM2];                        // Sinv @ c
__device__ float g_z [BATCH * TM2];
__device__ float g_u [BATCH * TM2];
__device__ float g_s [BATCH * TM2];
__device__ float g_M   [TM2 * TM2];
__device__ float g_G   [TM2 * TM2];
__device__ float g_Sinv[TM2 * TM2];
__device__ float g_HT  [TM2 * TM2];                        // H^T, H = rho(I - Sinv G)
__device__ float g_work[TM2 * 256];

// ============================================================================
// GEMM-NT (split-K): part[ks][r][j] = sum_{k in chunk} X[r,k] * W[j,k]
// 512 threads, 128x128 tile, warp-stripe 8 rows x 4 cols, double-buffered.
// ============================================================================
__global__ void __launch_bounds__(512, 1)
gemm_nt(const float* __restrict__ X, int ldx, const float* __restrict__ W,
        float* __restrict__ part, int rows, int kchunk) {
    __shared__ float Xs[2][8][132];
    __shared__ float Ws[2][8][132];
    int tid = threadIdx.x;
    int r0 = blockIdx.x * 128;
    int k0 = blockIdx.y * kchunk;
    int wrow = (tid >> 5) << 3;          // warp-stripe row base (broadcast A)
    int tx = tid & 31;                   // col group

    bool isX = tid < 256;
    int u = isX ? tid : tid - 256;
    int lr = u >> 1;                     // 0..127
    int lk = (u & 1) << 2;               // 0 or 4
    const float* P0 = isX ? X + (size_t)(r0 + lr) * ldx + k0 + lk
                          : W + (size_t)lr * NDIM + k0 + lk;

    float4 v = *(const float4*)P0;
    {
        float (*dst)[132] = isX ? Xs[0] : Ws[0];
        dst[lk + 0][lr] = v.x; dst[lk + 1][lr] = v.y;
        dst[lk + 2][lr] = v.z; dst[lk + 3][lr] = v.w;
    }
    float acc[8][4];
#pragma unroll
    for (int i = 0; i < 8; i++)
#pragma unroll
        for (int j = 0; j < 4; j++) acc[i][j] = 0.f;
    __syncthreads();

    int nkb = kchunk >> 3;
    int buf = 0;
    for (int ib = 0; ib < nkb; ib++) {
        if (ib + 1 < nkb) v = *(const float4*)(P0 + (ib + 1) * 8);
#pragma unroll
        for (int kk = 0; kk < 8; kk++) {
            float4 a0 = *(const float4*)&Xs[buf][kk][wrow];
            float4 a1 = *(const float4*)&Xs[buf][kk][wrow + 4];
            float4 b  = *(const float4*)&Ws[buf][kk][tx * 4];
            float a[8] = {a0.x, a0.y, a0.z, a0.w, a1.x, a1.y, a1.z, a1.w};
            float bb[4] = {b.x, b.y, b.z, b.w};
#pragma unroll
            for (int i = 0; i < 8; i++)
#pragma unroll
                for (int j = 0; j < 4; j++)
                    acc[i][j] = fmaf(a[i], bb[j], acc[i][j]);
        }
        if (ib + 1 < nkb) {
            int nb = buf ^ 1;
            float (*dst)[132] = isX ? Xs[nb] : Ws[nb];
            dst[lk + 0][lr] = v.x; dst[lk + 1][lr] = v.y;
            dst[lk + 2][lr] = v.z; dst[lk + 3][lr] = v.w;
            __syncthreads();
            buf = nb;
        }
    }
    float* pb = part + ((size_t)blockIdx.y * rows + r0) * TM2;
#pragma unroll
    for (int i = 0; i < 8; i++)
        *(float4*)&pb[(size_t)(wrow + i) * TM2 + tx * 4] =
            make_float4(acc[i][0], acc[i][1], acc[i][2], acc[i][3]);
}

// deterministic fixed-order reduction of split-K partials
__global__ void reduce_part(float* __restrict__ out, int count, int nsplit) {
    int i = blockIdx.x * blockDim.x + threadIdx.x;
    if (i < count) {
        float s = 0.f;
        for (int ks = 0; ks < nsplit; ks++)
            s += g_part[(size_t)ks * count + i];
        out[i] = s;
    }
}

// ============================================================================
// GEMM-NN + relu: X[b,n] = relu(rn_r[b,n] + sum_k s[b,k] * W[k,n]); K=128
// 512 threads, 128(batch) x 256(n) tile, warp-stripe 8 rows x 8 cols.
// ============================================================================
__global__ void __launch_bounds__(512, 1)
gemm_nn_relu(const float* __restrict__ W, const float* __restrict__ rn,
             float* __restrict__ outx, int final_out) {
    __shared__ float As[2][8][132];
    __shared__ float Bs[2][8][260];
    int tid = threadIdx.x;
    int n0 = blockIdx.x * 256;
    int r0 = blockIdx.y * 128;
    int wrow = (tid >> 5) << 3;
    int tx = tid & 31;

    bool isA = tid < 256;
    int u = isA ? tid : tid - 256;
    int lr = u >> 1, lk = (u & 1) << 2;      // A loader
    int bk = u >> 5, bn = (u & 31) << 2;     // B loader
    const float* Ap = g_s + (size_t)(r0 + lr) * TM2 + lk;
    const float* Bp = W + (size_t)bk * NDIM + n0 + bn;

    float4 av, bv0, bv1;
    if (isA) {
        av = *(const float4*)Ap;
        As[0][lk + 0][lr] = av.x; As[0][lk + 1][lr] = av.y;
        As[0][lk + 2][lr] = av.z; As[0][lk + 3][lr] = av.w;
    } else {
        bv0 = *(const float4*)Bp;
        bv1 = *(const float4*)(Bp + 128);
        *(float4*)&Bs[0][bk][bn]       = bv0;
        *(float4*)&Bs[0][bk][bn + 128] = bv1;
    }
    float acc[8][8];
#pragma unroll
    for (int i = 0; i < 8; i++)
#pragma unroll
        for (int j = 0; j < 8; j++) acc[i][j] = 0.f;
    __syncthreads();

    const int nkb = TM2 >> 3;   // 16
    int buf = 0;
    for (int ib = 0; ib < nkb; ib++) {
        if (ib + 1 < nkb) {
            if (isA) av = *(const float4*)(Ap + (ib + 1) * 8);
            else {
                bv0 = *(const float4*)(Bp + (size_t)(ib + 1) * 8 * NDIM);
                bv1 = *(const float4*)(Bp + (size_t)(ib + 1) * 8 * NDIM + 128);
            }
        }
#pragma unroll
        for (int kk = 0; kk < 8; kk++) {
            float4 a0 = *(const float4*)&As[buf][kk][wrow];
            float4 a1 = *(const float4*)&As[buf][kk][wrow + 4];
            float4 b0 = *(const float4*)&Bs[buf][kk][tx * 4];
            float4 b1 = *(const float4*)&Bs[buf][kk][tx * 4 + 128];
            float a[8] = {a0.x, a0.y, a0.z, a0.w, a1.x, a1.y, a1.z, a1.w};
            float b[8] = {b0.x, b0.y, b0.z, b0.w, b1.x, b1.y, b1.z, b1.w};
#pragma unroll
            for (int i = 0; i < 8; i++)
#pragma unroll
                for (int j = 0; j < 8; j++)
                    acc[i][j] = fmaf(a[i], b[j], acc[i][j]);
        }
        if (ib + 1 < nkb) {
            int nb = buf ^ 1;
            if (isA) {
                As[nb][lk + 0][lr] = av.x; As[nb][lk + 1][lr] = av.y;
                As[nb][lk + 2][lr] = av.z; As[nb][lk + 3][lr] = av.w;
            } else {
                *(float4*)&Bs[nb][bk][bn]       = bv0;
                *(float4*)&Bs[nb][bk][bn + 128] = bv1;
            }
            __syncthreads();
            buf = nb;
        }
    }

    float4 zero4 = make_float4(0.f, 0.f, 0.f, 0.f);
#pragma unroll
    for (int i = 0; i < 8; i++) {
        int r = r0 + wrow + i;
        float4 rn0 = *(const float4*)&rn[(size_t)r * (2 * NDIM) + n0 + tx * 4];
        float4 rn1 = *(const float4*)&rn[(size_t)r * (2 * NDIM) + n0 + 128 + tx * 4];
        float4 v0, v1;
        v0.x = fmaxf(acc[i][0] + rn0.x, 0.f); v0.y = fmaxf(acc[i][1] + rn0.y, 0.f);
        v0.z = fmaxf(acc[i][2] + rn0.z, 0.f); v0.w = fmaxf(acc[i][3] + rn0.w, 0.f);
        v1.x = fmaxf(acc[i][4] + rn1.x, 0.f); v1.y = fmaxf(acc[i][5] + rn1.y, 0.f);
        v1.z = fmaxf(acc[i][6] + rn1.z, 0.f); v1.w = fmaxf(acc[i][7] + rn1.w, 0.f);
        if (final_out) {
            size_t base = (size_t)r * (2 * NDIM);
            *(float4*)&outx[base + n0 + tx * 4]               = v0;
            *(float4*)&outx[base + n0 + 128 + tx * 4]         = v1;
            *(float4*)&outx[base + NDIM + n0 + tx * 4]        = zero4;
            *(float4*)&outx[base + NDIM + n0 + 128 + tx * 4]  = zero4;
        } else {
            *(float4*)&g_X[(size_t)r * NDIM + n0 + tx * 4]       = v0;
            *(float4*)&g_X[(size_t)r * NDIM + n0 + 128 + tx * 4] = v1;
        }
    }
}

// ---------------- build block(A A^H), S_block, init [S|I] ------------------
__global__ void build_S(const float* __restrict__ log_rho) {
    int idx = blockIdx.x * blockDim.x + threadIdx.x;   // 16384
    float inv_rho = 1.f / (expf(log_rho[0]) + 1e-12f);
    int p = idx >> 7, q = idx & 127;
    float sgn = ((p < 64) == (q < 64)) ? 1.f : -1.f;
    float g = g_M[idx] + sgn * g_M[((p ^ 64) << 7) + (q ^ 64)];
    g_G[idx] = g;
    g_work[p * 256 + q]       = g + ((p == q) ? inv_rho : 0.f);
    g_work[p * 256 + 128 + q] = (p == q) ? 1.f : 0.f;
}

// ---------------- Gauss-Jordan fully in shared memory ----------------------
__global__ void gauss_jordan_smem() {
    extern __shared__ float sw[];       // [128][257]
    const int LD = 257;
    __shared__ float s_pinv;
    int tid = threadIdx.x;              // 1024
    for (int e = tid; e < 128 * 256; e += 1024) {
        int p = e >> 8, q = e & 255;
        sw[p * LD + q] = g_work[p * 256 + q];
    }
    __syncthreads();
    int row = tid >> 3, sub = tid & 7;
    for (int k = 0; k < 128; k++) {
        if (tid == 0) s_pinv = 1.f / sw[k * LD + k];
        __syncthreads();
        if (tid <= 128) sw[k * LD + k + tid] *= s_pinv;
        __syncthreads();
        if (row != k) {
            float f = sw[row * LD + k];
            int jb = k + 1 + sub * 16;
#pragma unroll
            for (int t = 0; t < 16; t++)
                sw[row * LD + jb + t] -= f * sw[k * LD + jb + t];
        }
        __syncthreads();
    }
    for (int e = tid; e < 128 * 128; e += 1024) {
        int p = e >> 7, q = e & 127;
        g_Sinv[p * 128 + q] = sw[p * LD + 128 + q];
    }
}

// H^T[k][j] = rho * ((j==k) - sum_m Sinv[j,m] G[m,k]); uses symmetry of both
__global__ void compute_HT(const float* __restrict__ log_rho) {
    __shared__ float gk[128];
    int j = threadIdx.x, k = blockIdx.x;
    float rho = expf(log_rho[0]);
    gk[j] = g_G[k * 128 + j];
    __syncthreads();
    float acc = 0.f;
    for (int m = 0; m < 128; m++)
        acc = fmaf(g_Sinv[m * 128 + j], gk[m], acc);
    g_HT[k * 128 + j] = rho * (((j == k) ? 1.f : 0.f) - acc);
}

__global__ void init_zu(const float* __restrict__ y,
                        const float* __restrict__ u_in) {
    int i = blockIdx.x * blockDim.x + threadIdx.x;
    if (i < BATCH * TM2) { g_z[i] = y[i]; g_u[i] = u_in[i]; }
}

// c from interleaved projections (row 2b = real proj, 2b+1 = imag proj)
__global__ void combine_c() {
    int i = blockIdx.x * blockDim.x + threadIdx.x;
    if (i < BATCH * TM2) {
        int b = i >> 7, j = i & 127;
        float pa = g_R[(size_t)(2 * b) * TM2 + j];
        float pb = g_R[(size_t)(2 * b + 1) * TM2 + (j ^ 64)];
        g_c[i] = (j < 64) ? pa - pb : pa + pb;
    }
}

// d = Sinv @ c per batch (Sinv symmetric -> coalesced)
__global__ void precompute_d() {
    __shared__ float cb[8][128];
    int tid = threadIdx.x;
    int b0 = blockIdx.x * 8;
#pragma unroll
    for (int bb = 0; bb < 8; bb++)
        cb[bb][tid] = g_c[(b0 + bb) * TM2 + tid];
    __syncthreads();
    float acc[8];
#pragma unroll
    for (int bb = 0; bb < 8; bb++) acc[bb] = 0.f;
    for (int k = 0; k < 128; k++) {
        float sv = g_Sinv[k * 128 + tid];
#pragma unroll
        for (int bb = 0; bb < 8; bb++) acc[bb] = fmaf(sv, cb[bb][k], acc[bb]);
    }
#pragma unroll
    for (int bb = 0; bb < 8; bb++)
        g_d[(b0 + bb) * TM2 + tid] = acc[bb];
}

// s = H (z-u) - d : single 128-matvec per batch
__global__ void s_kernel2() {
    __shared__ float w[8][128];
    int tid = threadIdx.x;
    int b0 = blockIdx.x * 8;
#pragma unroll
    for (int bb = 0; bb < 8; bb++)
        w[bb][tid] = g_z[(b0 + bb) * TM2 + tid] - g_u[(b0 + bb) * TM2 + tid];
    __syncthreads();
    float acc[8];
#pragma unroll
    for (int bb = 0; bb < 8; bb++) acc[bb] = 0.f;
    for (int k = 0; k < 128; k++) {
        float h = g_HT[k * 128 + tid];
#pragma unroll
        for (int bb = 0; bb < 8; bb++) acc[bb] = fmaf(h, w[bb][k], acc[bb]);
    }
#pragma unroll
    for (int bb = 0; bb < 8; bb++)
        g_s[(b0 + bb) * TM2 + tid] = acc[bb] - g_d[(b0 + bb) * TM2 + tid];
}

__global__ void zu_update(const float* __restrict__ y,
                          const float* __restrict__ log_eps) {
    __shared__ float red[4];
    int b = blockIdx.x;
    int j = threadIdx.x;    // 128
    float eps = expf(log_eps[0]);
    float Pv = g_P[b * TM2 + j];
    float uv = g_u[b * TM2 + j];
    float yv = y[b * TM2 + j];
    float v = Pv + uv - yv;
    float t = v * v;
#pragma unroll
    for (int o = 16; o > 0; o >>= 1) t += __shfl_down_sync(0xffffffffu, t, o);
    if ((j & 31) == 0) red[j >> 5] = t;
    __syncthreads();
    float nrm = sqrtf(red[0] + red[1] + red[2] + red[3]);
    float scale = fminf(1.f, eps / (nrm + 1e-12f));
    float zv = yv + v * scale;
    g_z[b * TM2 + j] = zv;
    g_u[b * TM2 + j] = uv + Pv - zv;
}

__global__ void write_u(float* __restrict__ out) {
    int i = blockIdx.x * blockDim.x + threadIdx.x;
    if (i < BATCH * TM2)
        out[(size_t)BATCH * 2 * NDIM + i] = g_u[i];
}

// ---------------- launch ----------------------------------------------------
extern "C" void kernel_launch(void* const* d_in, const int* in_sizes, int n_in,
                              void* d_out, int out_size) {
    const float* rn   = (const float*)d_in[0];   // (1024, 2, 8192)
    const float* y    = (const float*)d_in[1];   // (1024, 2, 64)
    const float* u_in = (const float*)d_in[2];   // (1024, 2, 64)
    const float* A    = (const float*)d_in[3];   // (2,64,8192) = W(128,8192)
    const float* lrho = (const float*)d_in[4];
    const float* leps = (const float*)d_in[5];
    float* out = (float*)d_out;
    (void)in_sizes; (void)n_in; (void)out_size;

    float *dX, *dM, *dR, *dP, *dPart;
    cudaGetSymbolAddress((void**)&dX,    g_X);
    cudaGetSymbolAddress((void**)&dM,    g_M);
    cudaGetSymbolAddress((void**)&dR,    g_R);
    cudaGetSymbolAddress((void**)&dP,    g_P);
    cudaGetSymbolAddress((void**)&dPart, g_part);

    static int smem_set = 0;
    if (!smem_set) {
        cudaFuncSetAttribute(gauss_jordan_smem,
                             cudaFuncAttributeMaxDynamicSharedMemorySize,
                             128 * 257 * 4);
        smem_set = 1;
    }

    // M = W W^T  (64-way split-K for parallelism)
    gemm_nt<<<dim3(1, 64), 512>>>(A, NDIM, A, dPart, 128, 128);
    reduce_part<<<(TM2 * TM2 + 255) / 256, 256>>>(dM, TM2 * TM2, 64);
    build_S<<<64, 256>>>(lrho);
    gauss_jordan_smem<<<1, 1024, 128 * 257 * 4>>>();
    compute_HT<<<128, 128>>>(lrho);
    init_zu<<<(BATCH * TM2 + 255) / 256, 256>>>(y, u_in);

    // projections of all 2048 rn rows, combine into c, then d = Sinv c
    gemm_nt<<<dim3(16, 32), 512>>>(rn, NDIM, A, dPart, 2048, 256);
    reduce_part<<<(2048 * TM2 + 255) / 256, 256>>>(dR, 2048 * TM2, 32);
    combine_c<<<(BATCH * TM2 + 255) / 256, 256>>>();
    precompute_d<<<128, 128>>>();

    for (int it = 0; it < 3; it++) {
        int fin = (it == 2);
        s_kernel2<<<BATCH / 8, 128>>>();
        gemm_nn_relu<<<dim3(NDIM / 256, BATCH / 128), 512>>>(A, rn, out, fin);
        const float* xsrc = fin ? (const float*)out : (const float*)dX;
        int ldx = fin ? 2 * NDIM : NDIM;
        gemm_nt<<<dim3(BATCH / 128, 32), 512>>>(xsrc, ldx, A, dPart, BATCH, 256);
        reduce_part<<<(BATCH * TM2 + 255) / 256, 256>>>(dP, BATCH * TM2, 32);
        zu_update<<<BATCH, 128>>>(y, leps);
    }

    write_u<<<(BATCH * TM2 + 255) / 256, 256>>>(out);
}

// round 7
// speedup vs baseline: 5.3184x; 1.4804x over previous
#include <cuda_runtime.h>
#include <math.h>

#define BATCH 1024
#define NDIM  8192
#define TM2   128

// ---------------- scratch (static device globals; no runtime alloc) --------
__device__ float g_X[BATCH * NDIM];                        // 32 MB
__device__ float g_part[(size_t)64 * 2048 * TM2];          // split-K partials
__device__ float g_P [BATCH * TM2];
__device__ float g_R [2048 * TM2];
__device__ float g_d [BATCH * TM2];                        // Sinv @ c
__device__ float g_z [BATCH * TM2];
__device__ float g_u [BATCH * TM2];
__device__ float g_s [BATCH * TM2];
__device__ float g_M   [TM2 * TM2];
__device__ float g_G   [TM2 * TM2];
__device__ float g_S   [TM2 * TM2];                        // S = G + I/rho
__device__ float g_NSa [TM2 * TM2];                        // Newton-Schulz ping
__device__ float g_NSb [TM2 * TM2];                        // Newton-Schulz pong
__device__ float g_Y   [TM2 * TM2];                        // S @ X temp
__device__ float g_HT  [TM2 * TM2];                        // H^T, H = rho(I - Sinv G)

// ============================================================================
// GEMM-NT (split-K): part[ks][r][j] = sum_{k in chunk} X[r,k] * W[j,k]
// 512 threads, 128x128 tile, warp-stripe 8 rows x 4 cols, double-buffered.
// ============================================================================
__global__ void __launch_bounds__(512, 1)
gemm_nt(const float* __restrict__ X, int ldx, const float* __restrict__ W,
        float* __restrict__ part, int rows, int kchunk) {
    __shared__ float Xs[2][8][132];
    __shared__ float Ws[2][8][132];
    int tid = threadIdx.x;
    int r0 = blockIdx.x * 128;
    int k0 = blockIdx.y * kchunk;
    int wrow = (tid >> 5) << 3;
    int tx = tid & 31;

    bool isX = tid < 256;
    int u = isX ? tid : tid - 256;
    int lr = u >> 1;
    int lk = (u & 1) << 2;
    const float* P0 = isX ? X + (size_t)(r0 + lr) * ldx + k0 + lk
                          : W + (size_t)lr * NDIM + k0 + lk;

    float4 v = *(const float4*)P0;
    {
        float (*dst)[132] = isX ? Xs[0] : Ws[0];
        dst[lk + 0][lr] = v.x; dst[lk + 1][lr] = v.y;
        dst[lk + 2][lr] = v.z; dst[lk + 3][lr] = v.w;
    }
    float acc[8][4];
#pragma unroll
    for (int i = 0; i < 8; i++)
#pragma unroll
        for (int j = 0; j < 4; j++) acc[i][j] = 0.f;
    __syncthreads();

    int nkb = kchunk >> 3;
    int buf = 0;
    for (int ib = 0; ib < nkb; ib++) {
        if (ib + 1 < nkb) v = *(const float4*)(P0 + (ib + 1) * 8);
#pragma unroll
        for (int kk = 0; kk < 8; kk++) {
            float4 a0 = *(const float4*)&Xs[buf][kk][wrow];
            float4 a1 = *(const float4*)&Xs[buf][kk][wrow + 4];
            float4 b  = *(const float4*)&Ws[buf][kk][tx * 4];
            float a[8] = {a0.x, a0.y, a0.z, a0.w, a1.x, a1.y, a1.z, a1.w};
            float bb[4] = {b.x, b.y, b.z, b.w};
#pragma unroll
            for (int i = 0; i < 8; i++)
#pragma unroll
                for (int j = 0; j < 4; j++)
                    acc[i][j] = fmaf(a[i], bb[j], acc[i][j]);
        }
        if (ib + 1 < nkb) {
            int nb = buf ^ 1;
            float (*dst)[132] = isX ? Xs[nb] : Ws[nb];
            dst[lk + 0][lr] = v.x; dst[lk + 1][lr] = v.y;
            dst[lk + 2][lr] = v.z; dst[lk + 3][lr] = v.w;
            __syncthreads();
            buf = nb;
        }
    }
    float* pb = part + ((size_t)blockIdx.y * rows + r0) * TM2;
#pragma unroll
    for (int i = 0; i < 8; i++)
        *(float4*)&pb[(size_t)(wrow + i) * TM2 + tx * 4] =
            make_float4(acc[i][0], acc[i][1], acc[i][2], acc[i][3]);
}

// deterministic fixed-order reduction of split-K partials
__global__ void reduce_part(float* __restrict__ out, int count, int nsplit) {
    int i = blockIdx.x * blockDim.x + threadIdx.x;
    if (i < count) {
        float s = 0.f;
        for (int ks = 0; ks < nsplit; ks++)
            s += g_part[(size_t)ks * count + i];
        out[i] = s;
    }
}

// ============================================================================
// GEMM-NN + relu: X[b,n] = relu(rn_r[b,n] + sum_k s[b,k] * W[k,n]); K=128
// ============================================================================
__global__ void __launch_bounds__(512, 1)
gemm_nn_relu(const float* __restrict__ W, const float* __restrict__ rn,
             float* __restrict__ outx, int final_out) {
    __shared__ float As[2][8][132];
    __shared__ float Bs[2][8][260];
    int tid = threadIdx.x;
    int n0 = blockIdx.x * 256;
    int r0 = blockIdx.y * 128;
    int wrow = (tid >> 5) << 3;
    int tx = tid & 31;

    bool isA = tid < 256;
    int u = isA ? tid : tid - 256;
    int lr = u >> 1, lk = (u & 1) << 2;
    int bk = u >> 5, bn = (u & 31) << 2;
    const float* Ap = g_s + (size_t)(r0 + lr) * TM2 + lk;
    const float* Bp = W + (size_t)bk * NDIM + n0 + bn;

    float4 av, bv0, bv1;
    if (isA) {
        av = *(const float4*)Ap;
        As[0][lk + 0][lr] = av.x; As[0][lk + 1][lr] = av.y;
        As[0][lk + 2][lr] = av.z; As[0][lk + 3][lr] = av.w;
    } else {
        bv0 = *(const float4*)Bp;
        bv1 = *(const float4*)(Bp + 128);
        *(float4*)&Bs[0][bk][bn]       = bv0;
        *(float4*)&Bs[0][bk][bn + 128] = bv1;
    }
    float acc[8][8];
#pragma unroll
    for (int i = 0; i < 8; i++)
#pragma unroll
        for (int j = 0; j < 8; j++) acc[i][j] = 0.f;
    __syncthreads();

    const int nkb = TM2 >> 3;
    int buf = 0;
    for (int ib = 0; ib < nkb; ib++) {
        if (ib + 1 < nkb) {
            if (isA) av = *(const float4*)(Ap + (ib + 1) * 8);
            else {
                bv0 = *(const float4*)(Bp + (size_t)(ib + 1) * 8 * NDIM);
                bv1 = *(const float4*)(Bp + (size_t)(ib + 1) * 8 * NDIM + 128);
            }
        }
#pragma unroll
        for (int kk = 0; kk < 8; kk++) {
            float4 a0 = *(const float4*)&As[buf][kk][wrow];
            float4 a1 = *(const float4*)&As[buf][kk][wrow + 4];
            float4 b0 = *(const float4*)&Bs[buf][kk][tx * 4];
            float4 b1 = *(const float4*)&Bs[buf][kk][tx * 4 + 128];
            float a[8] = {a0.x, a0.y, a0.z, a0.w, a1.x, a1.y, a1.z, a1.w};
            float b[8] = {b0.x, b0.y, b0.z, b0.w, b1.x, b1.y, b1.z, b1.w};
#pragma unroll
            for (int i = 0; i < 8; i++)
#pragma unroll
                for (int j = 0; j < 8; j++)
                    acc[i][j] = fmaf(a[i], b[j], acc[i][j]);
        }
        if (ib + 1 < nkb) {
            int nb = buf ^ 1;
            if (isA) {
                As[nb][lk + 0][lr] = av.x; As[nb][lk + 1][lr] = av.y;
                As[nb][lk + 2][lr] = av.z; As[nb][lk + 3][lr] = av.w;
            } else {
                *(float4*)&Bs[nb][bk][bn]       = bv0;
                *(float4*)&Bs[nb][bk][bn + 128] = bv1;
            }
            __syncthreads();
            buf = nb;
        }
    }

    float4 zero4 = make_float4(0.f, 0.f, 0.f, 0.f);
#pragma unroll
    for (int i = 0; i < 8; i++) {
        int r = r0 + wrow + i;
        float4 rn0 = *(const float4*)&rn[(size_t)r * (2 * NDIM) + n0 + tx * 4];
        float4 rn1 = *(const float4*)&rn[(size_t)r * (2 * NDIM) + n0 + 128 + tx * 4];
        float4 v0, v1;
        v0.x = fmaxf(acc[i][0] + rn0.x, 0.f); v0.y = fmaxf(acc[i][1] + rn0.y, 0.f);
        v0.z = fmaxf(acc[i][2] + rn0.z, 0.f); v0.w = fmaxf(acc[i][3] + rn0.w, 0.f);
        v1.x = fmaxf(acc[i][4] + rn1.x, 0.f); v1.y = fmaxf(acc[i][5] + rn1.y, 0.f);
        v1.z = fmaxf(acc[i][6] + rn1.z, 0.f); v1.w = fmaxf(acc[i][7] + rn1.w, 0.f);
        if (final_out) {
            size_t base = (size_t)r * (2 * NDIM);
            *(float4*)&outx[base + n0 + tx * 4]               = v0;
            *(float4*)&outx[base + n0 + 128 + tx * 4]         = v1;
            *(float4*)&outx[base + NDIM + n0 + tx * 4]        = zero4;
            *(float4*)&outx[base + NDIM + n0 + 128 + tx * 4]  = zero4;
        } else {
            *(float4*)&g_X[(size_t)r * NDIM + n0 + tx * 4]       = v0;
            *(float4*)&g_X[(size_t)r * NDIM + n0 + 128 + tx * 4] = v1;
        }
    }
}

// ---------------- build G and S = G + I/rho --------------------------------
__global__ void build_S(const float* __restrict__ log_rho) {
    int idx = blockIdx.x * blockDim.x + threadIdx.x;   // 16384
    float inv_rho = 1.f / (expf(log_rho[0]) + 1e-12f);
    int p = idx >> 7, q = idx & 127;
    float sgn = ((p < 64) == (q < 64)) ? 1.f : -1.f;
    float g = g_M[idx] + sgn * g_M[((p ^ 64) << 7) + (q ^ 64)];
    g_G[idx] = g;
    g_S[idx] = g + ((p == q) ? inv_rho : 0.f);
}

// ---------------- Newton-Schulz inverse (replaces Gauss-Jordan) ------------
// Gershgorin bounds -> x0; X1 = 2*x0*I - x0^2*S (one NS step from x0*I).
__global__ void gersh_initX1() {
    __shared__ float s_rs[128], s_dg[128];
    __shared__ float s_x0;
    int i = threadIdx.x;    // 128
    float rs = 0.f, dg = 0.f;
#pragma unroll 8
    for (int k = 0; k < 128; k++) {
        float v = g_S[i * 128 + k];
        rs += fabsf(v);
        if (k == i) dg = v;
    }
    s_rs[i] = rs; s_dg[i] = dg;
    __syncthreads();
    if (i == 0) {
        float lmax = 0.f, lmin = 1e30f;
        for (int r = 0; r < 128; r++) {
            lmax = fmaxf(lmax, s_rs[r]);
            lmin = fminf(lmin, 2.f * s_dg[r] - s_rs[r]);
        }
        s_x0 = (lmin > 0.f) ? 2.f / (lmax + lmin) : 1.f / lmax;
    }
    __syncthreads();
    float x0 = s_x0;
    for (int e = i; e < 128 * 128; e += 128) {
        int p = e >> 7, q = e & 127;
        g_NSa[e] = 2.f * x0 * ((p == q) ? 1.f : 0.f) - x0 * x0 * g_S[e];
    }
}

// Y = S @ X   (64 blocks x 256 threads: 2 rows x 128 cols per block)
__global__ void __launch_bounds__(256)
ns_SX(const float* __restrict__ X, float* __restrict__ Y) {
    __shared__ float As[2][128];
    int tid = threadIdx.x;
    int r0 = blockIdx.x * 2;
    int rr = tid >> 7;
    int j  = tid & 127;
    As[rr][j] = g_S[(r0 + rr) * 128 + j];
    __syncthreads();
    float acc = 0.f;
#pragma unroll 8
    for (int k = 0; k < 128; k++)
        acc = fmaf(As[rr][k], X[k * 128 + j], acc);
    Y[(r0 + rr) * 128 + j] = acc;
}

// Xn = 2*X - X @ Y
__global__ void __launch_bounds__(256)
ns_update(const float* __restrict__ X, const float* __restrict__ Y,
          float* __restrict__ Xn) {
    __shared__ float As[2][128];
    int tid = threadIdx.x;
    int r0 = blockIdx.x * 2;
    int rr = tid >> 7;
    int j  = tid & 127;
    As[rr][j] = X[(r0 + rr) * 128 + j];
    __syncthreads();
    float acc = 0.f;
#pragma unroll 8
    for (int k = 0; k < 128; k++)
        acc = fmaf(As[rr][k], Y[k * 128 + j], acc);
    Xn[(r0 + rr) * 128 + j] = 2.f * As[rr][j] - acc;
}

// H^T[k][j] = rho * ((j==k) - sum_m Sinv[j,m] G[m,k]); both symmetric
__global__ void compute_HT(const float* __restrict__ Sinv,
                           const float* __restrict__ log_rho) {
    __shared__ float gk[128];
    int j = threadIdx.x, k = blockIdx.x;
    float rho = expf(log_rho[0]);
    gk[j] = g_G[k * 128 + j];
    __syncthreads();
    float acc = 0.f;
#pragma unroll 4
    for (int m = 0; m < 128; m++)
        acc = fmaf(Sinv[m * 128 + j], gk[m], acc);
    g_HT[k * 128 + j] = rho * (((j == k) ? 1.f : 0.f) - acc);
}

__global__ void init_zu(const float* __restrict__ y,
                        const float* __restrict__ u_in) {
    int i = blockIdx.x * blockDim.x + threadIdx.x;
    if (i < BATCH * TM2) { g_z[i] = y[i]; g_u[i] = u_in[i]; }
}

// d = Sinv @ c with c assembled on the fly from the rn projections g_R
// (row 2b = real proj, row 2b+1 = imag proj)
__global__ void precompute_d(const float* __restrict__ Sinv) {
    __shared__ float cb[8][128];
    int tid = threadIdx.x;
    int b0 = blockIdx.x * 8;
#pragma unroll
    for (int bb = 0; bb < 8; bb++) {
        int b = b0 + bb, j = tid;
        float pa = g_R[(size_t)(2 * b) * TM2 + j];
        float pb = g_R[(size_t)(2 * b + 1) * TM2 + (j ^ 64)];
        cb[bb][j] = (j < 64) ? pa - pb : pa + pb;
    }
    __syncthreads();
    float acc[8];
#pragma unroll
    for (int bb = 0; bb < 8; bb++) acc[bb] = 0.f;
    for (int k = 0; k < 128; k++) {
        float sv = Sinv[k * 128 + tid];
#pragma unroll
        for (int bb = 0; bb < 8; bb++) acc[bb] = fmaf(sv, cb[bb][k], acc[bb]);
    }
#pragma unroll
    for (int bb = 0; bb < 8; bb++)
        g_d[(b0 + bb) * TM2 + tid] = acc[bb];
}

// s = H (z-u) - d
__global__ void s_kernel2() {
    __shared__ float w[8][128];
    int tid = threadIdx.x;
    int b0 = blockIdx.x * 8;
#pragma unroll
    for (int bb = 0; bb < 8; bb++)
        w[bb][tid] = g_z[(b0 + bb) * TM2 + tid] - g_u[(b0 + bb) * TM2 + tid];
    __syncthreads();
    float acc[8];
#pragma unroll
    for (int bb = 0; bb < 8; bb++) acc[bb] = 0.f;
    for (int k = 0; k < 128; k++) {
        float h = g_HT[k * 128 + tid];
#pragma unroll
        for (int bb = 0; bb < 8; bb++) acc[bb] = fmaf(h, w[bb][k], acc[bb]);
    }
#pragma unroll
    for (int bb = 0; bb < 8; bb++)
        g_s[(b0 + bb) * TM2 + tid] = acc[bb] - g_d[(b0 + bb) * TM2 + tid];
}

__global__ void zu_update(const float* __restrict__ y,
                          const float* __restrict__ log_eps) {
    __shared__ float red[4];
    int b = blockIdx.x;
    int j = threadIdx.x;    // 128
    float eps = expf(log_eps[0]);
    float Pv = g_P[b * TM2 + j];
    float uv = g_u[b * TM2 + j];
    float yv = y[b * TM2 + j];
    float v = Pv + uv - yv;
    float t = v * v;
#pragma unroll
    for (int o = 16; o > 0; o >>= 1) t += __shfl_down_sync(0xffffffffu, t, o);
    if ((j & 31) == 0) red[j >> 5] = t;
    __syncthreads();
    float nrm = sqrtf(red[0] + red[1] + red[2] + red[3]);
    float scale = fminf(1.f, eps / (nrm + 1e-12f));
    float zv = yv + v * scale;
    g_z[b * TM2 + j] = zv;
    g_u[b * TM2 + j] = uv + Pv - zv;
}

__global__ void write_u(float* __restrict__ out) {
    int i = blockIdx.x * blockDim.x + threadIdx.x;
    if (i < BATCH * TM2)
        out[(size_t)BATCH * 2 * NDIM + i] = g_u[i];
}

// ---------------- launch ----------------------------------------------------
extern "C" void kernel_launch(void* const* d_in, const int* in_sizes, int n_in,
                              void* d_out, int out_size) {
    const float* rn   = (const float*)d_in[0];   // (1024, 2, 8192)
    const float* y    = (const float*)d_in[1];   // (1024, 2, 64)
    const float* u_in = (const float*)d_in[2];   // (1024, 2, 64)
    const float* A    = (const float*)d_in[3];   // (2,64,8192) = W(128,8192)
    const float* lrho = (const float*)d_in[4];
    const float* leps = (const float*)d_in[5];
    float* out = (float*)d_out;
    (void)in_sizes; (void)n_in; (void)out_size;

    float *dX, *dM, *dR, *dP, *dPart, *dNSa, *dNSb, *dY;
    cudaGetSymbolAddress((void**)&dX,    g_X);
    cudaGetSymbolAddress((void**)&dM,    g_M);
    cudaGetSymbolAddress((void**)&dR,    g_R);
    cudaGetSymbolAddress((void**)&dP,    g_P);
    cudaGetSymbolAddress((void**)&dPart, g_part);
    cudaGetSymbolAddress((void**)&dNSa,  g_NSa);
    cudaGetSymbolAddress((void**)&dNSb,  g_NSb);
    cudaGetSymbolAddress((void**)&dY,    g_Y);

    // M = W W^T (64-way split-K), then G and S
    gemm_nt<<<dim3(1, 64), 512>>>(A, NDIM, A, dPart, 128, 128);
    reduce_part<<<(TM2 * TM2 + 255) / 256, 256>>>(dM, TM2 * TM2, 64);
    build_S<<<64, 256>>>(lrho);

    // Newton-Schulz inverse: X1 elementwise, then 7 quadratic steps
    gersh_initX1<<<1, 128>>>();
    float* cur = dNSa;
    float* nxt = dNSb;
    for (int t = 0; t < 7; t++) {
        ns_SX<<<64, 256>>>(cur, dY);
        ns_update<<<64, 256>>>(cur, dY, nxt);
        float* tmp = cur; cur = nxt; nxt = tmp;
    }
    const float* Sinv = cur;

    compute_HT<<<128, 128>>>(Sinv, lrho);
    init_zu<<<(BATCH * TM2 + 255) / 256, 256>>>(y, u_in);

    // projections of all 2048 rn rows, then d = Sinv c (c fused)
    gemm_nt<<<dim3(16, 32), 512>>>(rn, NDIM, A, dPart, 2048, 256);
    reduce_part<<<(2048 * TM2 + 255) / 256, 256>>>(dR, 2048 * TM2, 32);
    precompute_d<<<128, 128>>>(Sinv);

    for (int it = 0; it < 3; it++) {
        int fin = (it == 2);
        s_kernel2<<<BATCH / 8, 128>>>();
        gemm_nn_relu<<<dim3(NDIM / 256, BATCH / 128), 512>>>(A, rn, out, fin);
        const float* xsrc = fin ? (const float*)out : (const float*)dX;
        int ldx = fin ? 2 * NDIM : NDIM;
        gemm_nt<<<dim3(BATCH / 128, 32), 512>>>(xsrc, ldx, A, dPart, BATCH, 256);
        reduce_part<<<(BATCH * TM2 + 255) / 256, 256>>>(dP, BATCH * TM2, 32);
        zu_update<<<BATCH, 128>>>(y, leps);
    }

    write_u<<<(BATCH * TM2 + 255) / 256, 256>>>(out);
}

// round 9
// speedup vs baseline: 7.2315x; 1.3597x over previous
#include <cuda_runtime.h>
#include <cuda_bf16.h>
#include <math.h>
#include <stdint.h>

#define BATCH 1024
#define NDIM  8192
#define TM2   128
#define NSPLIT 16
#define KCHUNK 512
#define PITCH 132            // u32 pitch for [kpair][row] smem tiles

// ---------------- scratch (static device globals; no runtime alloc) --------
__device__ float g_X[BATCH * NDIM];                        // 32 MB
__device__ float g_part[(size_t)NSPLIT * 2048 * TM2];      // split-K partials
__device__ float g_P [BATCH * TM2];
__device__ float g_R [2048 * TM2];
__device__ float g_d [BATCH * TM2];
__device__ float g_z [BATCH * TM2];
__device__ float g_u [BATCH * TM2];
__device__ float g_s [BATCH * TM2];
__device__ float g_M   [TM2 * TM2];
__device__ float g_G   [TM2 * TM2];
__device__ float g_S   [TM2 * TM2];
__device__ float g_NSa [TM2 * TM2];
__device__ float g_NSb [TM2 * TM2];
__device__ float g_Y   [TM2 * TM2];
__device__ float g_HT  [TM2 * TM2];
__device__ __nv_bfloat16 g_Whi [TM2 * NDIM];               // W  k-major bf16 hi
__device__ __nv_bfloat16 g_Wlo [TM2 * NDIM];               // W  k-major bf16 lo
__device__ __nv_bfloat16 g_Wthi[(size_t)NDIM * TM2];       // W^T n-major bf16 hi
__device__ __nv_bfloat16 g_Wtlo[(size_t)NDIM * TM2];       // W^T n-major bf16 lo

// ---------------- helpers ----------------------------------------------------
__device__ __forceinline__ uint32_t pack_bf16x2(float a, float b) {
    uint32_t lo = (uint32_t)__bfloat16_as_ushort(__float2bfloat16(a));
    uint32_t hi = (uint32_t)__bfloat16_as_ushort(__float2bfloat16(b));
    return lo | (hi << 16);
}

// m16n8k16 row.col bf16 -> f32 accumulate (baseline PTX, plain sm_103 OK)
__device__ __forceinline__ void mma16816(float* c, const uint32_t* a,
                                         const uint32_t* b) {
    asm volatile(
        "mma.sync.aligned.m16n8k16.row.col.f32.bf16.bf16.f32 "
        "{%0,%1,%2,%3}, {%4,%5,%6,%7}, {%8,%9}, {%0,%1,%2,%3};"
        : "+f"(c[0]), "+f"(c[1]), "+f"(c[2]), "+f"(c[3])
        : "r"(a[0]), "r"(a[1]), "r"(a[2]), "r"(a[3]), "r"(b[0]), "r"(b[1]));
}

#define SMEM_U32 (4 * 64 * PITCH)          // Ahi, Alo, Bhi, Blo tiles
#define SMEM_BYTES (SMEM_U32 * 4)

// ============================================================================
// mma_nt: part[split][r][j] += sum_{k in chunk} A[r,k] * W[j,k]
// A fp32 (split to bf16 hi/lo in-kernel), B = precomputed g_Whi/g_Wlo.
// grid (rows/128, NSPLIT), 256 threads, kchunk = 512 (4 x 128 subchunks).
// ============================================================================
__global__ void __launch_bounds__(256, 1)
mma_nt(const float* __restrict__ Asrc, int lda, float* __restrict__ part,
       int rows, int kchunk) {
    extern __shared__ uint32_t sm[];
    uint32_t* sAh = sm;
    uint32_t* sAl = sm + 64 * PITCH;
    uint32_t* sBh = sm + 2 * 64 * PITCH;
    uint32_t* sBl = sm + 3 * 64 * PITCH;
    int tid = threadIdx.x;
    int lane = tid & 31, wid = tid >> 5;
    int r0 = blockIdx.x * 128;
    int k0 = blockIdx.y * kchunk;
    int mbase = (wid >> 2) * 64;
    int nbase = (wid & 3) * 32;
    int q = lane & 3, rrow = lane >> 2;

    const uint32_t* Wh = (const uint32_t*)g_Whi;
    const uint32_t* Wl = (const uint32_t*)g_Wlo;

    float acc[4][4][4];
#pragma unroll
    for (int mt = 0; mt < 4; mt++)
#pragma unroll
        for (int nt = 0; nt < 4; nt++)
#pragma unroll
            for (int e = 0; e < 4; e++) acc[mt][nt][e] = 0.f;

    for (int sc = 0; sc < kchunk; sc += 128) {
        __syncthreads();
#pragma unroll
        for (int i = 0; i < 32; i++) {
            int idx = tid + i * 256;
            int row = idx >> 6, kp = idx & 63;
            float2 v = *(const float2*)(Asrc + (size_t)(r0 + row) * lda
                                        + k0 + sc + kp * 2);
            float h0 = __bfloat162float(__float2bfloat16(v.x));
            float h1 = __bfloat162float(__float2bfloat16(v.y));
            sAh[kp * PITCH + row] = pack_bf16x2(v.x, v.y);
            sAl[kp * PITCH + row] = pack_bf16x2(v.x - h0, v.y - h1);
            size_t wo = (size_t)row * (NDIM / 2) + (size_t)(k0 + sc) / 2 + kp;
            sBh[kp * PITCH + row] = Wh[wo];
            sBl[kp * PITCH + row] = Wl[wo];
        }
        __syncthreads();

#pragma unroll
        for (int s = 0; s < 8; s++) {
            int kb = s * 8;
            uint32_t ah[4][4], al[4][4], bh[4][2], bl[4][2];
#pragma unroll
            for (int mt = 0; mt < 4; mt++) {
                int rA = mbase + mt * 16 + rrow;
                ah[mt][0] = sAh[(kb + q) * PITCH + rA];
                ah[mt][1] = sAh[(kb + q) * PITCH + rA + 8];
                ah[mt][2] = sAh[(kb + 4 + q) * PITCH + rA];
                ah[mt][3] = sAh[(kb + 4 + q) * PITCH + rA + 8];
                al[mt][0] = sAl[(kb + q) * PITCH + rA];
                al[mt][1] = sAl[(kb + q) * PITCH + rA + 8];
                al[mt][2] = sAl[(kb + 4 + q) * PITCH + rA];
                al[mt][3] = sAl[(kb + 4 + q) * PITCH + rA + 8];
            }
#pragma unroll
            for (int nt = 0; nt < 4; nt++) {
                int nB = nbase + nt * 8 + rrow;
                bh[nt][0] = sBh[(kb + q) * PITCH + nB];
                bh[nt][1] = sBh[(kb + 4 + q) * PITCH + nB];
                bl[nt][0] = sBl[(kb + q) * PITCH + nB];
                bl[nt][1] = sBl[(kb + 4 + q) * PITCH + nB];
            }
#pragma unroll
            for (int mt = 0; mt < 4; mt++)
#pragma unroll
                for (int nt = 0; nt < 4; nt++) {
                    mma16816(acc[mt][nt], ah[mt], bh[nt]);
                    mma16816(acc[mt][nt], ah[mt], bl[nt]);
                    mma16816(acc[mt][nt], al[mt], bh[nt]);
                }
        }
    }

    float* pb = part + ((size_t)blockIdx.y * rows + r0) * TM2;
#pragma unroll
    for (int mt = 0; mt < 4; mt++) {
        int row = mbase + mt * 16 + rrow;
#pragma unroll
        for (int nt = 0; nt < 4; nt++) {
            int col = nbase + nt * 8 + 2 * q;
            *(float2*)&pb[(size_t)row * TM2 + col] =
                make_float2(acc[mt][nt][0], acc[mt][nt][1]);
            *(float2*)&pb[(size_t)(row + 8) * TM2 + col] =
                make_float2(acc[mt][nt][2], acc[mt][nt][3]);
        }
    }
}

// deterministic fixed-order split-K reduction (natural row-major layout)
__global__ void reduce_nt(const float4* __restrict__ part,
                          float4* __restrict__ out, int count4, int nsplit) {
    int i = blockIdx.x * 256 + threadIdx.x;
    if (i < count4) {
        float4 s = make_float4(0.f, 0.f, 0.f, 0.f);
        for (int k = 0; k < nsplit; k++) {
            float4 v = part[(size_t)k * count4 + i];
            s.x += v.x; s.y += v.y; s.z += v.z; s.w += v.w;
        }
        out[i] = s;
    }
}

// ============================================================================
// mma_nn: X[b,n] = relu(rn_r[b,n] + sum_k s[b,k] * W[k,n]); K = 128.
// B = g_Wthi/g_Wtlo (n-major, K-contig). grid (NDIM/128, BATCH/128), 256 thr.
// ============================================================================
__global__ void __launch_bounds__(256, 1)
mma_nn(const float* __restrict__ rn, float* __restrict__ outx, int final_out) {
    extern __shared__ uint32_t sm[];
    uint32_t* sAh = sm;
    uint32_t* sAl = sm + 64 * PITCH;
    uint32_t* sBh = sm + 2 * 64 * PITCH;
    uint32_t* sBl = sm + 3 * 64 * PITCH;
    int tid = threadIdx.x;
    int lane = tid & 31, wid = tid >> 5;
    int n0 = blockIdx.x * 128;
    int r0 = blockIdx.y * 128;
    int mbase = (wid >> 2) * 64;
    int nbase = (wid & 3) * 32;
    int q = lane & 3, rrow = lane >> 2;

    const uint32_t* Wth = (const uint32_t*)g_Wthi;
    const uint32_t* Wtl = (const uint32_t*)g_Wtlo;

#pragma unroll
    for (int i = 0; i < 32; i++) {
        int idx = tid + i * 256;
        int row = idx >> 6, kp = idx & 63;
        float2 v = *(const float2*)(g_s + (size_t)(r0 + row) * TM2 + kp * 2);
        float h0 = __bfloat162float(__float2bfloat16(v.x));
        float h1 = __bfloat162float(__float2bfloat16(v.y));
        sAh[kp * PITCH + row] = pack_bf16x2(v.x, v.y);
        sAl[kp * PITCH + row] = pack_bf16x2(v.x - h0, v.y - h1);
        size_t wo = (size_t)(n0 + row) * 64 + kp;
        sBh[kp * PITCH + row] = Wth[wo];
        sBl[kp * PITCH + row] = Wtl[wo];
    }
    __syncthreads();

    float acc[4][4][4];
#pragma unroll
    for (int mt = 0; mt < 4; mt++)
#pragma unroll
        for (int nt = 0; nt < 4; nt++)
#pragma unroll
            for (int e = 0; e < 4; e++) acc[mt][nt][e] = 0.f;

#pragma unroll
    for (int s = 0; s < 8; s++) {
        int kb = s * 8;
        uint32_t ah[4][4], al[4][4], bh[4][2], bl[4][2];
#pragma unroll
        for (int mt = 0; mt < 4; mt++) {
            int rA = mbase + mt * 16 + rrow;
            ah[mt][0] = sAh[(kb + q) * PITCH + rA];
            ah[mt][1] = sAh[(kb + q) * PITCH + rA + 8];
            ah[mt][2] = sAh[(kb + 4 + q) * PITCH + rA];
            ah[mt][3] = sAh[(kb + 4 + q) * PITCH + rA + 8];
            al[mt][0] = sAl[(kb + q) * PITCH + rA];
            al[mt][1] = sAl[(kb + q) * PITCH + rA + 8];
            al[mt][2] = sAl[(kb + 4 + q) * PITCH + rA];
            al[mt][3] = sAl[(kb + 4 + q) * PITCH + rA + 8];
        }
#pragma unroll
        for (int nt = 0; nt < 4; nt++) {
            int nB = nbase + nt * 8 + rrow;
            bh[nt][0] = sBh[(kb + q) * PITCH + nB];
            bh[nt][1] = sBh[(kb + 4 + q) * PITCH + nB];
            bl[nt][0] = sBl[(kb + q) * PITCH + nB];
            bl[nt][1] = sBl[(kb + 4 + q) * PITCH + nB];
        }
#pragma unroll
        for (int mt = 0; mt < 4; mt++)
#pragma unroll
            for (int nt = 0; nt < 4; nt++) {
                mma16816(acc[mt][nt], ah[mt], bh[nt]);
                mma16816(acc[mt][nt], ah[mt], bl[nt]);
                mma16816(acc[mt][nt], al[mt], bh[nt]);
            }
    }

    float2 zero2 = make_float2(0.f, 0.f);
#pragma unroll
    for (int mt = 0; mt < 4; mt++) {
#pragma unroll
        for (int half = 0; half < 2; half++) {
            int row = mbase + mt * 16 + rrow + half * 8;
            int r = r0 + row;
#pragma unroll
            for (int nt = 0; nt < 4; nt++) {
                int col = n0 + nbase + nt * 8 + 2 * q;
                float2 rv = *(const float2*)(rn + (size_t)r * (2 * NDIM) + col);
                float c0 = acc[mt][nt][half * 2 + 0] + rv.x;
                float c1 = acc[mt][nt][half * 2 + 1] + rv.y;
                float2 o = make_float2(fmaxf(c0, 0.f), fmaxf(c1, 0.f));
                if (final_out) {
                    size_t base = (size_t)r * (2 * NDIM);
                    *(float2*)(outx + base + col) = o;
                    *(float2*)(outx + base + NDIM + col) = zero2;
                } else {
                    *(float2*)(g_X + (size_t)r * NDIM + col) = o;
                }
            }
        }
    }
}

// ---------------- W bf16 precompute -----------------------------------------
__global__ void conv_W(const float* __restrict__ W) {
    int i = blockIdx.x * 256 + threadIdx.x;
    if (i < TM2 * NDIM) {
        float v = W[i];
        __nv_bfloat16 h = __float2bfloat16(v);
        g_Whi[i] = h;
        g_Wlo[i] = __float2bfloat16(v - __bfloat162float(h));
    }
}
__global__ void conv_Wt(const float* __restrict__ W) {
    __shared__ float t[32][33];
    int bx = blockIdx.x * 32;   // n tile
    int by = blockIdx.y * 32;   // k tile
    for (int yy = threadIdx.y; yy < 32; yy += 8)
        t[yy][threadIdx.x] = W[(size_t)(by + yy) * NDIM + bx + threadIdx.x];
    __syncthreads();
    for (int ny = threadIdx.y; ny < 32; ny += 8) {
        float v = t[threadIdx.x][ny];
        __nv_bfloat16 h = __float2bfloat16(v);
        size_t o = (size_t)(bx + ny) * TM2 + by + threadIdx.x;
        g_Wthi[o] = h;
        g_Wtlo[o] = __float2bfloat16(v - __bfloat162float(h));
    }
}

// ---------------- build G and S = G + I/rho ---------------------------------
__global__ void build_S(const float* __restrict__ log_rho) {
    int idx = blockIdx.x * blockDim.x + threadIdx.x;
    float inv_rho = 1.f / (expf(log_rho[0]) + 1e-12f);
    int p = idx >> 7, q = idx & 127;
    float sgn = ((p < 64) == (q < 64)) ? 1.f : -1.f;
    float g = g_M[idx] + sgn * g_M[((p ^ 64) << 7) + (q ^ 64)];
    g_G[idx] = g;
    g_S[idx] = g + ((p == q) ? inv_rho : 0.f);
}

// ---------------- Newton-Schulz inverse -------------------------------------
__global__ void gersh_initX1() {
    __shared__ float smax[4], smin[4], s_x0;
    int i = threadIdx.x;    // 128
    float rs = 0.f, dg = 0.f;
#pragma unroll 8
    for (int k = 0; k < 128; k++) {
        float v = g_S[i * 128 + k];
        rs += fabsf(v);
        if (k == i) dg = v;
    }
    float lo = 2.f * dg - rs;
    float mx = rs, mn = lo;
#pragma unroll
    for (int o = 16; o > 0; o >>= 1) {
        mx = fmaxf(mx, __shfl_down_sync(0xffffffffu, mx, o));
        mn = fminf(mn, __shfl_down_sync(0xffffffffu, mn, o));
    }
    if ((i & 31) == 0) { smax[i >> 5] = mx; smin[i >> 5] = mn; }
    __syncthreads();
    if (i == 0) {
        float lmax = fmaxf(fmaxf(smax[0], smax[1]), fmaxf(smax[2], smax[3]));
        float lmin = fminf(fminf(smin[0], smin[1]), fminf(smin[2], smin[3]));
        s_x0 = (lmin > 0.f) ? 2.f / (lmax + lmin) : 1.f / lmax;
    }
    __syncthreads();
    float x0 = s_x0;
    for (int e = i; e < 128 * 128; e += 128) {
        int p = e >> 7, q = e & 127;
        g_NSa[e] = 2.f * x0 * ((p == q) ? 1.f : 0.f) - x0 * x0 * g_S[e];
    }
}

__global__ void __launch_bounds__(256)
ns_SX(const float* __restrict__ X, float* __restrict__ Y) {
    __shared__ float As[2][128];
    int tid = threadIdx.x;
    int r0 = blockIdx.x * 2;
    int rr = tid >> 7, j = tid & 127;
    As[rr][j] = g_S[(r0 + rr) * 128 + j];
    __syncthreads();
    float acc = 0.f;
#pragma unroll 8
    for (int k = 0; k < 128; k++)
        acc = fmaf(As[rr][k], X[k * 128 + j], acc);
    Y[(r0 + rr) * 128 + j] = acc;
}
__global__ void __launch_bounds__(256)
ns_update(const float* __restrict__ X, const float* __restrict__ Y,
          float* __restrict__ Xn) {
    __shared__ float As[2][128];
    int tid = threadIdx.x;
    int r0 = blockIdx.x * 2;
    int rr = tid >> 7, j = tid & 127;
    As[rr][j] = X[(r0 + rr) * 128 + j];
    __syncthreads();
    float acc = 0.f;
#pragma unroll 8
    for (int k = 0; k < 128; k++)
        acc = fmaf(As[rr][k], Y[k * 128 + j], acc);
    Xn[(r0 + rr) * 128 + j] = 2.f * As[rr][j] - acc;
}

__global__ void compute_HT(const float* __restrict__ Sinv,
                           const float* __restrict__ log_rho) {
    __shared__ float gk[128];
    int j = threadIdx.x, k = blockIdx.x;
    float rho = expf(log_rho[0]);
    gk[j] = g_G[k * 128 + j];
    __syncthreads();
    float acc = 0.f;
#pragma unroll 4
    for (int m = 0; m < 128; m++)
        acc = fmaf(Sinv[m * 128 + j], gk[m], acc);
    g_HT[k * 128 + j] = rho * (((j == k) ? 1.f : 0.f) - acc);
}

__global__ void init_zu(const float* __restrict__ y,
                        const float* __restrict__ u_in) {
    int i = blockIdx.x * blockDim.x + threadIdx.x;
    if (i < BATCH * TM2) { g_z[i] = y[i]; g_u[i] = u_in[i]; }
}

// d = Sinv @ c, c assembled from rn projections g_R (row 2b real, 2b+1 imag)
__global__ void precompute_d(const float* __restrict__ Sinv) {
    __shared__ float cb[8][128];
    int tid = threadIdx.x;
    int b0 = blockIdx.x * 8;
#pragma unroll
    for (int bb = 0; bb < 8; bb++) {
        int b = b0 + bb, j = tid;
        float pa = g_R[(size_t)(2 * b) * TM2 + j];
        float pb = g_R[(size_t)(2 * b + 1) * TM2 + (j ^ 64)];
        cb[bb][j] = (j < 64) ? pa - pb : pa + pb;
    }
    __syncthreads();
    float acc[8];
#pragma unroll
    for (int bb = 0; bb < 8; bb++) acc[bb] = 0.f;
    for (int k = 0; k < 128; k++) {
        float sv = Sinv[k * 128 + tid];
#pragma unroll
        for (int bb = 0; bb < 8; bb++) acc[bb] = fmaf(sv, cb[bb][k], acc[bb]);
    }
#pragma unroll
    for (int bb = 0; bb < 8; bb++)
        g_d[(b0 + bb) * TM2 + tid] = acc[bb];
}

__global__ void s_kernel2() {
    __shared__ float w[8][128];
    int tid = threadIdx.x;
    int b0 = blockIdx.x * 8;
#pragma unroll
    for (int bb = 0; bb < 8; bb++)
        w[bb][tid] = g_z[(b0 + bb) * TM2 + tid] - g_u[(b0 + bb) * TM2 + tid];
    __syncthreads();
    float acc[8];
#pragma unroll
    for (int bb = 0; bb < 8; bb++) acc[bb] = 0.f;
    for (int k = 0; k < 128; k++) {
        float h = g_HT[k * 128 + tid];
#pragma unroll
        for (int bb = 0; bb < 8; bb++) acc[bb] = fmaf(h, w[bb][k], acc[bb]);
    }
#pragma unroll
    for (int bb = 0; bb < 8; bb++)
        g_s[(b0 + bb) * TM2 + tid] = acc[bb] - g_d[(b0 + bb) * TM2 + tid];
}

__global__ void zu_update(const float* __restrict__ y,
                          const float* __restrict__ log_eps) {
    __shared__ float red[4];
    int b = blockIdx.x;
    int j = threadIdx.x;
    float eps = expf(log_eps[0]);
    float Pv = g_P[b * TM2 + j];
    float uv = g_u[b * TM2 + j];
    float yv = y[b * TM2 + j];
    float v = Pv + uv - yv;
    float t = v * v;
#pragma unroll
    for (int o = 16; o > 0; o >>= 1) t += __shfl_down_sync(0xffffffffu, t, o);
    if ((j & 31) == 0) red[j >> 5] = t;
    __syncthreads();
    float nrm = sqrtf(red[0] + red[1] + red[2] + red[3]);
    float scale = fminf(1.f, eps / (nrm + 1e-12f));
    float zv = yv + v * scale;
    g_z[b * TM2 + j] = zv;
    g_u[b * TM2 + j] = uv + Pv - zv;
}

__global__ void write_u(float* __restrict__ out) {
    int i = blockIdx.x * blockDim.x + threadIdx.x;
    if (i < BATCH * TM2)
        out[(size_t)BATCH * 2 * NDIM + i] = g_u[i];
}

// ---------------- launch ----------------------------------------------------
extern "C" void kernel_launch(void* const* d_in, const int* in_sizes, int n_in,
                              void* d_out, int out_size) {
    const float* rn   = (const float*)d_in[0];
    const float* y    = (const float*)d_in[1];
    const float* u_in = (const float*)d_in[2];
    const float* A    = (const float*)d_in[3];
    const float* lrho = (const float*)d_in[4];
    const float* leps = (const float*)d_in[5];
    float* out = (float*)d_out;
    (void)in_sizes; (void)n_in; (void)out_size;

    float *dX, *dM, *dR, *dP, *dPart, *dNSa, *dNSb, *dY;
    cudaGetSymbolAddress((void**)&dX,    g_X);
    cudaGetSymbolAddress((void**)&dM,    g_M);
    cudaGetSymbolAddress((void**)&dR,    g_R);
    cudaGetSymbolAddress((void**)&dP,    g_P);
    cudaGetSymbolAddress((void**)&dPart, g_part);
    cudaGetSymbolAddress((void**)&dNSa,  g_NSa);
    cudaGetSymbolAddress((void**)&dNSb,  g_NSb);
    cudaGetSymbolAddress((void**)&dY,    g_Y);

    static int attr_set = 0;
    if (!attr_set) {
        cudaFuncSetAttribute(mma_nt, cudaFuncAttributeMaxDynamicSharedMemorySize,
                             SMEM_BYTES);
        cudaFuncSetAttribute(mma_nn, cudaFuncAttributeMaxDynamicSharedMemorySize,
                             SMEM_BYTES);
        attr_set = 1;
    }

    // bf16 splits of W (both layouts)
    conv_W<<<(TM2 * NDIM + 255) / 256, 256>>>(A);
    conv_Wt<<<dim3(NDIM / 32, TM2 / 32), dim3(32, 8)>>>(A);

    // M = W W^T via HMMA, then S
    mma_nt<<<dim3(1, NSPLIT), 256, SMEM_BYTES>>>(A, NDIM, dPart, 128, KCHUNK);
    reduce_nt<<<(128 * 32 + 255) / 256, 256>>>((const float4*)dPart,
                                               (float4*)dM, 128 * 32, NSPLIT);
    build_S<<<64, 256>>>(lrho);

    // Newton-Schulz inverse (4 steps)
    gersh_initX1<<<1, 128>>>();
    float* cur = dNSa;
    float* nxt = dNSb;
    for (int t = 0; t < 4; t++) {
        ns_SX<<<64, 256>>>(cur, dY);
        ns_update<<<64, 256>>>(cur, dY, nxt);
        float* tmp = cur; cur = nxt; nxt = tmp;
    }
    const float* Sinv = cur;

    compute_HT<<<128, 128>>>(Sinv, lrho);
    init_zu<<<(BATCH * TM2 + 255) / 256, 256>>>(y, u_in);

    // rn projections (2048 rows), then d = Sinv c
    mma_nt<<<dim3(16, NSPLIT), 256, SMEM_BYTES>>>(rn, NDIM, dPart, 2048, KCHUNK);
    reduce_nt<<<(2048 * 32 + 255) / 256, 256>>>((const float4*)dPart,
                                                (float4*)dR, 2048 * 32, NSPLIT);
    precompute_d<<<128, 128>>>(Sinv);

    for (int it = 0; it < 3; it++) {
        int fin = (it == 2);
        s_kernel2<<<BATCH / 8, 128>>>();
        mma_nn<<<dim3(NDIM / 128, BATCH / 128), 256, SMEM_BYTES>>>(rn, out, fin);
        const float* xsrc = fin ? (const float*)out : (const float*)dX;
        int ldx = fin ? 2 * NDIM : NDIM;
        mma_nt<<<dim3(BATCH / 128, NSPLIT), 256, SMEM_BYTES>>>(xsrc, ldx, dPart,
                                                               BATCH, KCHUNK);
        reduce_nt<<<(BATCH * 32 + 255) / 256, 256>>>((const float4*)dPart,
                                                     (float4*)dP, BATCH * 32,
                                                     NSPLIT);
        zu_update<<<BATCH, 128>>>(y, leps);
    }

    write_u<<<(BATCH * TM2 + 255) / 256, 256>>>(out);
}

// round 10
// speedup vs baseline: 8.8543x; 1.2244x over previous
#include <cuda_runtime.h>
#include <cuda_bf16.h>
#include <math.h>
#include <stdint.h>

#define BATCH 1024
#define NDIM  8192
#define TM2   128
#define NSPLIT 16
#define KCHUNK 512

// fragment-order smem tile sizes (u32)
#define A_TILE_STRIDE 136     // 128 payload + 8 pad (16x8kp tile)
#define B_TILE_STRIDE 72      // 64 payload + 8 pad (8x8kp tile)
#define A_REGION (64 * A_TILE_STRIDE)   // 8 rowtiles x 8 ktiles
#define B_REGION (128 * B_TILE_STRIDE)  // 16 ntiles x 8 ktiles
#define SMEM_U32 (2 * A_REGION + 2 * B_REGION)
#define SMEM_BYTES (SMEM_U32 * 4)       // 143360

// ---------------- scratch (static device globals; no runtime alloc) --------
__device__ float g_X[BATCH * NDIM];                        // 32 MB
__device__ float g_part[(size_t)64 * 2048 * TM2];          // split-K partials
__device__ float g_R [2048 * TM2];
__device__ float g_d [BATCH * TM2];
__device__ float g_u [BATCH * TM2];
__device__ float g_s [BATCH * TM2];
__device__ float g_M   [TM2 * TM2];
__device__ float g_G   [TM2 * TM2];
__device__ float g_S   [TM2 * TM2];
__device__ float g_NSa [TM2 * TM2];
__device__ float g_NSb [TM2 * TM2];
__device__ float g_Y   [TM2 * TM2];
__device__ float g_HT  [TM2 * TM2];
__device__ __nv_bfloat16 g_Whi [TM2 * NDIM];               // W  k-major bf16 hi
__device__ __nv_bfloat16 g_Wlo [TM2 * NDIM];               // W  k-major bf16 lo
__device__ __nv_bfloat16 g_Wthi[(size_t)NDIM * TM2];       // W^T n-major bf16 hi
__device__ __nv_bfloat16 g_Wtlo[(size_t)NDIM * TM2];       // W^T n-major bf16 lo

// ---------------- helpers ----------------------------------------------------
__device__ __forceinline__ uint32_t pack_bf16x2(float a, float b) {
    uint32_t lo = (uint32_t)__bfloat16_as_ushort(__float2bfloat16(a));
    uint32_t hi = (uint32_t)__bfloat16_as_ushort(__float2bfloat16(b));
    return lo | (hi << 16);
}

// m16n8k16 row.col bf16 -> f32 accumulate (baseline PTX)
__device__ __forceinline__ void mma16816(float* c, const uint4& a,
                                         const uint2& b) {
    asm volatile(
        "mma.sync.aligned.m16n8k16.row.col.f32.bf16.bf16.f32 "
        "{%0,%1,%2,%3}, {%4,%5,%6,%7}, {%8,%9}, {%0,%1,%2,%3};"
        : "+f"(c[0]), "+f"(c[1]), "+f"(c[2]), "+f"(c[3])
        : "r"(a.x), "r"(a.y), "r"(a.z), "r"(a.w), "r"(b.x), "r"(b.y));
}

// fragment-order addresses: value (row,kp) -> lane/reg slot of its mma tile
// A (16 rows x 8 kpairs): lane=(row&7)*4+(kp&3), reg=((row>>3)&1)|(((kp>>2)&1)<<1)
__device__ __forceinline__ uint32_t a_addr(int row, int kp) {
    uint32_t tile = (uint32_t)((row >> 4) * 8 + (kp >> 3));
    uint32_t lane = ((row & 7) << 2) + (kp & 3);
    uint32_t reg = ((row >> 3) & 1) | (((kp >> 2) & 1) << 1);
    return tile * A_TILE_STRIDE + lane * 4 + reg;
}
// B (8 n x 8 kpairs): lane=(n&7)*4+(kp&3), reg=(kp>>2)&1
__device__ __forceinline__ uint32_t b_addr(int n, int kp) {
    uint32_t tile = (uint32_t)((n >> 3) * 8 + (kp >> 3));
    uint32_t lane = ((n & 7) << 2) + (kp & 3);
    uint32_t reg = (kp >> 2) & 1;
    return tile * B_TILE_STRIDE + lane * 2 + reg;
}

// ============================================================================
// mma_nt: part[split][r][j] = sum_{k in chunk} A[r,k] * W[j,k]
// 512 threads, 128x128 tile, 4x4 warp grid (32x32 warp tiles).
// ============================================================================
__global__ void __launch_bounds__(512, 1)
mma_nt(const float* __restrict__ Asrc, int lda, float* __restrict__ part,
       int rows, int kchunk) {
    extern __shared__ uint32_t sm[];
    uint32_t* sAh = sm;
    uint32_t* sAl = sm + A_REGION;
    uint32_t* sBh = sm + 2 * A_REGION;
    uint32_t* sBl = sm + 2 * A_REGION + B_REGION;
    int tid = threadIdx.x;
    int lane = tid & 31, wid = tid >> 5;
    int wr = wid >> 2, wc = wid & 3;
    int r0 = blockIdx.x * 128;
    int k0 = blockIdx.y * kchunk;
    int q = lane & 3, g = lane >> 2;

    const uint32_t* Wh = (const uint32_t*)g_Whi;
    const uint32_t* Wl = (const uint32_t*)g_Wlo;

    float acc[2][4][4];
#pragma unroll
    for (int mt = 0; mt < 2; mt++)
#pragma unroll
        for (int nt = 0; nt < 4; nt++)
#pragma unroll
            for (int e = 0; e < 4; e++) acc[mt][nt][e] = 0.f;

    for (int sc = 0; sc < kchunk; sc += 128) {
        __syncthreads();
#pragma unroll
        for (int i = 0; i < 16; i++) {
            int idx = tid + i * 512;
            int row = idx >> 6, kp = idx & 63;
            float2 v = *(const float2*)(Asrc + (size_t)(r0 + row) * lda
                                        + k0 + sc + kp * 2);
            float h0 = __bfloat162float(__float2bfloat16(v.x));
            float h1 = __bfloat162float(__float2bfloat16(v.y));
            uint32_t aa = a_addr(row, kp);
            sAh[aa] = pack_bf16x2(v.x, v.y);
            sAl[aa] = pack_bf16x2(v.x - h0, v.y - h1);
            size_t wo = (size_t)row * (NDIM / 2) + (size_t)(k0 + sc) / 2 + kp;
            uint32_t ba = b_addr(row, kp);
            sBh[ba] = Wh[wo];
            sBl[ba] = Wl[wo];
        }
        __syncthreads();

#pragma unroll
        for (int s = 0; s < 8; s++) {
            uint4 ah[2], al[2];
            uint2 bh[4], bl[4];
#pragma unroll
            for (int mt = 0; mt < 2; mt++) {
                uint32_t base = (uint32_t)(((wr * 2 + mt) * 8 + s) * A_TILE_STRIDE
                                           + lane * 4);
                ah[mt] = *(const uint4*)(sAh + base);
                al[mt] = *(const uint4*)(sAl + base);
            }
#pragma unroll
            for (int nt = 0; nt < 4; nt++) {
                uint32_t base = (uint32_t)(((wc * 4 + nt) * 8 + s) * B_TILE_STRIDE
                                           + lane * 2);
                bh[nt] = *(const uint2*)(sBh + base);
                bl[nt] = *(const uint2*)(sBl + base);
            }
#pragma unroll
            for (int mt = 0; mt < 2; mt++)
#pragma unroll
                for (int nt = 0; nt < 4; nt++) {
                    mma16816(acc[mt][nt], ah[mt], bh[nt]);
                    mma16816(acc[mt][nt], ah[mt], bl[nt]);
                    mma16816(acc[mt][nt], al[mt], bh[nt]);
                }
        }
    }

    float* pb = part + ((size_t)blockIdx.y * rows + r0) * TM2;
#pragma unroll
    for (int mt = 0; mt < 2; mt++) {
        int row = wr * 32 + mt * 16 + g;
#pragma unroll
        for (int nt = 0; nt < 4; nt++) {
            int col = wc * 32 + nt * 8 + 2 * q;
            *(float2*)&pb[(size_t)row * TM2 + col] =
                make_float2(acc[mt][nt][0], acc[mt][nt][1]);
            *(float2*)&pb[(size_t)(row + 8) * TM2 + col] =
                make_float2(acc[mt][nt][2], acc[mt][nt][3]);
        }
    }
}

// deterministic fixed-order split-K reduction
__global__ void reduce_nt(const float4* __restrict__ part,
                          float4* __restrict__ out, int count4, int nsplit) {
    int i = blockIdx.x * 256 + threadIdx.x;
    if (i < count4) {
        float4 s = make_float4(0.f, 0.f, 0.f, 0.f);
        for (int k = 0; k < nsplit; k++) {
            float4 v = part[(size_t)k * count4 + i];
            s.x += v.x; s.y += v.y; s.z += v.z; s.w += v.w;
        }
        out[i] = s;
    }
}

// ============================================================================
// mma_nn: X[b,n] = relu(rn_r[b,n] + sum_k s[b,k] * W[k,n]); K = 128.
// grid (NDIM/128, BATCH/128), 512 threads.
// ============================================================================
__global__ void __launch_bounds__(512, 1)
mma_nn(const float* __restrict__ rn, float* __restrict__ outx, int final_out) {
    extern __shared__ uint32_t sm[];
    uint32_t* sAh = sm;
    uint32_t* sAl = sm + A_REGION;
    uint32_t* sBh = sm + 2 * A_REGION;
    uint32_t* sBl = sm + 2 * A_REGION + B_REGION;
    int tid = threadIdx.x;
    int lane = tid & 31, wid = tid >> 5;
    int wr = wid >> 2, wc = wid & 3;
    int n0 = blockIdx.x * 128;
    int r0 = blockIdx.y * 128;
    int q = lane & 3, g = lane >> 2;

    const uint32_t* Wth = (const uint32_t*)g_Wthi;
    const uint32_t* Wtl = (const uint32_t*)g_Wtlo;

#pragma unroll
    for (int i = 0; i < 16; i++) {
        int idx = tid + i * 512;
        int row = idx >> 6, kp = idx & 63;
        float2 v = *(const float2*)(g_s + (size_t)(r0 + row) * TM2 + kp * 2);
        float h0 = __bfloat162float(__float2bfloat16(v.x));
        float h1 = __bfloat162float(__float2bfloat16(v.y));
        uint32_t aa = a_addr(row, kp);
        sAh[aa] = pack_bf16x2(v.x, v.y);
        sAl[aa] = pack_bf16x2(v.x - h0, v.y - h1);
        size_t wo = (size_t)(n0 + row) * 64 + kp;
        uint32_t ba = b_addr(row, kp);
        sBh[ba] = Wth[wo];
        sBl[ba] = Wtl[wo];
    }
    __syncthreads();

    float acc[2][4][4];
#pragma unroll
    for (int mt = 0; mt < 2; mt++)
#pragma unroll
        for (int nt = 0; nt < 4; nt++)
#pragma unroll
            for (int e = 0; e < 4; e++) acc[mt][nt][e] = 0.f;

#pragma unroll
    for (int s = 0; s < 8; s++) {
        uint4 ah[2], al[2];
        uint2 bh[4], bl[4];
#pragma unroll
        for (int mt = 0; mt < 2; mt++) {
            uint32_t base = (uint32_t)(((wr * 2 + mt) * 8 + s) * A_TILE_STRIDE
                                       + lane * 4);
            ah[mt] = *(const uint4*)(sAh + base);
            al[mt] = *(const uint4*)(sAl + base);
        }
#pragma unroll
        for (int nt = 0; nt < 4; nt++) {
            uint32_t base = (uint32_t)(((wc * 4 + nt) * 8 + s) * B_TILE_STRIDE
                                       + lane * 2);
            bh[nt] = *(const uint2*)(sBh + base);
            bl[nt] = *(const uint2*)(sBl + base);
        }
#pragma unroll
        for (int mt = 0; mt < 2; mt++)
#pragma unroll
            for (int nt = 0; nt < 4; nt++) {
                mma16816(acc[mt][nt], ah[mt], bh[nt]);
                mma16816(acc[mt][nt], ah[mt], bl[nt]);
                mma16816(acc[mt][nt], al[mt], bh[nt]);
            }
    }

    float2 zero2 = make_float2(0.f, 0.f);
#pragma unroll
    for (int mt = 0; mt < 2; mt++) {
#pragma unroll
        for (int half = 0; half < 2; half++) {
            int row = wr * 32 + mt * 16 + g + half * 8;
            int r = r0 + row;
#pragma unroll
            for (int nt = 0; nt < 4; nt++) {
                int col = n0 + wc * 32 + nt * 8 + 2 * q;
                float2 rv = *(const float2*)(rn + (size_t)r * (2 * NDIM) + col);
                float c0 = acc[mt][nt][half * 2 + 0] + rv.x;
                float c1 = acc[mt][nt][half * 2 + 1] + rv.y;
                float2 o = make_float2(fmaxf(c0, 0.f), fmaxf(c1, 0.f));
                if (final_out) {
                    size_t base = (size_t)r * (2 * NDIM);
                    *(float2*)(outx + base + col) = o;
                    *(float2*)(outx + base + NDIM + col) = zero2;
                } else {
                    *(float2*)(g_X + (size_t)r * NDIM + col) = o;
                }
            }
        }
    }
}

// ---------------- W bf16 precompute -----------------------------------------
__global__ void conv_W(const float* __restrict__ W) {
    int i = blockIdx.x * 256 + threadIdx.x;
    if (i < TM2 * NDIM) {
        float v = W[i];
        __nv_bfloat16 h = __float2bfloat16(v);
        g_Whi[i] = h;
        g_Wlo[i] = __float2bfloat16(v - __bfloat162float(h));
    }
}
__global__ void conv_Wt(const float* __restrict__ W) {
    __shared__ float t[32][33];
    int bx = blockIdx.x * 32;   // n tile
    int by = blockIdx.y * 32;   // k tile
    for (int yy = threadIdx.y; yy < 32; yy += 8)
        t[yy][threadIdx.x] = W[(size_t)(by + yy) * NDIM + bx + threadIdx.x];
    __syncthreads();
    for (int ny = threadIdx.y; ny < 32; ny += 8) {
        float v = t[threadIdx.x][ny];
        __nv_bfloat16 h = __float2bfloat16(v);
        size_t o = (size_t)(bx + ny) * TM2 + by + threadIdx.x;
        g_Wthi[o] = h;
        g_Wtlo[o] = __float2bfloat16(v - __bfloat162float(h));
    }
}

// ---------------- build G and S = G + I/rho ---------------------------------
__global__ void build_S(const float* __restrict__ log_rho) {
    int idx = blockIdx.x * blockDim.x + threadIdx.x;
    float inv_rho = 1.f / (expf(log_rho[0]) + 1e-12f);
    int p = idx >> 7, q = idx & 127;
    float sgn = ((p < 64) == (q < 64)) ? 1.f : -1.f;
    float g = g_M[idx] + sgn * g_M[((p ^ 64) << 7) + (q ^ 64)];
    g_G[idx] = g;
    g_S[idx] = g + ((p == q) ? inv_rho : 0.f);
}

// ---------------- Newton-Schulz inverse -------------------------------------
__global__ void gersh_initX1() {
    __shared__ float smax[4], smin[4], s_x0;
    int i = threadIdx.x;    // 128
    float rs = 0.f, dg = 0.f;
#pragma unroll 8
    for (int k = 0; k < 128; k++) {
        float v = g_S[i * 128 + k];
        rs += fabsf(v);
        if (k == i) dg = v;
    }
    float lo = 2.f * dg - rs;
    float mx = rs, mn = lo;
#pragma unroll
    for (int o = 16; o > 0; o >>= 1) {
        mx = fmaxf(mx, __shfl_down_sync(0xffffffffu, mx, o));
        mn = fminf(mn, __shfl_down_sync(0xffffffffu, mn, o));
    }
    if ((i & 31) == 0) { smax[i >> 5] = mx; smin[i >> 5] = mn; }
    __syncthreads();
    if (i == 0) {
        float lmax = fmaxf(fmaxf(smax[0], smax[1]), fmaxf(smax[2], smax[3]));
        float lmin = fminf(fminf(smin[0], smin[1]), fminf(smin[2], smin[3]));
        s_x0 = (lmin > 0.f) ? 2.f / (lmax + lmin) : 1.f / lmax;
    }
    __syncthreads();
    float x0 = s_x0;
    for (int e = i; e < 128 * 128; e += 128) {
        int p = e >> 7, q = e & 127;
        g_NSa[e] = 2.f * x0 * ((p == q) ? 1.f : 0.f) - x0 * x0 * g_S[e];
    }
}

__global__ void __launch_bounds__(256)
ns_SX(const float* __restrict__ X, float* __restrict__ Y) {
    __shared__ float As[2][128];
    int tid = threadIdx.x;
    int r0 = blockIdx.x * 2;
    int rr = tid >> 7, j = tid & 127;
    As[rr][j] = g_S[(r0 + rr) * 128 + j];
    __syncthreads();
    float acc = 0.f;
#pragma unroll 8
    for (int k = 0; k < 128; k++)
        acc = fmaf(As[rr][k], X[k * 128 + j], acc);
    Y[(r0 + rr) * 128 + j] = acc;
}
__global__ void __launch_bounds__(256)
ns_update(const float* __restrict__ X, const float* __restrict__ Y,
          float* __restrict__ Xn) {
    __shared__ float As[2][128];
    int tid = threadIdx.x;
    int r0 = blockIdx.x * 2;
    int rr = tid >> 7, j = tid & 127;
    As[rr][j] = X[(r0 + rr) * 128 + j];
    __syncthreads();
    float acc = 0.f;
#pragma unroll 8
    for (int k = 0; k < 128; k++)
        acc = fmaf(As[rr][k], Y[k * 128 + j], acc);
    Xn[(r0 + rr) * 128 + j] = 2.f * As[rr][j] - acc;
}

__global__ void compute_HT(const float* __restrict__ Sinv,
                           const float* __restrict__ log_rho) {
    __shared__ float gk[128];
    int j = threadIdx.x, k = blockIdx.x;
    float rho = expf(log_rho[0]);
    gk[j] = g_G[k * 128 + j];
    __syncthreads();
    float acc = 0.f;
#pragma unroll 4
    for (int m = 0; m < 128; m++)
        acc = fmaf(Sinv[m * 128 + j], gk[m], acc);
    g_HT[k * 128 + j] = rho * (((j == k) ? 1.f : 0.f) - acc);
}

// d = Sinv @ c, c assembled from rn projections g_R (row 2b real, 2b+1 imag)
__global__ void precompute_d(const float* __restrict__ Sinv) {
    __shared__ float cb[8][128];
    int tid = threadIdx.x;
    int b0 = blockIdx.x * 8;
#pragma unroll
    for (int bb = 0; bb < 8; bb++) {
        int b = b0 + bb, j = tid;
        float pa = g_R[(size_t)(2 * b) * TM2 + j];
        float pb = g_R[(size_t)(2 * b + 1) * TM2 + (j ^ 64)];
        cb[bb][j] = (j < 64) ? pa - pb : pa + pb;
    }
    __syncthreads();
    float acc[8];
#pragma unroll
    for (int bb = 0; bb < 8; bb++) acc[bb] = 0.f;
    for (int k = 0; k < 128; k++) {
        float sv = Sinv[k * 128 + tid];
#pragma unroll
        for (int bb = 0; bb < 8; bb++) acc[bb] = fmaf(sv, cb[bb][k], acc[bb]);
    }
#pragma unroll
    for (int bb = 0; bb < 8; bb++)
        g_d[(b0 + bb) * TM2 + tid] = acc[bb];
}

// s for iteration 0: w = y - u_in; s = H w - d; also init g_u = u_in
__global__ void s_init(const float* __restrict__ y,
                       const float* __restrict__ u_in) {
    __shared__ float w[8][128];
    int tid = threadIdx.x;
    int b0 = blockIdx.x * 8;
#pragma unroll
    for (int bb = 0; bb < 8; bb++) {
        float uv = u_in[(b0 + bb) * TM2 + tid];
        g_u[(b0 + bb) * TM2 + tid] = uv;
        w[bb][tid] = y[(b0 + bb) * TM2 + tid] - uv;
    }
    __syncthreads();
    float acc[8];
#pragma unroll
    for (int bb = 0; bb < 8; bb++) acc[bb] = 0.f;
    for (int k = 0; k < 128; k++) {
        float h = g_HT[k * 128 + tid];
#pragma unroll
        for (int bb = 0; bb < 8; bb++) acc[bb] = fmaf(h, w[bb][k], acc[bb]);
    }
#pragma unroll
    for (int bb = 0; bb < 8; bb++)
        g_s[(b0 + bb) * TM2 + tid] = acc[bb] - g_d[(b0 + bb) * TM2 + tid];
}

// fused: P = reduce(partials); zu update; s = H (z-u) - d for next iter
__global__ void zus(const float* __restrict__ y,
                    const float* __restrict__ log_eps, int compute_s) {
    __shared__ float red[4];
    __shared__ float w[128];
    int b = blockIdx.x;
    int j = threadIdx.x;    // 128
    float eps = expf(log_eps[0]);
    float Pv = 0.f;
#pragma unroll
    for (int ks = 0; ks < NSPLIT; ks++)
        Pv += g_part[((size_t)ks * BATCH + b) * TM2 + j];
    float uv = g_u[b * TM2 + j];
    float yv = y[b * TM2 + j];
    float v = Pv + uv - yv;
    float t = v * v;
#pragma unroll
    for (int o = 16; o > 0; o >>= 1) t += __shfl_down_sync(0xffffffffu, t, o);
    if ((j & 31) == 0) red[j >> 5] = t;
    __syncthreads();
    float nrm = sqrtf(red[0] + red[1] + red[2] + red[3]);
    float scale = fminf(1.f, eps / (nrm + 1e-12f));
    float zv = yv + v * scale;
    float un = uv + Pv - zv;
    g_u[b * TM2 + j] = un;
    if (compute_s) {
        w[j] = zv - un;
        __syncthreads();
        float acc = 0.f;
#pragma unroll 4
        for (int k = 0; k < 128; k++)
            acc = fmaf(g_HT[k * 128 + j], w[k], acc);
        g_s[b * TM2 + j] = acc - g_d[b * TM2 + j];
    }
}

__global__ void write_u(float* __restrict__ out) {
    int i = blockIdx.x * blockDim.x + threadIdx.x;
    if (i < BATCH * TM2)
        out[(size_t)BATCH * 2 * NDIM + i] = g_u[i];
}

// ---------------- launch ----------------------------------------------------
extern "C" void kernel_launch(void* const* d_in, const int* in_sizes, int n_in,
                              void* d_out, int out_size) {
    const float* rn   = (const float*)d_in[0];
    const float* y    = (const float*)d_in[1];
    const float* u_in = (const float*)d_in[2];
    const float* A    = (const float*)d_in[3];
    const float* lrho = (const float*)d_in[4];
    const float* leps = (const float*)d_in[5];
    float* out = (float*)d_out;
    (void)in_sizes; (void)n_in; (void)out_size;

    float *dX, *dM, *dR, *dPart, *dNSa, *dNSb, *dY;
    cudaGetSymbolAddress((void**)&dX,    g_X);
    cudaGetSymbolAddress((void**)&dM,    g_M);
    cudaGetSymbolAddress((void**)&dR,    g_R);
    cudaGetSymbolAddress((void**)&dPart, g_part);
    cudaGetSymbolAddress((void**)&dNSa,  g_NSa);
    cudaGetSymbolAddress((void**)&dNSb,  g_NSb);
    cudaGetSymbolAddress((void**)&dY,    g_Y);

    static int attr_set = 0;
    if (!attr_set) {
        cudaFuncSetAttribute(mma_nt, cudaFuncAttributeMaxDynamicSharedMemorySize,
                             SMEM_BYTES);
        cudaFuncSetAttribute(mma_nn, cudaFuncAttributeMaxDynamicSharedMemorySize,
                             SMEM_BYTES);
        attr_set = 1;
    }

    // bf16 splits of W (both layouts)
    conv_W<<<(TM2 * NDIM + 255) / 256, 256>>>(A);
    conv_Wt<<<dim3(NDIM / 32, TM2 / 32), dim3(32, 8)>>>(A);

    // M = W W^T via HMMA (64-way split), then S
    mma_nt<<<dim3(1, 64), 512, SMEM_BYTES>>>(A, NDIM, dPart, 128, 128);
    reduce_nt<<<(128 * 32 + 255) / 256, 256>>>((const float4*)dPart,
                                               (float4*)dM, 128 * 32, 64);
    build_S<<<64, 256>>>(lrho);

    // Newton-Schulz inverse (4 steps)
    gersh_initX1<<<1, 128>>>();
    float* cur = dNSa;
    float* nxt = dNSb;
    for (int t = 0; t < 4; t++) {
        ns_SX<<<64, 256>>>(cur, dY);
        ns_update<<<64, 256>>>(cur, dY, nxt);
        float* tmp = cur; cur = nxt; nxt = tmp;
    }
    const float* Sinv = cur;

    compute_HT<<<128, 128>>>(Sinv, lrho);

    // rn projections (2048 rows), then d = Sinv c, then s for iter 0
    mma_nt<<<dim3(16, NSPLIT), 512, SMEM_BYTES>>>(rn, NDIM, dPart, 2048, KCHUNK);
    reduce_nt<<<(2048 * 32 + 255) / 256, 256>>>((const float4*)dPart,
                                                (float4*)dR, 2048 * 32, NSPLIT);
    precompute_d<<<128, 128>>>(Sinv);
    s_init<<<128, 128>>>(y, u_in);

    for (int it = 0; it < 3; it++) {
        int fin = (it == 2);
        mma_nn<<<dim3(NDIM / 128, BATCH / 128), 512, SMEM_BYTES>>>(rn, out, fin);
        const float* xsrc = fin ? (const float*)out : (const float*)dX;
        int ldx = fin ? 2 * NDIM : NDIM;
        mma_nt<<<dim3(BATCH / 128, NSPLIT), 512, SMEM_BYTES>>>(xsrc, ldx, dPart,
                                                               BATCH, KCHUNK);
        zus<<<BATCH, 128>>>(y, leps, it < 2);
    }

    write_u<<<(BATCH * TM2 + 255) / 256, 256>>>(out);
}

// round 11
// speedup vs baseline: 8.9001x; 1.0052x over previous
#include <cuda_runtime.h>
#include <cuda_bf16.h>
#include <math.h>
#include <stdint.h>

#define BATCH 1024
#define NDIM  8192
#define TM2   128
#define NSPLIT 16
#define KCHUNK 512

// fragment-order smem tile sizes (u32)
#define A_TILE_STRIDE 136     // 128 payload + 8 pad (16x8kp tile)
#define B_TILE_STRIDE 72      // 64 payload + 8 pad (8x8kp tile)
#define A_REGION (64 * A_TILE_STRIDE)   // 8 rowtiles x 8 ktiles
#define B_REGION (128 * B_TILE_STRIDE)  // 16 ntiles x 8 ktiles
#define SMEM_U32 (2 * A_REGION + 2 * B_REGION)
#define SMEM_BYTES (SMEM_U32 * 4)       // 143360

// ---------------- scratch (static device globals; no runtime alloc) --------
__device__ float g_X[BATCH * NDIM];                        // 32 MB
__device__ float g_part[(size_t)64 * 2048 * TM2];          // split-K partials
__device__ float g_R [2048 * TM2];
__device__ float g_d [BATCH * TM2];
__device__ float g_u [BATCH * TM2];
__device__ float g_s [BATCH * TM2];
__device__ float g_M   [TM2 * TM2];
__device__ float g_G   [TM2 * TM2];
__device__ float g_S   [TM2 * TM2];
__device__ float g_NSa [TM2 * TM2];
__device__ float g_NSb [TM2 * TM2];
__device__ float g_Y   [TM2 * TM2];
__device__ float g_HT  [TM2 * TM2];
__device__ __nv_bfloat16 g_Whi [TM2 * NDIM];               // W  k-major bf16 hi
__device__ __nv_bfloat16 g_Wlo [TM2 * NDIM];               // W  k-major bf16 lo
__device__ __nv_bfloat16 g_Wthi[(size_t)NDIM * TM2];       // W^T n-major bf16 hi
__device__ __nv_bfloat16 g_Wtlo[(size_t)NDIM * TM2];       // W^T n-major bf16 lo

// ---------------- helpers ----------------------------------------------------
__device__ __forceinline__ uint32_t pack_bf16x2(float a, float b) {
    uint32_t lo = (uint32_t)__bfloat16_as_ushort(__float2bfloat16(a));
    uint32_t hi = (uint32_t)__bfloat16_as_ushort(__float2bfloat16(b));
    return lo | (hi << 16);
}

// m16n8k16 row.col bf16 -> f32 accumulate. NOT volatile: pure register op,
// lets ptxas interleave independent MMAs and overlap LDS with MMA issue.
__device__ __forceinline__ void mma16816(float* c, const uint4& a,
                                         const uint2& b) {
    asm("mma.sync.aligned.m16n8k16.row.col.f32.bf16.bf16.f32 "
        "{%0,%1,%2,%3}, {%4,%5,%6,%7}, {%8,%9}, {%0,%1,%2,%3};"
        : "+f"(c[0]), "+f"(c[1]), "+f"(c[2]), "+f"(c[3])
        : "r"(a.x), "r"(a.y), "r"(a.z), "r"(a.w), "r"(b.x), "r"(b.y));
}

// fragment-order addresses: value (row,kp) -> lane/reg slot of its mma tile
__device__ __forceinline__ uint32_t a_addr(int row, int kp) {
    uint32_t tile = (uint32_t)((row >> 4) * 8 + (kp >> 3));
    uint32_t lane = ((row & 7) << 2) + (kp & 3);
    uint32_t reg = ((row >> 3) & 1) | (((kp >> 2) & 1) << 1);
    return tile * A_TILE_STRIDE + lane * 4 + reg;
}
__device__ __forceinline__ uint32_t b_addr(int n, int kp) {
    uint32_t tile = (uint32_t)((n >> 3) * 8 + (kp >> 3));
    uint32_t lane = ((n & 7) << 2) + (kp & 3);
    uint32_t reg = (kp >> 2) & 1;
    return tile * B_TILE_STRIDE + lane * 2 + reg;
}

// ============================================================================
// mma_nt: part[split][r][j] = sum_{k in chunk} A[r,k] * W[j,k]
// 512 threads, 128x128 tile, 4x4 warp grid (32x32 warp tiles).
// ============================================================================
__global__ void __launch_bounds__(512, 1)
mma_nt(const float* __restrict__ Asrc, int lda, float* __restrict__ part,
       int rows, int kchunk) {
    extern __shared__ uint32_t sm[];
    uint32_t* sAh = sm;
    uint32_t* sAl = sm + A_REGION;
    uint32_t* sBh = sm + 2 * A_REGION;
    uint32_t* sBl = sm + 2 * A_REGION + B_REGION;
    int tid = threadIdx.x;
    int lane = tid & 31, wid = tid >> 5;
    int wr = wid >> 2, wc = wid & 3;
    int r0 = blockIdx.x * 128;
    int k0 = blockIdx.y * kchunk;
    int q = lane & 3, g = lane >> 2;

    const uint32_t* Wh = (const uint32_t*)g_Whi;
    const uint32_t* Wl = (const uint32_t*)g_Wlo;

    float acc[2][4][4];
#pragma unroll
    for (int mt = 0; mt < 2; mt++)
#pragma unroll
        for (int nt = 0; nt < 4; nt++)
#pragma unroll
            for (int e = 0; e < 4; e++) acc[mt][nt][e] = 0.f;

    for (int sc = 0; sc < kchunk; sc += 128) {
        __syncthreads();
#pragma unroll
        for (int i = 0; i < 16; i++) {
            int idx = tid + i * 512;
            int row = idx >> 6, kp = idx & 63;
            float2 v = *(const float2*)(Asrc + (size_t)(r0 + row) * lda
                                        + k0 + sc + kp * 2);
            float h0 = __bfloat162float(__float2bfloat16(v.x));
            float h1 = __bfloat162float(__float2bfloat16(v.y));
            uint32_t aa = a_addr(row, kp);
            sAh[aa] = pack_bf16x2(v.x, v.y);
            sAl[aa] = pack_bf16x2(v.x - h0, v.y - h1);
            size_t wo = (size_t)row * (NDIM / 2) + (size_t)(k0 + sc) / 2 + kp;
            uint32_t ba = b_addr(row, kp);
            sBh[ba] = Wh[wo];
            sBl[ba] = Wl[wo];
        }
        __syncthreads();

#pragma unroll
        for (int s = 0; s < 8; s++) {
            uint4 ah[2], al[2];
            uint2 bh[4], bl[4];
#pragma unroll
            for (int mt = 0; mt < 2; mt++) {
                uint32_t base = (uint32_t)(((wr * 2 + mt) * 8 + s) * A_TILE_STRIDE
                                           + lane * 4);
                ah[mt] = *(const uint4*)(sAh + base);
                al[mt] = *(const uint4*)(sAl + base);
            }
#pragma unroll
            for (int nt = 0; nt < 4; nt++) {
                uint32_t base = (uint32_t)(((wc * 4 + nt) * 8 + s) * B_TILE_STRIDE
                                           + lane * 2);
                bh[nt] = *(const uint2*)(sBh + base);
                bl[nt] = *(const uint2*)(sBl + base);
            }
            // term-major order: 8 independent MMAs between accumulator reuses
#pragma unroll
            for (int mt = 0; mt < 2; mt++)
#pragma unroll
                for (int nt = 0; nt < 4; nt++)
                    mma16816(acc[mt][nt], ah[mt], bh[nt]);
#pragma unroll
            for (int mt = 0; mt < 2; mt++)
#pragma unroll
                for (int nt = 0; nt < 4; nt++)
                    mma16816(acc[mt][nt], ah[mt], bl[nt]);
#pragma unroll
            for (int mt = 0; mt < 2; mt++)
#pragma unroll
                for (int nt = 0; nt < 4; nt++)
                    mma16816(acc[mt][nt], al[mt], bh[nt]);
        }
    }

    float* pb = part + ((size_t)blockIdx.y * rows + r0) * TM2;
#pragma unroll
    for (int mt = 0; mt < 2; mt++) {
        int row = wr * 32 + mt * 16 + g;
#pragma unroll
        for (int nt = 0; nt < 4; nt++) {
            int col = wc * 32 + nt * 8 + 2 * q;
            *(float2*)&pb[(size_t)row * TM2 + col] =
                make_float2(acc[mt][nt][0], acc[mt][nt][1]);
            *(float2*)&pb[(size_t)(row + 8) * TM2 + col] =
                make_float2(acc[mt][nt][2], acc[mt][nt][3]);
        }
    }
}

// deterministic fixed-order split-K reduction
__global__ void reduce_nt(const float4* __restrict__ part,
                          float4* __restrict__ out, int count4, int nsplit) {
    int i = blockIdx.x * 256 + threadIdx.x;
    if (i < count4) {
        float4 s = make_float4(0.f, 0.f, 0.f, 0.f);
        for (int k = 0; k < nsplit; k++) {
            float4 v = part[(size_t)k * count4 + i];
            s.x += v.x; s.y += v.y; s.z += v.z; s.w += v.w;
        }
        out[i] = s;
    }
}

// ============================================================================
// mma_nn: X[b,n] = relu(rn_r[b,n] + sum_k s[b,k] * W[k,n]); K = 128.
// grid (NDIM/128, BATCH/128), 512 threads.
// ============================================================================
__global__ void __launch_bounds__(512, 1)
mma_nn(const float* __restrict__ rn, float* __restrict__ outx, int final_out) {
    extern __shared__ uint32_t sm[];
    uint32_t* sAh = sm;
    uint32_t* sAl = sm + A_REGION;
    uint32_t* sBh = sm + 2 * A_REGION;
    uint32_t* sBl = sm + 2 * A_REGION + B_REGION;
    int tid = threadIdx.x;
    int lane = tid & 31, wid = tid >> 5;
    int wr = wid >> 2, wc = wid & 3;
    int n0 = blockIdx.x * 128;
    int r0 = blockIdx.y * 128;
    int q = lane & 3, g = lane >> 2;

    const uint32_t* Wth = (const uint32_t*)g_Wthi;
    const uint32_t* Wtl = (const uint32_t*)g_Wtlo;

#pragma unroll
    for (int i = 0; i < 16; i++) {
        int idx = tid + i * 512;
        int row = idx >> 6, kp = idx & 63;
        float2 v = *(const float2*)(g_s + (size_t)(r0 + row) * TM2 + kp * 2);
        float h0 = __bfloat162float(__float2bfloat16(v.x));
        float h1 = __bfloat162float(__float2bfloat16(v.y));
        uint32_t aa = a_addr(row, kp);
        sAh[aa] = pack_bf16x2(v.x, v.y);
        sAl[aa] = pack_bf16x2(v.x - h0, v.y - h1);
        size_t wo = (size_t)(n0 + row) * 64 + kp;
        uint32_t ba = b_addr(row, kp);
        sBh[ba] = Wth[wo];
        sBl[ba] = Wtl[wo];
    }
    __syncthreads();

    float acc[2][4][4];
#pragma unroll
    for (int mt = 0; mt < 2; mt++)
#pragma unroll
        for (int nt = 0; nt < 4; nt++)
#pragma unroll
            for (int e = 0; e < 4; e++) acc[mt][nt][e] = 0.f;

#pragma unroll
    for (int s = 0; s < 8; s++) {
        uint4 ah[2], al[2];
        uint2 bh[4], bl[4];
#pragma unroll
        for (int mt = 0; mt < 2; mt++) {
            uint32_t base = (uint32_t)(((wr * 2 + mt) * 8 + s) * A_TILE_STRIDE
                                       + lane * 4);
            ah[mt] = *(const uint4*)(sAh + base);
            al[mt] = *(const uint4*)(sAl + base);
        }
#pragma unroll
        for (int nt = 0; nt < 4; nt++) {
            uint32_t base = (uint32_t)(((wc * 4 + nt) * 8 + s) * B_TILE_STRIDE
                                       + lane * 2);
            bh[nt] = *(const uint2*)(sBh + base);
            bl[nt] = *(const uint2*)(sBl + base);
        }
#pragma unroll
        for (int mt = 0; mt < 2; mt++)
#pragma unroll
            for (int nt = 0; nt < 4; nt++)
                mma16816(acc[mt][nt], ah[mt], bh[nt]);
#pragma unroll
        for (int mt = 0; mt < 2; mt++)
#pragma unroll
            for (int nt = 0; nt < 4; nt++)
                mma16816(acc[mt][nt], ah[mt], bl[nt]);
#pragma unroll
        for (int mt = 0; mt < 2; mt++)
#pragma unroll
            for (int nt = 0; nt < 4; nt++)
                mma16816(acc[mt][nt], al[mt], bh[nt]);
    }

    float2 zero2 = make_float2(0.f, 0.f);
#pragma unroll
    for (int mt = 0; mt < 2; mt++) {
#pragma unroll
        for (int half = 0; half < 2; half++) {
            int row = wr * 32 + mt * 16 + g + half * 8;
            int r = r0 + row;
#pragma unroll
            for (int nt = 0; nt < 4; nt++) {
                int col = n0 + wc * 32 + nt * 8 + 2 * q;
                float2 rv = *(const float2*)(rn + (size_t)r * (2 * NDIM) + col);
                float c0 = acc[mt][nt][half * 2 + 0] + rv.x;
                float c1 = acc[mt][nt][half * 2 + 1] + rv.y;
                float2 o = make_float2(fmaxf(c0, 0.f), fmaxf(c1, 0.f));
                if (final_out) {
                    size_t base = (size_t)r * (2 * NDIM);
                    *(float2*)(outx + base + col) = o;
                    *(float2*)(outx + base + NDIM + col) = zero2;
                } else {
                    *(float2*)(g_X + (size_t)r * NDIM + col) = o;
                }
            }
        }
    }
}

// ---------------- W bf16 precompute -----------------------------------------
__global__ void conv_W(const float* __restrict__ W) {
    int i = blockIdx.x * 256 + threadIdx.x;
    if (i < TM2 * NDIM) {
        float v = W[i];
        __nv_bfloat16 h = __float2bfloat16(v);
        g_Whi[i] = h;
        g_Wlo[i] = __float2bfloat16(v - __bfloat162float(h));
    }
}
__global__ void conv_Wt(const float* __restrict__ W) {
    __shared__ float t[32][33];
    int bx = blockIdx.x * 32;   // n tile
    int by = blockIdx.y * 32;   // k tile
    for (int yy = threadIdx.y; yy < 32; yy += 8)
        t[yy][threadIdx.x] = W[(size_t)(by + yy) * NDIM + bx + threadIdx.x];
    __syncthreads();
    for (int ny = threadIdx.y; ny < 32; ny += 8) {
        float v = t[threadIdx.x][ny];
        __nv_bfloat16 h = __float2bfloat16(v);
        size_t o = (size_t)(bx + ny) * TM2 + by + threadIdx.x;
        g_Wthi[o] = h;
        g_Wtlo[o] = __float2bfloat16(v - __bfloat162float(h));
    }
}

// ---------------- build G and S = G + I/rho ---------------------------------
__global__ void build_S(const float* __restrict__ log_rho) {
    int idx = blockIdx.x * blockDim.x + threadIdx.x;
    float inv_rho = 1.f / (expf(log_rho[0]) + 1e-12f);
    int p = idx >> 7, q = idx & 127;
    float sgn = ((p < 64) == (q < 64)) ? 1.f : -1.f;
    float g = g_M[idx] + sgn * g_M[((p ^ 64) << 7) + (q ^ 64)];
    g_G[idx] = g;
    g_S[idx] = g + ((p == q) ? inv_rho : 0.f);
}

// ---------------- Newton-Schulz inverse -------------------------------------
__global__ void gersh_initX1() {
    __shared__ float smax[4], smin[4], s_x0;
    int i = threadIdx.x;    // 128
    float rs = 0.f, dg = 0.f;
#pragma unroll 8
    for (int k = 0; k < 128; k++) {
        float v = g_S[i * 128 + k];
        rs += fabsf(v);
        if (k == i) dg = v;
    }
    float lo = 2.f * dg - rs;
    float mx = rs, mn = lo;
#pragma unroll
    for (int o = 16; o > 0; o >>= 1) {
        mx = fmaxf(mx, __shfl_down_sync(0xffffffffu, mx, o));
        mn = fminf(mn, __shfl_down_sync(0xffffffffu, mn, o));
    }
    if ((i & 31) == 0) { smax[i >> 5] = mx; smin[i >> 5] = mn; }
    __syncthreads();
    if (i == 0) {
        float lmax = fmaxf(fmaxf(smax[0], smax[1]), fmaxf(smax[2], smax[3]));
        float lmin = fminf(fminf(smin[0], smin[1]), fminf(smin[2], smin[3]));
        s_x0 = (lmin > 0.f) ? 2.f / (lmax + lmin) : 1.f / lmax;
    }
    __syncthreads();
    float x0 = s_x0;
    for (int e = i; e < 128 * 128; e += 128) {
        int p = e >> 7, q = e & 127;
        g_NSa[e] = 2.f * x0 * ((p == q) ? 1.f : 0.f) - x0 * x0 * g_S[e];
    }
}

__global__ void __launch_bounds__(256)
ns_SX(const float* __restrict__ X, float* __restrict__ Y) {
    __shared__ float As[2][128];
    int tid = threadIdx.x;
    int r0 = blockIdx.x * 2;
    int rr = tid >> 7, j = tid & 127;
    As[rr][j] = g_S[(r0 + rr) * 128 + j];
    __syncthreads();
    float acc = 0.f;
#pragma unroll 8
    for (int k = 0; k < 128; k++)
        acc = fmaf(As[rr][k], X[k * 128 + j], acc);
    Y[(r0 + rr) * 128 + j] = acc;
}
__global__ void __launch_bounds__(256)
ns_update(const float* __restrict__ X, const float* __restrict__ Y,
          float* __restrict__ Xn) {
    __shared__ float As[2][128];
    int tid = threadIdx.x;
    int r0 = blockIdx.x * 2;
    int rr = tid >> 7, j = tid & 127;
    As[rr][j] = X[(r0 + rr) * 128 + j];
    __syncthreads();
    float acc = 0.f;
#pragma unroll 8
    for (int k = 0; k < 128; k++)
        acc = fmaf(As[rr][k], Y[k * 128 + j], acc);
    Xn[(r0 + rr) * 128 + j] = 2.f * As[rr][j] - acc;
}

__global__ void compute_HT(const float* __restrict__ Sinv,
                           const float* __restrict__ log_rho) {
    __shared__ float gk[128];
    int j = threadIdx.x, k = blockIdx.x;
    float rho = expf(log_rho[0]);
    gk[j] = g_G[k * 128 + j];
    __syncthreads();
    float acc = 0.f;
#pragma unroll 4
    for (int m = 0; m < 128; m++)
        acc = fmaf(Sinv[m * 128 + j], gk[m], acc);
    g_HT[k * 128 + j] = rho * (((j == k) ? 1.f : 0.f) - acc);
}

// d = Sinv @ c, c assembled from rn projections g_R (row 2b real, 2b+1 imag)
__global__ void precompute_d(const float* __restrict__ Sinv) {
    __shared__ float cb[8][128];
    int tid = threadIdx.x;
    int b0 = blockIdx.x * 8;
#pragma unroll
    for (int bb = 0; bb < 8; bb++) {
        int b = b0 + bb, j = tid;
        float pa = g_R[(size_t)(2 * b) * TM2 + j];
        float pb = g_R[(size_t)(2 * b + 1) * TM2 + (j ^ 64)];
        cb[bb][j] = (j < 64) ? pa - pb : pa + pb;
    }
    __syncthreads();
    float acc[8];
#pragma unroll
    for (int bb = 0; bb < 8; bb++) acc[bb] = 0.f;
    for (int k = 0; k < 128; k++) {
        float sv = Sinv[k * 128 + tid];
#pragma unroll
        for (int bb = 0; bb < 8; bb++) acc[bb] = fmaf(sv, cb[bb][k], acc[bb]);
    }
#pragma unroll
    for (int bb = 0; bb < 8; bb++)
        g_d[(b0 + bb) * TM2 + tid] = acc[bb];
}

// s for iteration 0: w = y - u_in; s = H w - d; also init g_u = u_in
__global__ void s_init(const float* __restrict__ y,
                       const float* __restrict__ u_in) {
    __shared__ float w[8][128];
    int tid = threadIdx.x;
    int b0 = blockIdx.x * 8;
#pragma unroll
    for (int bb = 0; bb < 8; bb++) {
        float uv = u_in[(b0 + bb) * TM2 + tid];
        g_u[(b0 + bb) * TM2 + tid] = uv;
        w[bb][tid] = y[(b0 + bb) * TM2 + tid] - uv;
    }
    __syncthreads();
    float acc[8];
#pragma unroll
    for (int bb = 0; bb < 8; bb++) acc[bb] = 0.f;
    for (int k = 0; k < 128; k++) {
        float h = g_HT[k * 128 + tid];
#pragma unroll
        for (int bb = 0; bb < 8; bb++) acc[bb] = fmaf(h, w[bb][k], acc[bb]);
    }
#pragma unroll
    for (int bb = 0; bb < 8; bb++)
        g_s[(b0 + bb) * TM2 + tid] = acc[bb] - g_d[(b0 + bb) * TM2 + tid];
}

// fused: P = reduce(partials); zu update; s = H (z-u) - d; final u -> out
__global__ void zus(const float* __restrict__ y,
                    const float* __restrict__ log_eps, int compute_s,
                    float* __restrict__ uout) {
    __shared__ float red[4];
    __shared__ float w[128];
    int b = blockIdx.x;
    int j = threadIdx.x;    // 128
    float eps = expf(log_eps[0]);
    float Pv = 0.f;
#pragma unroll
    for (int ks = 0; ks < NSPLIT; ks++)
        Pv += g_part[((size_t)ks * BATCH + b) * TM2 + j];
    float uv = g_u[b * TM2 + j];
    float yv = y[b * TM2 + j];
    float v = Pv + uv - yv;
    float t = v * v;
#pragma unroll
    for (int o = 16; o > 0; o >>= 1) t += __shfl_down_sync(0xffffffffu, t, o);
    if ((j & 31) == 0) red[j >> 5] = t;
    __syncthreads();
    float nrm = sqrtf(red[0] + red[1] + red[2] + red[3]);
    float scale = fminf(1.f, eps / (nrm + 1e-12f));
    float zv = yv + v * scale;
    float un = uv + Pv - zv;
    if (compute_s) {
        g_u[b * TM2 + j] = un;
        w[j] = zv - un;
        __syncthreads();
        float acc = 0.f;
#pragma unroll 4
        for (int k = 0; k < 128; k++)
            acc = fmaf(g_HT[k * 128 + j], w[k], acc);
        g_s[b * TM2 + j] = acc - g_d[b * TM2 + j];
    } else {
        uout[(size_t)BATCH * 2 * NDIM + b * TM2 + j] = un;
    }
}

// ---------------- launch ----------------------------------------------------
extern "C" void kernel_launch(void* const* d_in, const int* in_sizes, int n_in,
                              void* d_out, int out_size) {
    const float* rn   = (const float*)d_in[0];
    const float* y    = (const float*)d_in[1];
    const float* u_in = (const float*)d_in[2];
    const float* A    = (const float*)d_in[3];
    const float* lrho = (const float*)d_in[4];
    const float* leps = (const float*)d_in[5];
    float* out = (float*)d_out;
    (void)in_sizes; (void)n_in; (void)out_size;

    float *dX, *dM, *dR, *dPart, *dNSa, *dNSb, *dY;
    cudaGetSymbolAddress((void**)&dX,    g_X);
    cudaGetSymbolAddress((void**)&dM,    g_M);
    cudaGetSymbolAddress((void**)&dR,    g_R);
    cudaGetSymbolAddress((void**)&dPart, g_part);
    cudaGetSymbolAddress((void**)&dNSa,  g_NSa);
    cudaGetSymbolAddress((void**)&dNSb,  g_NSb);
    cudaGetSymbolAddress((void**)&dY,    g_Y);

    static int attr_set = 0;
    if (!attr_set) {
        cudaFuncSetAttribute(mma_nt, cudaFuncAttributeMaxDynamicSharedMemorySize,
                             SMEM_BYTES);
        cudaFuncSetAttribute(mma_nn, cudaFuncAttributeMaxDynamicSharedMemorySize,
                             SMEM_BYTES);
        attr_set = 1;
    }

    // bf16 splits of W (both layouts)
    conv_W<<<(TM2 * NDIM + 255) / 256, 256>>>(A);
    conv_Wt<<<dim3(NDIM / 32, TM2 / 32), dim3(32, 8)>>>(A);

    // M = W W^T via HMMA (64-way split), then S
    mma_nt<<<dim3(1, 64), 512, SMEM_BYTES>>>(A, NDIM, dPart, 128, 128);
    reduce_nt<<<(128 * 32 + 255) / 256, 256>>>((const float4*)dPart,
                                               (float4*)dM, 128 * 32, 64);
    build_S<<<64, 256>>>(lrho);

    // Newton-Schulz inverse (4 steps)
    gersh_initX1<<<1, 128>>>();
    float* cur = dNSa;
    float* nxt = dNSb;
    for (int t = 0; t < 4; t++) {
        ns_SX<<<64, 256>>>(cur, dY);
        ns_update<<<64, 256>>>(cur, dY, nxt);
        float* tmp = cur; cur = nxt; nxt = tmp;
    }
    const float* Sinv = cur;

    compute_HT<<<128, 128>>>(Sinv, lrho);

    // rn projections (2048 rows), then d = Sinv c, then s for iter 0
    mma_nt<<<dim3(16, NSPLIT), 512, SMEM_BYTES>>>(rn, NDIM, dPart, 2048, KCHUNK);
    reduce_nt<<<(2048 * 32 + 255) / 256, 256>>>((const float4*)dPart,
                                                (float4*)dR, 2048 * 32, NSPLIT);
    precompute_d<<<128, 128>>>(Sinv);
    s_init<<<128, 128>>>(y, u_in);

    for (int it = 0; it < 3; it++) {
        int fin = (it == 2);
        mma_nn<<<dim3(NDIM / 128, BATCH / 128), 512, SMEM_BYTES>>>(rn, out, fin);
        const float* xsrc = fin ? (const float*)out : (const float*)dX;
        int ldx = fin ? 2 * NDIM : NDIM;
        mma_nt<<<dim3(BATCH / 128, NSPLIT), 512, SMEM_BYTES>>>(xsrc, ldx, dPart,
                                                               BATCH, KCHUNK);
        zus<<<BATCH, 128>>>(y, leps, it < 2, out);
    }
}

// round 12
// speedup vs baseline: 9.6248x; 1.0814x over previous
#include <cuda_runtime.h>
#include <cuda_bf16.h>
#include <math.h>
#include <stdint.h>

#define BATCH 1024
#define NDIM  8192
#define TM2   128
#define NSPLIT 16
#define KCHUNK 512

// ---------------- old (setup) kernel smem layout: padded fragment tiles ----
#define A_TILE_STRIDE 136
#define B_TILE_STRIDE 72
#define A_REGION (64 * A_TILE_STRIDE)
#define B_REGION (128 * B_TILE_STRIDE)
#define OLD_SMEM_BYTES ((2 * A_REGION + 2 * B_REGION) * 4)   // 143360

// ---------------- new (loop) kernel smem: packed frag tiles, 128x64 --------
// A: 128 rows x 64 kp = 64 tiles x 128 u32 = 8192 u32 (32KB) per hi/lo
// B: 64 n x 64 kp = 32 tiles x 128 u32... (8 ntiles x 8 ktiles x 64 u32) = 4096 u32
#define NEW_SMEM_U32 (2 * 8192 + 2 * 4096)
#define NEW_SMEM_BYTES (NEW_SMEM_U32 * 4)                    // 98304

// ---------------- scratch (static device globals; no runtime alloc) --------
__device__ float g_part[(size_t)64 * 2048 * TM2];
__device__ float g_R [2048 * TM2];
__device__ float g_d [BATCH * TM2];
__device__ float g_u [BATCH * TM2];
__device__ float g_M   [TM2 * TM2];
__device__ float g_G   [TM2 * TM2];
__device__ float g_S   [TM2 * TM2];
__device__ float g_NSa [TM2 * TM2];
__device__ float g_NSb [TM2 * TM2];
__device__ float g_HT  [TM2 * TM2];
__device__ __nv_bfloat16 g_Whi [TM2 * NDIM];   // W k-major bf16 hi (setup kernels)
__device__ __nv_bfloat16 g_Wlo [TM2 * NDIM];
// fragment-order operand stores for the loop kernels (u32 = bf16x2)
__device__ uint32_t g_sfh[8 * 8192];                 // s frags [rtile][8192]
__device__ uint32_t g_sfl[8 * 8192];
__device__ uint32_t g_Xfh[(size_t)8 * 64 * 8192];    // X frags [rtile][ksub][8192]
__device__ uint32_t g_Xfl[(size_t)8 * 64 * 8192];
__device__ uint32_t g_Wnfh[128 * 4096];              // nn B frags [nblk][4096]
__device__ uint32_t g_Wnfl[128 * 4096];
__device__ uint32_t g_Wtfh[64 * 2 * 4096];           // nt B frags [ksub][jblk][4096]
__device__ uint32_t g_Wtfl[64 * 2 * 4096];

// ---------------- helpers ----------------------------------------------------
__device__ __forceinline__ uint32_t pack_bf16x2(float a, float b) {
    uint32_t lo = (uint32_t)__bfloat16_as_ushort(__float2bfloat16(a));
    uint32_t hi = (uint32_t)__bfloat16_as_ushort(__float2bfloat16(b));
    return lo | (hi << 16);
}
__device__ __forceinline__ void mma16816(float* c, const uint4& a,
                                         const uint2& b) {
    asm("mma.sync.aligned.m16n8k16.row.col.f32.bf16.bf16.f32 "
        "{%0,%1,%2,%3}, {%4,%5,%6,%7}, {%8,%9}, {%0,%1,%2,%3};"
        : "+f"(c[0]), "+f"(c[1]), "+f"(c[2]), "+f"(c[3])
        : "r"(a.x), "r"(a.y), "r"(a.z), "r"(a.w), "r"(b.x), "r"(b.y));
}
// padded fragment addressing (old setup kernels only)
__device__ __forceinline__ uint32_t a_addr_p(int row, int kp) {
    uint32_t tile = (uint32_t)((row >> 4) * 8 + (kp >> 3));
    uint32_t lane = ((row & 7) << 2) + (kp & 3);
    uint32_t reg = ((row >> 3) & 1) | (((kp >> 2) & 1) << 1);
    return tile * A_TILE_STRIDE + lane * 4 + reg;
}
__device__ __forceinline__ uint32_t b_addr_p(int n, int kp) {
    uint32_t tile = (uint32_t)((n >> 3) * 8 + (kp >> 3));
    uint32_t lane = ((n & 7) << 2) + (kp & 3);
    uint32_t reg = (kp >> 2) & 1;
    return tile * B_TILE_STRIDE + lane * 2 + reg;
}
// packed fragment addressing (frag-order global arrays / new kernels)
__device__ __forceinline__ uint32_t a_addr(int row, int kp) {
    uint32_t tile = (uint32_t)((row >> 4) * 8 + (kp >> 3));
    uint32_t lane = ((row & 7) << 2) + (kp & 3);
    uint32_t reg = ((row >> 3) & 1) | (((kp >> 2) & 1) << 1);
    return tile * 128 + lane * 4 + reg;
}
__device__ __forceinline__ uint32_t b_addr(int n, int kp) {
    uint32_t tile = (uint32_t)((n >> 3) * 8 + (kp >> 3));
    uint32_t lane = ((n & 7) << 2) + (kp & 3);
    uint32_t reg = (kp >> 2) & 1;
    return tile * 64 + lane * 2 + reg;
}

// ============================================================================
// OLD mma_nt (512 thr, 128x128, convert-fill) — setup only (WWT, rn proj)
// ============================================================================
__global__ void __launch_bounds__(512, 1)
mma_nt(const float* __restrict__ Asrc, int lda, float* __restrict__ part,
       int rows, int kchunk) {
    extern __shared__ uint32_t sm[];
    uint32_t* sAh = sm;
    uint32_t* sAl = sm + A_REGION;
    uint32_t* sBh = sm + 2 * A_REGION;
    uint32_t* sBl = sm + 2 * A_REGION + B_REGION;
    int tid = threadIdx.x;
    int lane = tid & 31, wid = tid >> 5;
    int wr = wid >> 2, wc = wid & 3;
    int r0 = blockIdx.x * 128;
    int k0 = blockIdx.y * kchunk;
    int q = lane & 3, g = lane >> 2;
    const uint32_t* Wh = (const uint32_t*)g_Whi;
    const uint32_t* Wl = (const uint32_t*)g_Wlo;

    float acc[2][4][4];
#pragma unroll
    for (int mt = 0; mt < 2; mt++)
#pragma unroll
        for (int nt = 0; nt < 4; nt++)
#pragma unroll
            for (int e = 0; e < 4; e++) acc[mt][nt][e] = 0.f;

    for (int sc = 0; sc < kchunk; sc += 128) {
        __syncthreads();
#pragma unroll
        for (int i = 0; i < 16; i++) {
            int idx = tid + i * 512;
            int row = idx >> 6, kp = idx & 63;
            float2 v = *(const float2*)(Asrc + (size_t)(r0 + row) * lda
                                        + k0 + sc + kp * 2);
            float h0 = __bfloat162float(__float2bfloat16(v.x));
            float h1 = __bfloat162float(__float2bfloat16(v.y));
            uint32_t aa = a_addr_p(row, kp);
            sAh[aa] = pack_bf16x2(v.x, v.y);
            sAl[aa] = pack_bf16x2(v.x - h0, v.y - h1);
            size_t wo = (size_t)row * (NDIM / 2) + (size_t)(k0 + sc) / 2 + kp;
            uint32_t ba = b_addr_p(row, kp);
            sBh[ba] = Wh[wo];
            sBl[ba] = Wl[wo];
        }
        __syncthreads();
#pragma unroll
        for (int s = 0; s < 8; s++) {
            uint4 ah[2], al[2];
            uint2 bh[4], bl[4];
#pragma unroll
            for (int mt = 0; mt < 2; mt++) {
                uint32_t base = (uint32_t)(((wr * 2 + mt) * 8 + s) * A_TILE_STRIDE
                                           + lane * 4);
                ah[mt] = *(const uint4*)(sAh + base);
                al[mt] = *(const uint4*)(sAl + base);
            }
#pragma unroll
            for (int nt = 0; nt < 4; nt++) {
                uint32_t base = (uint32_t)(((wc * 4 + nt) * 8 + s) * B_TILE_STRIDE
                                           + lane * 2);
                bh[nt] = *(const uint2*)(sBh + base);
                bl[nt] = *(const uint2*)(sBl + base);
            }
#pragma unroll
            for (int mt = 0; mt < 2; mt++)
#pragma unroll
                for (int nt = 0; nt < 4; nt++)
                    mma16816(acc[mt][nt], ah[mt], bh[nt]);
#pragma unroll
            for (int mt = 0; mt < 2; mt++)
#pragma unroll
                for (int nt = 0; nt < 4; nt++)
                    mma16816(acc[mt][nt], ah[mt], bl[nt]);
#pragma unroll
            for (int mt = 0; mt < 2; mt++)
#pragma unroll
                for (int nt = 0; nt < 4; nt++)
                    mma16816(acc[mt][nt], al[mt], bh[nt]);
        }
    }
    float* pb = part + ((size_t)blockIdx.y * rows + r0) * TM2;
#pragma unroll
    for (int mt = 0; mt < 2; mt++) {
        int row = wr * 32 + mt * 16 + g;
#pragma unroll
        for (int nt = 0; nt < 4; nt++) {
            int col = wc * 32 + nt * 8 + 2 * q;
            *(float2*)&pb[(size_t)row * TM2 + col] =
                make_float2(acc[mt][nt][0], acc[mt][nt][1]);
            *(float2*)&pb[(size_t)(row + 8) * TM2 + col] =
                make_float2(acc[mt][nt][2], acc[mt][nt][3]);
        }
    }
}

__global__ void reduce_nt(const float4* __restrict__ part,
                          float4* __restrict__ out, int count4, int nsplit) {
    int i = blockIdx.x * 256 + threadIdx.x;
    if (i < count4) {
        float4 s = make_float4(0.f, 0.f, 0.f, 0.f);
        for (int k = 0; k < nsplit; k++) {
            float4 v = part[(size_t)k * count4 + i];
            s.x += v.x; s.y += v.y; s.z += v.z; s.w += v.w;
        }
        out[i] = s;
    }
}

// ============================================================================
// NEW loop kernels: 256 threads, 128x64 tiles, copy-only fills, 2 blocks/SM
// warp grid: wr = wid>>1 (4 row groups of 32), wc = wid&1 (2 col groups of 32)
// ============================================================================
__global__ void __launch_bounds__(256, 2)
mma_nn2(const float* __restrict__ rn, float* __restrict__ outx, int final_out) {
    extern __shared__ uint32_t sm[];
    uint32_t* sAh = sm;
    uint32_t* sAl = sm + 8192;
    uint32_t* sBh = sm + 16384;
    uint32_t* sBl = sm + 20480;
    int tid = threadIdx.x;
    int lane = tid & 31, wid = tid >> 5;
    int wr = wid >> 1, wc = wid & 1;
    int nblk = blockIdx.x;           // 0..127, n0 = nblk*64
    int rtile = blockIdx.y;          // 0..7
    int n0 = nblk * 64;
    int r0 = rtile * 128;
    int q = lane & 3, g = lane >> 2;

    {
        const uint4* gAh = (const uint4*)g_sfh + (size_t)rtile * 2048;
        const uint4* gAl = (const uint4*)g_sfl + (size_t)rtile * 2048;
        const uint4* gBh = (const uint4*)g_Wnfh + (size_t)nblk * 1024;
        const uint4* gBl = (const uint4*)g_Wnfl + (size_t)nblk * 1024;
#pragma unroll
        for (int i = 0; i < 8; i++) {
            ((uint4*)sAh)[tid + i * 256] = gAh[tid + i * 256];
            ((uint4*)sAl)[tid + i * 256] = gAl[tid + i * 256];
        }
#pragma unroll
        for (int i = 0; i < 4; i++) {
            ((uint4*)sBh)[tid + i * 256] = gBh[tid + i * 256];
            ((uint4*)sBl)[tid + i * 256] = gBl[tid + i * 256];
        }
    }
    __syncthreads();

    float acc[2][4][4];
#pragma unroll
    for (int mt = 0; mt < 2; mt++)
#pragma unroll
        for (int nt = 0; nt < 4; nt++)
#pragma unroll
            for (int e = 0; e < 4; e++) acc[mt][nt][e] = 0.f;

#pragma unroll
    for (int s = 0; s < 8; s++) {
        uint4 ah[2], al[2];
        uint2 bh[4], bl[4];
#pragma unroll
        for (int mt = 0; mt < 2; mt++) {
            uint32_t i4 = (uint32_t)(((wr * 2 + mt) * 8 + s) * 32 + lane);
            ah[mt] = ((const uint4*)sAh)[i4];
            al[mt] = ((const uint4*)sAl)[i4];
        }
#pragma unroll
        for (int nt = 0; nt < 4; nt++) {
            uint32_t i2 = (uint32_t)(((wc * 4 + nt) * 8 + s) * 32 + lane);
            bh[nt] = ((const uint2*)sBh)[i2];
            bl[nt] = ((const uint2*)sBl)[i2];
        }
#pragma unroll
        for (int mt = 0; mt < 2; mt++)
#pragma unroll
            for (int nt = 0; nt < 4; nt++)
                mma16816(acc[mt][nt], ah[mt], bh[nt]);
#pragma unroll
        for (int mt = 0; mt < 2; mt++)
#pragma unroll
            for (int nt = 0; nt < 4; nt++)
                mma16816(acc[mt][nt], ah[mt], bl[nt]);
#pragma unroll
        for (int mt = 0; mt < 2; mt++)
#pragma unroll
            for (int nt = 0; nt < 4; nt++)
                mma16816(acc[mt][nt], al[mt], bh[nt]);
    }

    // epilogue: relu(acc + rn_r) -> X frags (+ final fp32 out)
    int ksub = nblk >> 1;
    uint32_t* gxh = g_Xfh + ((size_t)rtile * 64 + ksub) * 8192;
    uint32_t* gxl = g_Xfl + ((size_t)rtile * 64 + ksub) * 8192;
    float2 zero2 = make_float2(0.f, 0.f);
#pragma unroll
    for (int mt = 0; mt < 2; mt++) {
        int rowbase = wr * 32 + mt * 16 + g;
#pragma unroll
        for (int nt = 0; nt < 4; nt++) {
            int col = wc * 32 + nt * 8 + 2 * q;     // local in 64
            int kp = ((nblk & 1) << 5) + (col >> 1); // kp within 128-ksub
#pragma unroll
            for (int half = 0; half < 2; half++) {
                int row = rowbase + half * 8;
                int r = r0 + row;
                int n = n0 + col;
                float2 rv = *(const float2*)(rn + (size_t)r * (2 * NDIM) + n);
                float c0 = fmaxf(acc[mt][nt][half * 2 + 0] + rv.x, 0.f);
                float c1 = fmaxf(acc[mt][nt][half * 2 + 1] + rv.y, 0.f);
                float h0 = __bfloat162float(__float2bfloat16(c0));
                float h1 = __bfloat162float(__float2bfloat16(c1));
                uint32_t ad = a_addr(row, kp);
                gxh[ad] = pack_bf16x2(c0, c1);
                gxl[ad] = pack_bf16x2(c0 - h0, c1 - h1);
                if (final_out) {
                    size_t base = (size_t)r * (2 * NDIM);
                    *(float2*)(outx + base + n) = make_float2(c0, c1);
                    *(float2*)(outx + base + NDIM + n) = zero2;
                }
            }
        }
    }
}

// nt2: part[split][r][j] over 128 rows x 64 j, K chunk 512 (4 subchunks)
__global__ void __launch_bounds__(256, 2)
mma_nt2(float* __restrict__ part) {
    extern __shared__ uint32_t sm[];
    uint32_t* sAh = sm;
    uint32_t* sAl = sm + 8192;
    uint32_t* sBh = sm + 16384;
    uint32_t* sBl = sm + 20480;
    int tid = threadIdx.x;
    int lane = tid & 31, wid = tid >> 5;
    int wr = wid >> 1, wc = wid & 1;
    int rtile = blockIdx.x;          // 0..7
    int split = blockIdx.y;          // 0..15
    int jblk  = blockIdx.z;          // 0..1
    int r0 = rtile * 128;
    int q = lane & 3, g = lane >> 2;

    float acc[2][4][4];
#pragma unroll
    for (int mt = 0; mt < 2; mt++)
#pragma unroll
        for (int nt = 0; nt < 4; nt++)
#pragma unroll
            for (int e = 0; e < 4; e++) acc[mt][nt][e] = 0.f;

    for (int sc = 0; sc < 4; sc++) {
        int ksub = split * 4 + sc;
        __syncthreads();
        {
            const uint4* gAh = (const uint4*)g_Xfh
                               + ((size_t)rtile * 64 + ksub) * 2048;
            const uint4* gAl = (const uint4*)g_Xfl
                               + ((size_t)rtile * 64 + ksub) * 2048;
            const uint4* gBh = (const uint4*)g_Wtfh
                               + ((size_t)ksub * 2 + jblk) * 1024;
            const uint4* gBl = (const uint4*)g_Wtfl
                               + ((size_t)ksub * 2 + jblk) * 1024;
#pragma unroll
            for (int i = 0; i < 8; i++) {
                ((uint4*)sAh)[tid + i * 256] = gAh[tid + i * 256];
                ((uint4*)sAl)[tid + i * 256] = gAl[tid + i * 256];
            }
#pragma unroll
            for (int i = 0; i < 4; i++) {
                ((uint4*)sBh)[tid + i * 256] = gBh[tid + i * 256];
                ((uint4*)sBl)[tid + i * 256] = gBl[tid + i * 256];
            }
        }
        __syncthreads();

#pragma unroll
        for (int s = 0; s < 8; s++) {
            uint4 ah[2], al[2];
            uint2 bh[4], bl[4];
#pragma unroll
            for (int mt = 0; mt < 2; mt++) {
                uint32_t i4 = (uint32_t)(((wr * 2 + mt) * 8 + s) * 32 + lane);
                ah[mt] = ((const uint4*)sAh)[i4];
                al[mt] = ((const uint4*)sAl)[i4];
            }
#pragma unroll
            for (int nt = 0; nt < 4; nt++) {
                uint32_t i2 = (uint32_t)(((wc * 4 + nt) * 8 + s) * 32 + lane);
                bh[nt] = ((const uint2*)sBh)[i2];
                bl[nt] = ((const uint2*)sBl)[i2];
            }
#pragma unroll
            for (int mt = 0; mt < 2; mt++)
#pragma unroll
                for (int nt = 0; nt < 4; nt++)
                    mma16816(acc[mt][nt], ah[mt], bh[nt]);
#pragma unroll
            for (int mt = 0; mt < 2; mt++)
#pragma unroll
                for (int nt = 0; nt < 4; nt++)
                    mma16816(acc[mt][nt], ah[mt], bl[nt]);
#pragma unroll
            for (int mt = 0; mt < 2; mt++)
#pragma unroll
                for (int nt = 0; nt < 4; nt++)
                    mma16816(acc[mt][nt], al[mt], bh[nt]);
        }
    }

    float* pb = part + ((size_t)split * BATCH + r0) * TM2;
#pragma unroll
    for (int mt = 0; mt < 2; mt++) {
        int row = wr * 32 + mt * 16 + g;
#pragma unroll
        for (int nt = 0; nt < 4; nt++) {
            int col = jblk * 64 + wc * 32 + nt * 8 + 2 * q;
            *(float2*)&pb[(size_t)row * TM2 + col] =
                make_float2(acc[mt][nt][0], acc[mt][nt][1]);
            *(float2*)&pb[(size_t)(row + 8) * TM2 + col] =
                make_float2(acc[mt][nt][2], acc[mt][nt][3]);
        }
    }
}

// ---------------- W precomputes ---------------------------------------------
__global__ void conv_W(const float* __restrict__ W) {
    int i = blockIdx.x * 256 + threadIdx.x;
    if (i < TM2 * NDIM) {
        float v = W[i];
        __nv_bfloat16 h = __float2bfloat16(v);
        g_Whi[i] = h;
        g_Wlo[i] = __float2bfloat16(v - __bfloat162float(h));
    }
}
// nn B frags: B(n, k) = W[k, n];  idx over 8192 n x 64 kp
__global__ void wf_nn(const float* __restrict__ W) {
    int idx = blockIdx.x * 256 + threadIdx.x;
    if (idx < 8192 * 64) {
        int n = idx >> 6, kp = idx & 63;
        float v0 = W[(size_t)(2 * kp) * NDIM + n];
        float v1 = W[(size_t)(2 * kp + 1) * NDIM + n];
        float h0 = __bfloat162float(__float2bfloat16(v0));
        float h1 = __bfloat162float(__float2bfloat16(v1));
        int nblk = n >> 6, nl = n & 63;
        uint32_t ad = (uint32_t)nblk * 4096 + b_addr(nl, kp);
        g_Wnfh[ad] = pack_bf16x2(v0, v1);
        g_Wnfl[ad] = pack_bf16x2(v0 - h0, v1 - h1);
    }
}
// nt B frags: B(j, k) = W[j, k];  idx over 128 j x 4096 k2
__global__ void wf_nt(const float* __restrict__ W) {
    int idx = blockIdx.x * 256 + threadIdx.x;
    if (idx < 128 * 4096) {
        int j = idx >> 12, k2 = idx & 4095;
        float v0 = W[(size_t)j * NDIM + 2 * k2];
        float v1 = W[(size_t)j * NDIM + 2 * k2 + 1];
        float h0 = __bfloat162float(__float2bfloat16(v0));
        float h1 = __bfloat162float(__float2bfloat16(v1));
        int ksub = k2 >> 6, kpl = k2 & 63;
        int jblk = j >> 6, jl = j & 63;
        uint32_t ad = (uint32_t)(ksub * 2 + jblk) * 4096 + b_addr(jl, kpl);
        g_Wtfh[ad] = pack_bf16x2(v0, v1);
        g_Wtfl[ad] = pack_bf16x2(v0 - h0, v1 - h1);
    }
}

// ---------------- build G and S = G + I/rho ---------------------------------
__global__ void build_S(const float* __restrict__ log_rho) {
    int idx = blockIdx.x * blockDim.x + threadIdx.x;
    float inv_rho = 1.f / (expf(log_rho[0]) + 1e-12f);
    int p = idx >> 7, q = idx & 127;
    float sgn = ((p < 64) == (q < 64)) ? 1.f : -1.f;
    float g = g_M[idx] + sgn * g_M[((p ^ 64) << 7) + (q ^ 64)];
    g_G[idx] = g;
    g_S[idx] = g + ((p == q) ? inv_rho : 0.f);
}

// ---------------- Newton-Schulz inverse -------------------------------------
__global__ void gersh_initX1() {
    __shared__ float smax[4], smin[4], s_x0;
    int i = threadIdx.x;    // 128
    float rs = 0.f, dg = 0.f;
#pragma unroll 8
    for (int k = 0; k < 128; k++) {
        float v = g_S[i * 128 + k];
        rs += fabsf(v);
        if (k == i) dg = v;
    }
    float lo = 2.f * dg - rs;
    float mx = rs, mn = lo;
#pragma unroll
    for (int o = 16; o > 0; o >>= 1) {
        mx = fmaxf(mx, __shfl_down_sync(0xffffffffu, mx, o));
        mn = fminf(mn, __shfl_down_sync(0xffffffffu, mn, o));
    }
    if ((i & 31) == 0) { smax[i >> 5] = mx; smin[i >> 5] = mn; }
    __syncthreads();
    if (i == 0) {
        float lmax = fmaxf(fmaxf(smax[0], smax[1]), fmaxf(smax[2], smax[3]));
        float lmin = fminf(fminf(smin[0], smin[1]), fminf(smin[2], smin[3]));
        s_x0 = (lmin > 0.f) ? 2.f / (lmax + lmin) : 1.f / lmax;
    }
    __syncthreads();
    float x0 = s_x0;
    for (int e = i; e < 128 * 128; e += 128) {
        int p = e >> 7, q = e & 127;
        g_NSa[e] = 2.f * x0 * ((p == q) ? 1.f : 0.f) - x0 * x0 * g_S[e];
    }
}

// fused NS step: Xn = 2X - (X S) X  (one kernel per step, 2 rows per block)
__global__ void __launch_bounds__(256)
ns_step(const float* __restrict__ X, float* __restrict__ Xn) {
    __shared__ float xr[2][128];
    __shared__ float t[2][128];
    int tid = threadIdx.x;
    int r0 = blockIdx.x * 2;
    int rr = tid >> 7, j = tid & 127;
    xr[rr][j] = X[(r0 + rr) * 128 + j];
    __syncthreads();
    float acc = 0.f;
#pragma unroll 8
    for (int k = 0; k < 128; k++)
        acc = fmaf(xr[rr][k], g_S[k * 128 + j], acc);
    t[rr][j] = acc;
    __syncthreads();
    float acc2 = 0.f;
#pragma unroll 8
    for (int k = 0; k < 128; k++)
        acc2 = fmaf(t[rr][k], X[k * 128 + j], acc2);
    Xn[(r0 + rr) * 128 + j] = 2.f * xr[rr][j] - acc2;
}

// fused: blocks 0-127 -> HT rows; blocks 128-255 -> d (Sinv @ c) groups
__global__ void HT_d(const float* __restrict__ Sinv,
                     const float* __restrict__ log_rho) {
    int tid = threadIdx.x;
    if (blockIdx.x < 128) {
        __shared__ float gk[128];
        int j = tid, k = blockIdx.x;
        float rho = expf(log_rho[0]);
        gk[j] = g_G[k * 128 + j];
        __syncthreads();
        float acc = 0.f;
#pragma unroll 4
        for (int m = 0; m < 128; m++)
            acc = fmaf(Sinv[m * 128 + j], gk[m], acc);
        g_HT[k * 128 + j] = rho * (((j == k) ? 1.f : 0.f) - acc);
    } else {
        __shared__ float cb[8][128];
        int b0 = (blockIdx.x - 128) * 8;
#pragma unroll
        for (int bb = 0; bb < 8; bb++) {
            int b = b0 + bb, j = tid;
            float pa = g_R[(size_t)(2 * b) * TM2 + j];
            float pb = g_R[(size_t)(2 * b + 1) * TM2 + (j ^ 64)];
            cb[bb][j] = (j < 64) ? pa - pb : pa + pb;
        }
        __syncthreads();
        float acc[8];
#pragma unroll
        for (int bb = 0; bb < 8; bb++) acc[bb] = 0.f;
        for (int k = 0; k < 128; k++) {
            float sv = Sinv[k * 128 + tid];
#pragma unroll
            for (int bb = 0; bb < 8; bb++) acc[bb] = fmaf(sv, cb[bb][k], acc[bb]);
        }
#pragma unroll
        for (int bb = 0; bb < 8; bb++)
            g_d[(b0 + bb) * TM2 + tid] = acc[bb];
    }
}

// s for iter 0 (frag output): w = y - u_in; s = H w - d; init g_u
__global__ void s_init(const float* __restrict__ y,
                       const float* __restrict__ u_in) {
    __shared__ float w[8][128];
    int tid = threadIdx.x;
    int b0 = blockIdx.x * 8;
#pragma unroll
    for (int bb = 0; bb < 8; bb++) {
        float uv = u_in[(b0 + bb) * TM2 + tid];
        g_u[(b0 + bb) * TM2 + tid] = uv;
        w[bb][tid] = y[(b0 + bb) * TM2 + tid] - uv;
    }
    __syncthreads();
    float acc[8];
#pragma unroll
    for (int bb = 0; bb < 8; bb++) acc[bb] = 0.f;
    for (int k = 0; k < 128; k++) {
        float h = g_HT[k * 128 + tid];
#pragma unroll
        for (int bb = 0; bb < 8; bb++) acc[bb] = fmaf(h, w[bb][k], acc[bb]);
    }
    __syncthreads();
#pragma unroll
    for (int bb = 0; bb < 8; bb++)
        w[bb][tid] = acc[bb] - g_d[(b0 + bb) * TM2 + tid];
    __syncthreads();
    if (tid < 64) {
#pragma unroll
        for (int bb = 0; bb < 8; bb++) {
            int b = b0 + bb;
            int row = b & 127, rtile = b >> 7, kp = tid;
            float s0 = w[bb][2 * kp], s1 = w[bb][2 * kp + 1];
            float h0 = __bfloat162float(__float2bfloat16(s0));
            float h1 = __bfloat162float(__float2bfloat16(s1));
            uint32_t ad = (uint32_t)rtile * 8192 + a_addr(row, kp);
            g_sfh[ad] = pack_bf16x2(s0, s1);
            g_sfl[ad] = pack_bf16x2(s0 - h0, s1 - h1);
        }
    }
}

// fused: P = reduce(partials); zu update; s(frag) for next iter / final u out
__global__ void zus(const float* __restrict__ y,
                    const float* __restrict__ log_eps, int compute_s,
                    float* __restrict__ uout) {
    __shared__ float red[4];
    __shared__ float w[128];
    int b = blockIdx.x;
    int j = threadIdx.x;    // 128
    float eps = expf(log_eps[0]);
    float Pv = 0.f;
#pragma unroll
    for (int ks = 0; ks < NSPLIT; ks++)
        Pv += g_part[((size_t)ks * BATCH + b) * TM2 + j];
    float uv = g_u[b * TM2 + j];
    float yv = y[b * TM2 + j];
    float v = Pv + uv - yv;
    float t = v * v;
#pragma unroll
    for (int o = 16; o > 0; o >>= 1) t += __shfl_down_sync(0xffffffffu, t, o);
    if ((j & 31) == 0) red[j >> 5] = t;
    __syncthreads();
    float nrm = sqrtf(red[0] + red[1] + red[2] + red[3]);
    float scale = fminf(1.f, eps / (nrm + 1e-12f));
    float zv = yv + v * scale;
    float un = uv + Pv - zv;
    if (compute_s) {
        g_u[b * TM2 + j] = un;
        w[j] = zv - un;
        __syncthreads();
        float acc = 0.f;
#pragma unroll 4
        for (int k = 0; k < 128; k++)
            acc = fmaf(g_HT[k * 128 + j], w[k], acc);
        float sval = acc - g_d[b * TM2 + j];
        __syncthreads();
        w[j] = sval;
        __syncthreads();
        if (j < 64) {
            int row = b & 127, rtile = b >> 7, kp = j;
            float s0 = w[2 * kp], s1 = w[2 * kp + 1];
            float h0 = __bfloat162float(__float2bfloat16(s0));
            float h1 = __bfloat162float(__float2bfloat16(s1));
            uint32_t ad = (uint32_t)rtile * 8192 + a_addr(row, kp);
            g_sfh[ad] = pack_bf16x2(s0, s1);
            g_sfl[ad] = pack_bf16x2(s0 - h0, s1 - h1);
        }
    } else {
        uout[(size_t)BATCH * 2 * NDIM + b * TM2 + j] = un;
    }
}

// ---------------- launch ----------------------------------------------------
extern "C" void kernel_launch(void* const* d_in, const int* in_sizes, int n_in,
                              void* d_out, int out_size) {
    const float* rn   = (const float*)d_in[0];
    const float* y    = (const float*)d_in[1];
    const float* u_in = (const float*)d_in[2];
    const float* A    = (const float*)d_in[3];
    const float* lrho = (const float*)d_in[4];
    const float* leps = (const float*)d_in[5];
    float* out = (float*)d_out;
    (void)in_sizes; (void)n_in; (void)out_size;

    float *dM, *dR, *dPart, *dNSa, *dNSb;
    cudaGetSymbolAddress((void**)&dM,    g_M);
    cudaGetSymbolAddress((void**)&dR,    g_R);
    cudaGetSymbolAddress((void**)&dPart, g_part);
    cudaGetSymbolAddress((void**)&dNSa,  g_NSa);
    cudaGetSymbolAddress((void**)&dNSb,  g_NSb);

    static int attr_set = 0;
    if (!attr_set) {
        cudaFuncSetAttribute(mma_nt, cudaFuncAttributeMaxDynamicSharedMemorySize,
                             OLD_SMEM_BYTES);
        cudaFuncSetAttribute(mma_nn2, cudaFuncAttributeMaxDynamicSharedMemorySize,
                             NEW_SMEM_BYTES);
        cudaFuncSetAttribute(mma_nt2, cudaFuncAttributeMaxDynamicSharedMemorySize,
                             NEW_SMEM_BYTES);
        attr_set = 1;
    }

    // W precomputes: k-major split (setup), nn/nt fragment layouts (loop)
    conv_W<<<(TM2 * NDIM + 255) / 256, 256>>>(A);
    wf_nn<<<(8192 * 64 + 255) / 256, 256>>>(A);
    wf_nt<<<(128 * 4096 + 255) / 256, 256>>>(A);

    // M = W W^T, then S
    mma_nt<<<dim3(1, 64), 512, OLD_SMEM_BYTES>>>(A, NDIM, dPart, 128, 128);
    reduce_nt<<<(128 * 32 + 255) / 256, 256>>>((const float4*)dPart,
                                               (float4*)dM, 128 * 32, 64);
    build_S<<<64, 256>>>(lrho);

    // Newton-Schulz inverse: X1 + 3 fused steps (residual ~1e-12)
    gersh_initX1<<<1, 128>>>();
    ns_step<<<64, 256>>>(dNSa, dNSb);
    ns_step<<<64, 256>>>(dNSb, dNSa);
    ns_step<<<64, 256>>>(dNSa, dNSb);
    const float* Sinv = dNSb;

    // rn projections (2048 rows), then fused HT + d, then s for iter 0
    mma_nt<<<dim3(16, NSPLIT), 512, OLD_SMEM_BYTES>>>(rn, NDIM, dPart, 2048,
                                                      KCHUNK);
    reduce_nt<<<(2048 * 32 + 255) / 256, 256>>>((const float4*)dPart,
                                                (float4*)dR, 2048 * 32, NSPLIT);
    HT_d<<<256, 128>>>(Sinv, lrho);
    s_init<<<128, 128>>>(y, u_in);

    for (int it = 0; it < 3; it++) {
        int fin = (it == 2);
        mma_nn2<<<dim3(128, 8), 256, NEW_SMEM_BYTES>>>(rn, out, fin);
        mma_nt2<<<dim3(8, NSPLIT, 2), 256, NEW_SMEM_BYTES>>>(dPart);
        zus<<<BATCH, 128>>>(y, leps, it < 2, out);
    }
}

// round 13
// speedup vs baseline: 9.7835x; 1.0165x over previous
#include <cuda_runtime.h>
#include <cuda_bf16.h>
#include <math.h>
#include <stdint.h>

#define BATCH 1024
#define NDIM  8192
#define TM2   128
#define NSPLIT 16                 // loop nt split

// loop/nt kernel smem: two 48KB buffers (A 32KB + B 16KB each) = 96KB
#define NT_SMEM_BYTES 98304
#define NN_SMEM_BYTES 98304
#define AF_SMEM_BYTES 65536

// ---------------- scratch (static device globals; no runtime alloc) --------
__device__ float g_part[(size_t)8 * 2048 * TM2];     // 8MB (max of all users)
__device__ float g_d [BATCH * TM2];
__device__ float g_u [BATCH * TM2];
__device__ float g_M   [TM2 * TM2];
__device__ float g_G   [TM2 * TM2];
__device__ float g_S   [TM2 * TM2];
__device__ float g_NSa [TM2 * TM2];
__device__ float g_NSb [TM2 * TM2];
__device__ float g_HT  [TM2 * TM2];
// fragment-order operand stores (u32 = bf16x2)
__device__ uint32_t g_sfh[8 * 8192];                 // s A-frags [rtile][8192]
__device__ uint32_t g_sfl[8 * 8192];
__device__ uint32_t g_Xfh[(size_t)8 * 64 * 8192];    // X A-frags [rtile][ksub]
__device__ uint32_t g_Xfl[(size_t)8 * 64 * 8192];
__device__ uint32_t g_rnfh[(size_t)16 * 64 * 8192];  // rn A-frags [rtile][ksub]
__device__ uint32_t g_rnfl[(size_t)16 * 64 * 8192];
__device__ uint32_t g_Wafh[64 * 8192];               // W A-frags [ksub]
__device__ uint32_t g_Wafl[64 * 8192];
__device__ uint32_t g_Wnfh[128 * 4096];              // nn B-frags [nblk]
__device__ uint32_t g_Wnfl[128 * 4096];
__device__ uint32_t g_Wtfh[64 * 2 * 4096];           // nt B-frags [ksub][jblk]
__device__ uint32_t g_Wtfl[64 * 2 * 4096];

// ---------------- helpers ----------------------------------------------------
__device__ __forceinline__ uint32_t pack_bf16x2(float a, float b) {
    uint32_t lo = (uint32_t)__bfloat16_as_ushort(__float2bfloat16(a));
    uint32_t hi = (uint32_t)__bfloat16_as_ushort(__float2bfloat16(b));
    return lo | (hi << 16);
}
__device__ __forceinline__ void mma16816(float* c, const uint4& a,
                                         const uint2& b) {
    asm("mma.sync.aligned.m16n8k16.row.col.f32.bf16.bf16.f32 "
        "{%0,%1,%2,%3}, {%4,%5,%6,%7}, {%8,%9}, {%0,%1,%2,%3};"
        : "+f"(c[0]), "+f"(c[1]), "+f"(c[2]), "+f"(c[3])
        : "r"(a.x), "r"(a.y), "r"(a.z), "r"(a.w), "r"(b.x), "r"(b.y));
}
__device__ __forceinline__ uint32_t a_addr(int row, int kp) {
    uint32_t tile = (uint32_t)((row >> 4) * 8 + (kp >> 3));
    uint32_t lane = ((row & 7) << 2) + (kp & 3);
    uint32_t reg = ((row >> 3) & 1) | (((kp >> 2) & 1) << 1);
    return tile * 128 + lane * 4 + reg;
}
__device__ __forceinline__ uint32_t b_addr(int n, int kp) {
    uint32_t tile = (uint32_t)((n >> 3) * 8 + (kp >> 3));
    uint32_t lane = ((n & 7) << 2) + (kp & 3);
    uint32_t reg = (kp >> 2) & 1;
    return tile * 64 + lane * 2 + reg;
}
__device__ __forceinline__ uint32_t smem_u32(const void* p) {
    uint32_t a;
    asm("{ .reg .u64 t; cvta.to.shared.u64 t, %1; cvt.u32.u64 %0, t; }"
        : "=r"(a) : "l"(p));
    return a;
}
__device__ __forceinline__ void cp16(uint32_t saddr, const void* g) {
    asm volatile("cp.async.cg.shared.global [%0], [%1], 16;"
                 :: "r"(saddr), "l"(g));
}

// ============================================================================
// nt2: part[split][r][j] = sum_{k in chunk} A[r,k] * W[j,k]
// A/B in fragment order; cp.async double-buffered 32-kp halves.
// grid (rtiles, nsplit, 2), 256 threads, 2 blocks/SM.
// ============================================================================
__global__ void __launch_bounds__(256, 2)
nt2(const uint32_t* __restrict__ Afh, const uint32_t* __restrict__ Afl,
    float* __restrict__ part, int rows, int nsubs) {
    extern __shared__ uint32_t sm[];
    uint32_t sb = smem_u32(sm);
    const uint4* sA4h = (const uint4*)sm;              // [2][1024] uint4
    const uint4* sA4l = (const uint4*)(sm + 8192);
    const uint2* sB2h = (const uint2*)(sm + 16384);    // [2][1024] uint2
    const uint2* sB2l = (const uint2*)(sm + 20480);
    int tid = threadIdx.x;
    int lane = tid & 31, wid = tid >> 5;
    int wr = wid >> 1, wc = wid & 1;
    int rtile = blockIdx.x;
    int split = blockIdx.y;
    int jblk  = blockIdx.z;
    int r0 = rtile * 128;
    int q = lane & 3, g = lane >> 2;
    int H = nsubs * 2;

    float acc[2][4][4];
#pragma unroll
    for (int mt = 0; mt < 2; mt++)
#pragma unroll
        for (int nt = 0; nt < 4; nt++)
#pragma unroll
            for (int e = 0; e < 4; e++) acc[mt][nt][e] = 0.f;

    // fill lambda (macro-style): half h into buffer h&1
#define NT2_FILL(h)                                                           \
    do {                                                                      \
        int ksub_ = split * nsubs + ((h) >> 1);                               \
        int s0_ = ((h) & 1) * 4;                                              \
        int buf_ = (h) & 1;                                                   \
        const uint4* gAh4 = (const uint4*)Afh                                 \
                            + ((size_t)rtile * 64 + ksub_) * 2048;            \
        const uint4* gAl4 = (const uint4*)Afl                                 \
                            + ((size_t)rtile * 64 + ksub_) * 2048;            \
        const uint4* gBh4 = (const uint4*)g_Wtfh                              \
                            + ((size_t)ksub_ * 2 + jblk) * 1024;              \
        const uint4* gBl4 = (const uint4*)g_Wtfl                              \
                            + ((size_t)ksub_ * 2 + jblk) * 1024;              \
        _Pragma("unroll")                                                     \
        for (int j_ = 0; j_ < 4; j_++) {                                      \
            int i_ = tid + j_ * 256;                                          \
            int seg_ = i_ >> 5, e_ = i_ & 31;                                 \
            int rg_ = seg_ >> 2, tl_ = seg_ & 3;                              \
            const uint4* sh_ = gAh4 + (rg_ * 8 + s0_ + tl_) * 32 + e_;        \
            const uint4* sl_ = gAl4 + (rg_ * 8 + s0_ + tl_) * 32 + e_;        \
            cp16(sb + buf_ * 16384 + i_ * 16, sh_);                           \
            cp16(sb + 32768 + buf_ * 16384 + i_ * 16, sl_);                   \
        }                                                                     \
        _Pragma("unroll")                                                     \
        for (int j_ = 0; j_ < 2; j_++) {                                      \
            int i_ = tid + j_ * 256;                                          \
            int seg_ = i_ >> 4, e_ = i_ & 15;                                 \
            int ng_ = seg_ >> 2, tl_ = seg_ & 3;                              \
            const uint4* sh_ = gBh4 + (ng_ * 8 + s0_ + tl_) * 16 + e_;        \
            const uint4* sl_ = gBl4 + (ng_ * 8 + s0_ + tl_) * 16 + e_;        \
            cp16(sb + 65536 + buf_ * 8192 + i_ * 16, sh_);                    \
            cp16(sb + 81920 + buf_ * 8192 + i_ * 16, sl_);                    \
        }                                                                     \
        asm volatile("cp.async.commit_group;" ::: "memory");                  \
    } while (0)

    NT2_FILL(0);
    for (int h = 0; h < H; h++) {
        if (h + 1 < H) {
            NT2_FILL(h + 1);
            asm volatile("cp.async.wait_group 1;" ::: "memory");
        } else {
            asm volatile("cp.async.wait_group 0;" ::: "memory");
        }
        __syncthreads();
        int buf = h & 1;
#pragma unroll
        for (int s = 0; s < 4; s++) {
            uint4 ah[2], al[2];
            uint2 bh[4], bl[4];
#pragma unroll
            for (int mt = 0; mt < 2; mt++) {
                uint32_t i4 = (uint32_t)(buf * 1024
                               + ((wr * 2 + mt) * 4 + s) * 32 + lane);
                ah[mt] = sA4h[i4];
                al[mt] = sA4l[i4];
            }
#pragma unroll
            for (int nt = 0; nt < 4; nt++) {
                uint32_t i2 = (uint32_t)(buf * 1024
                               + ((wc * 4 + nt) * 4 + s) * 32 + lane);
                bh[nt] = sB2h[i2];
                bl[nt] = sB2l[i2];
            }
#pragma unroll
            for (int mt = 0; mt < 2; mt++)
#pragma unroll
                for (int nt = 0; nt < 4; nt++)
                    mma16816(acc[mt][nt], ah[mt], bh[nt]);
#pragma unroll
            for (int mt = 0; mt < 2; mt++)
#pragma unroll
                for (int nt = 0; nt < 4; nt++)
                    mma16816(acc[mt][nt], ah[mt], bl[nt]);
#pragma unroll
            for (int mt = 0; mt < 2; mt++)
#pragma unroll
                for (int nt = 0; nt < 4; nt++)
                    mma16816(acc[mt][nt], al[mt], bh[nt]);
        }
        __syncthreads();
    }
#undef NT2_FILL

    float* pb = part + ((size_t)split * rows + r0) * TM2;
#pragma unroll
    for (int mt = 0; mt < 2; mt++) {
        int row = wr * 32 + mt * 16 + g;
#pragma unroll
        for (int nt = 0; nt < 4; nt++) {
            int col = jblk * 64 + wc * 32 + nt * 8 + 2 * q;
            *(float2*)&pb[(size_t)row * TM2 + col] =
                make_float2(acc[mt][nt][0], acc[mt][nt][1]);
            *(float2*)&pb[(size_t)(row + 8) * TM2 + col] =
                make_float2(acc[mt][nt][2], acc[mt][nt][3]);
        }
    }
}

// deterministic fixed-order split reduction (for W W^T only)
__global__ void reduce_nt(const float4* __restrict__ part,
                          float4* __restrict__ out, int count4, int nsplit) {
    int i = blockIdx.x * 256 + threadIdx.x;
    if (i < count4) {
        float4 s = make_float4(0.f, 0.f, 0.f, 0.f);
        for (int k = 0; k < nsplit; k++) {
            float4 v = part[(size_t)k * count4 + i];
            s.x += v.x; s.y += v.y; s.z += v.z; s.w += v.w;
        }
        out[i] = s;
    }
}

// ============================================================================
// nn2: X[b,n] = relu(rn_r[b,n] + sum_k s[b,k] * W[k,n]); K = 128.
// grid (128, 8), 256 threads, copy fills, 2 blocks/SM.
// ============================================================================
__global__ void __launch_bounds__(256, 2)
mma_nn2(const float* __restrict__ rn, float* __restrict__ outx, int final_out) {
    extern __shared__ uint32_t sm[];
    uint32_t* sAh = sm;
    uint32_t* sAl = sm + 8192;
    uint32_t* sBh = sm + 16384;
    uint32_t* sBl = sm + 20480;
    int tid = threadIdx.x;
    int lane = tid & 31, wid = tid >> 5;
    int wr = wid >> 1, wc = wid & 1;
    int nblk = blockIdx.x;
    int rtile = blockIdx.y;
    int n0 = nblk * 64;
    int r0 = rtile * 128;
    int q = lane & 3, g = lane >> 2;

    {
        const uint4* gAh = (const uint4*)g_sfh + (size_t)rtile * 2048;
        const uint4* gAl = (const uint4*)g_sfl + (size_t)rtile * 2048;
        const uint4* gBh = (const uint4*)g_Wnfh + (size_t)nblk * 1024;
        const uint4* gBl = (const uint4*)g_Wnfl + (size_t)nblk * 1024;
#pragma unroll
        for (int i = 0; i < 8; i++) {
            ((uint4*)sAh)[tid + i * 256] = gAh[tid + i * 256];
            ((uint4*)sAl)[tid + i * 256] = gAl[tid + i * 256];
        }
#pragma unroll
        for (int i = 0; i < 4; i++) {
            ((uint4*)sBh)[tid + i * 256] = gBh[tid + i * 256];
            ((uint4*)sBl)[tid + i * 256] = gBl[tid + i * 256];
        }
    }
    __syncthreads();

    float acc[2][4][4];
#pragma unroll
    for (int mt = 0; mt < 2; mt++)
#pragma unroll
        for (int nt = 0; nt < 4; nt++)
#pragma unroll
            for (int e = 0; e < 4; e++) acc[mt][nt][e] = 0.f;

#pragma unroll
    for (int s = 0; s < 8; s++) {
        uint4 ah[2], al[2];
        uint2 bh[4], bl[4];
#pragma unroll
        for (int mt = 0; mt < 2; mt++) {
            uint32_t i4 = (uint32_t)(((wr * 2 + mt) * 8 + s) * 32 + lane);
            ah[mt] = ((const uint4*)sAh)[i4];
            al[mt] = ((const uint4*)sAl)[i4];
        }
#pragma unroll
        for (int nt = 0; nt < 4; nt++) {
            uint32_t i2 = (uint32_t)(((wc * 4 + nt) * 8 + s) * 32 + lane);
            bh[nt] = ((const uint2*)sBh)[i2];
            bl[nt] = ((const uint2*)sBl)[i2];
        }
#pragma unroll
        for (int mt = 0; mt < 2; mt++)
#pragma unroll
            for (int nt = 0; nt < 4; nt++)
                mma16816(acc[mt][nt], ah[mt], bh[nt]);
#pragma unroll
        for (int mt = 0; mt < 2; mt++)
#pragma unroll
            for (int nt = 0; nt < 4; nt++)
                mma16816(acc[mt][nt], ah[mt], bl[nt]);
#pragma unroll
        for (int mt = 0; mt < 2; mt++)
#pragma unroll
            for (int nt = 0; nt < 4; nt++)
                mma16816(acc[mt][nt], al[mt], bh[nt]);
    }

    int ksub = nblk >> 1;
    uint32_t* gxh = g_Xfh + ((size_t)rtile * 64 + ksub) * 8192;
    uint32_t* gxl = g_Xfl + ((size_t)rtile * 64 + ksub) * 8192;
    float2 zero2 = make_float2(0.f, 0.f);
#pragma unroll
    for (int mt = 0; mt < 2; mt++) {
        int rowbase = wr * 32 + mt * 16 + g;
#pragma unroll
        for (int nt = 0; nt < 4; nt++) {
            int col = wc * 32 + nt * 8 + 2 * q;
            int kp = ((nblk & 1) << 5) + (col >> 1);
#pragma unroll
            for (int half = 0; half < 2; half++) {
                int row = rowbase + half * 8;
                int r = r0 + row;
                int n = n0 + col;
                float2 rv = *(const float2*)(rn + (size_t)r * (2 * NDIM) + n);
                float c0 = fmaxf(acc[mt][nt][half * 2 + 0] + rv.x, 0.f);
                float c1 = fmaxf(acc[mt][nt][half * 2 + 1] + rv.y, 0.f);
                float h0 = __bfloat162float(__float2bfloat16(c0));
                float h1 = __bfloat162float(__float2bfloat16(c1));
                uint32_t ad = a_addr(row, kp);
                gxh[ad] = pack_bf16x2(c0, c1);
                gxl[ad] = pack_bf16x2(c0 - h0, c1 - h1);
                if (final_out) {
                    size_t base = (size_t)r * (2 * NDIM);
                    *(float2*)(outx + base + n) = make_float2(c0, c1);
                    *(float2*)(outx + base + NDIM + n) = zero2;
                }
            }
        }
    }
}

// ---------------- fp32 -> A-fragment conversion (smem-staged) ---------------
// grid (rtiles, 64), 256 threads; src row-major ld = NDIM
__global__ void to_afrag(const float* __restrict__ src,
                         uint32_t* __restrict__ dfh,
                         uint32_t* __restrict__ dfl) {
    extern __shared__ uint32_t sm[];
    uint32_t* sh = sm;
    uint32_t* sl = sm + 8192;
    int tid = threadIdx.x;
    int rtile = blockIdx.x, ksub = blockIdx.y;
#pragma unroll
    for (int i = 0; i < 32; i++) {
        int idx = tid + i * 256;
        int rowl = idx >> 6, kpl = idx & 63;
        float2 v = *(const float2*)(src
                    + (size_t)(rtile * 128 + rowl) * NDIM + ksub * 128 + 2 * kpl);
        float h0 = __bfloat162float(__float2bfloat16(v.x));
        float h1 = __bfloat162float(__float2bfloat16(v.y));
        uint32_t ad = a_addr(rowl, kpl);
        sh[ad] = pack_bf16x2(v.x, v.y);
        sl[ad] = pack_bf16x2(v.x - h0, v.y - h1);
    }
    __syncthreads();
    size_t base = ((size_t)rtile * 64 + ksub) * 2048;
#pragma unroll
    for (int i = 0; i < 8; i++) {
        ((uint4*)dfh)[base + tid + i * 256] = ((const uint4*)sh)[tid + i * 256];
        ((uint4*)dfl)[base + tid + i * 256] = ((const uint4*)sl)[tid + i * 256];
    }
}

// ---------------- W B-fragment precomputes ----------------------------------
__global__ void wf_nn(const float* __restrict__ W) {
    int idx = blockIdx.x * 256 + threadIdx.x;
    if (idx < 8192 * 64) {
        int n = idx >> 6, kp = idx & 63;
        float v0 = W[(size_t)(2 * kp) * NDIM + n];
        float v1 = W[(size_t)(2 * kp + 1) * NDIM + n];
        float h0 = __bfloat162float(__float2bfloat16(v0));
        float h1 = __bfloat162float(__float2bfloat16(v1));
        int nblk = n >> 6, nl = n & 63;
        uint32_t ad = (uint32_t)nblk * 4096 + b_addr(nl, kp);
        g_Wnfh[ad] = pack_bf16x2(v0, v1);
        g_Wnfl[ad] = pack_bf16x2(v0 - h0, v1 - h1);
    }
}
__global__ void wf_nt(const float* __restrict__ W) {
    int idx = blockIdx.x * 256 + threadIdx.x;
    if (idx < 128 * 4096) {
        int j = idx >> 12, k2 = idx & 4095;
        float v0 = W[(size_t)j * NDIM + 2 * k2];
        float v1 = W[(size_t)j * NDIM + 2 * k2 + 1];
        float h0 = __bfloat162float(__float2bfloat16(v0));
        float h1 = __bfloat162float(__float2bfloat16(v1));
        int ksub = k2 >> 6, kpl = k2 & 63;
        int jblk = j >> 6, jl = j & 63;
        uint32_t ad = (uint32_t)(ksub * 2 + jblk) * 4096 + b_addr(jl, kpl);
        g_Wtfh[ad] = pack_bf16x2(v0, v1);
        g_Wtfl[ad] = pack_bf16x2(v0 - h0, v1 - h1);
    }
}

// ---------------- build G and S = G + I/rho ---------------------------------
__global__ void build_S(const float* __restrict__ log_rho) {
    int idx = blockIdx.x * blockDim.x + threadIdx.x;
    float inv_rho = 1.f / (expf(log_rho[0]) + 1e-12f);
    int p = idx >> 7, q = idx & 127;
    float sgn = ((p < 64) == (q < 64)) ? 1.f : -1.f;
    float g = g_M[idx] + sgn * g_M[((p ^ 64) << 7) + (q ^ 64)];
    g_G[idx] = g;
    g_S[idx] = g + ((p == q) ? inv_rho : 0.f);
}

// ---------------- Newton-Schulz inverse -------------------------------------
__global__ void gersh_initX1() {
    __shared__ float smax[4], smin[4], s_x0;
    int i = threadIdx.x;
    float rs = 0.f, dg = 0.f;
#pragma unroll 8
    for (int k = 0; k < 128; k++) {
        float v = g_S[i * 128 + k];
        rs += fabsf(v);
        if (k == i) dg = v;
    }
    float lo = 2.f * dg - rs;
    float mx = rs, mn = lo;
#pragma unroll
    for (int o = 16; o > 0; o >>= 1) {
        mx = fmaxf(mx, __shfl_down_sync(0xffffffffu, mx, o));
        mn = fminf(mn, __shfl_down_sync(0xffffffffu, mn, o));
    }
    if ((i & 31) == 0) { smax[i >> 5] = mx; smin[i >> 5] = mn; }
    __syncthreads();
    if (i == 0) {
        float lmax = fmaxf(fmaxf(smax[0], smax[1]), fmaxf(smax[2], smax[3]));
        float lmin = fminf(fminf(smin[0], smin[1]), fminf(smin[2], smin[3]));
        s_x0 = (lmin > 0.f) ? 2.f / (lmax + lmin) : 1.f / lmax;
    }
    __syncthreads();
    float x0 = s_x0;
    for (int e = i; e < 128 * 128; e += 128) {
        int p = e >> 7, q = e & 127;
        g_NSa[e] = 2.f * x0 * ((p == q) ? 1.f : 0.f) - x0 * x0 * g_S[e];
    }
}
__global__ void __launch_bounds__(256)
ns_step(const float* __restrict__ X, float* __restrict__ Xn) {
    __shared__ float xr[2][128];
    __shared__ float t[2][128];
    int tid = threadIdx.x;
    int r0 = blockIdx.x * 2;
    int rr = tid >> 7, j = tid & 127;
    xr[rr][j] = X[(r0 + rr) * 128 + j];
    __syncthreads();
    float acc = 0.f;
#pragma unroll 8
    for (int k = 0; k < 128; k++)
        acc = fmaf(xr[rr][k], g_S[k * 128 + j], acc);
    t[rr][j] = acc;
    __syncthreads();
    float acc2 = 0.f;
#pragma unroll 8
    for (int k = 0; k < 128; k++)
        acc2 = fmaf(t[rr][k], X[k * 128 + j], acc2);
    Xn[(r0 + rr) * 128 + j] = 2.f * xr[rr][j] - acc2;
}

// fused: blocks 0-127 -> HT rows; blocks 128-255 -> d = Sinv @ c
// (c assembled from rn-projection partials, 8-way split summed in-place)
__global__ void HT_d(const float* __restrict__ Sinv,
                     const float* __restrict__ log_rho) {
    int tid = threadIdx.x;
    if (blockIdx.x < 128) {
        __shared__ float gk[128];
        int j = tid, k = blockIdx.x;
        float rho = expf(log_rho[0]);
        gk[j] = g_G[k * 128 + j];
        __syncthreads();
        float acc = 0.f;
#pragma unroll 4
        for (int m = 0; m < 128; m++)
            acc = fmaf(Sinv[m * 128 + j], gk[m], acc);
        g_HT[k * 128 + j] = rho * (((j == k) ? 1.f : 0.f) - acc);
    } else {
        __shared__ float cb[8][128];
        int b0 = (blockIdx.x - 128) * 8;
#pragma unroll
        for (int bb = 0; bb < 8; bb++) {
            int b = b0 + bb;
            float pa = 0.f, pbv = 0.f;
#pragma unroll
            for (int sp = 0; sp < 8; sp++) {
                pa  += g_part[((size_t)sp * 2048 + 2 * b) * TM2 + tid];
                pbv += g_part[((size_t)sp * 2048 + 2 * b + 1) * TM2 + (tid ^ 64)];
            }
            cb[bb][tid] = (tid < 64) ? pa - pbv : pa + pbv;
        }
        __syncthreads();
        float acc[8];
#pragma unroll
        for (int bb = 0; bb < 8; bb++) acc[bb] = 0.f;
        for (int k = 0; k < 128; k++) {
            float sv = Sinv[k * 128 + tid];
#pragma unroll
            for (int bb = 0; bb < 8; bb++) acc[bb] = fmaf(sv, cb[bb][k], acc[bb]);
        }
#pragma unroll
        for (int bb = 0; bb < 8; bb++)
            g_d[(b0 + bb) * TM2 + tid] = acc[bb];
    }
}

// s for iter 0: w = y - u_in; s = H w - d (frag output); init g_u
__global__ void s_init(const float* __restrict__ y,
                       const float* __restrict__ u_in) {
    __shared__ float w[8][128];
    int tid = threadIdx.x;
    int b0 = blockIdx.x * 8;
#pragma unroll
    for (int bb = 0; bb < 8; bb++) {
        float uv = u_in[(b0 + bb) * TM2 + tid];
        g_u[(b0 + bb) * TM2 + tid] = uv;
        w[bb][tid] = y[(b0 + bb) * TM2 + tid] - uv;
    }
    __syncthreads();
    float acc[8];
#pragma unroll
    for (int bb = 0; bb < 8; bb++) acc[bb] = 0.f;
    for (int k = 0; k < 128; k++) {
        float h = g_HT[k * 128 + tid];
#pragma unroll
        for (int bb = 0; bb < 8; bb++) acc[bb] = fmaf(h, w[bb][k], acc[bb]);
    }
    __syncthreads();
#pragma unroll
    for (int bb = 0; bb < 8; bb++)
        w[bb][tid] = acc[bb] - g_d[(b0 + bb) * TM2 + tid];
    __syncthreads();
    if (tid < 64) {
#pragma unroll
        for (int bb = 0; bb < 8; bb++) {
            int b = b0 + bb;
            int row = b & 127, rtile = b >> 7, kp = tid;
            float s0 = w[bb][2 * kp], s1 = w[bb][2 * kp + 1];
            float h0 = __bfloat162float(__float2bfloat16(s0));
            float h1 = __bfloat162float(__float2bfloat16(s1));
            uint32_t ad = (uint32_t)rtile * 8192 + a_addr(row, kp);
            g_sfh[ad] = pack_bf16x2(s0, s1);
            g_sfl[ad] = pack_bf16x2(s0 - h0, s1 - h1);
        }
    }
}

// fused: P = reduce(partials); zu update; s(frag) for next iter / final u out
__global__ void zus(const float* __restrict__ y,
                    const float* __restrict__ log_eps, int compute_s,
                    float* __restrict__ uout) {
    __shared__ float red[4];
    __shared__ float w[128];
    int b = blockIdx.x;
    int j = threadIdx.x;
    float eps = expf(log_eps[0]);
    float Pv = 0.f;
#pragma unroll
    for (int ks = 0; ks < NSPLIT; ks++)
        Pv += g_part[((size_t)ks * BATCH + b) * TM2 + j];
    float uv = g_u[b * TM2 + j];
    float yv = y[b * TM2 + j];
    float v = Pv + uv - yv;
    float t = v * v;
#pragma unroll
    for (int o = 16; o > 0; o >>= 1) t += __shfl_down_sync(0xffffffffu, t, o);
    if ((j & 31) == 0) red[j >> 5] = t;
    __syncthreads();
    float nrm = sqrtf(red[0] + red[1] + red[2] + red[3]);
    float scale = fminf(1.f, eps / (nrm + 1e-12f));
    float zv = yv + v * scale;
    float un = uv + Pv - zv;
    if (compute_s) {
        g_u[b * TM2 + j] = un;
        w[j] = zv - un;
        __syncthreads();
        float acc = 0.f;
#pragma unroll 4
        for (int k = 0; k < 128; k++)
            acc = fmaf(g_HT[k * 128 + j], w[k], acc);
        float sval = acc - g_d[b * TM2 + j];
        __syncthreads();
        w[j] = sval;
        __syncthreads();
        if (j < 64) {
            int row = b & 127, rtile = b >> 7, kp = j;
            float s0 = w[2 * kp], s1 = w[2 * kp + 1];
            float h0 = __bfloat162float(__float2bfloat16(s0));
            float h1 = __bfloat162float(__float2bfloat16(s1));
            uint32_t ad = (uint32_t)rtile * 8192 + a_addr(row, kp);
            g_sfh[ad] = pack_bf16x2(s0, s1);
            g_sfl[ad] = pack_bf16x2(s0 - h0, s1 - h1);
        }
    } else {
        uout[(size_t)BATCH * 2 * NDIM + b * TM2 + j] = un;
    }
}

// ---------------- launch ----------------------------------------------------
extern "C" void kernel_launch(void* const* d_in, const int* in_sizes, int n_in,
                              void* d_out, int out_size) {
    const float* rn   = (const float*)d_in[0];
    const float* y    = (const float*)d_in[1];
    const float* u_in = (const float*)d_in[2];
    const float* A    = (const float*)d_in[3];
    const float* lrho = (const float*)d_in[4];
    const float* leps = (const float*)d_in[5];
    float* out = (float*)d_out;
    (void)in_sizes; (void)n_in; (void)out_size;

    float *dM, *dPart, *dNSa, *dNSb;
    uint32_t *dWafh, *dWafl, *drnfh, *drnfl, *dXfh, *dXfl;
    cudaGetSymbolAddress((void**)&dM,    g_M);
    cudaGetSymbolAddress((void**)&dPart, g_part);
    cudaGetSymbolAddress((void**)&dNSa,  g_NSa);
    cudaGetSymbolAddress((void**)&dNSb,  g_NSb);
    cudaGetSymbolAddress((void**)&dWafh, g_Wafh);
    cudaGetSymbolAddress((void**)&dWafl, g_Wafl);
    cudaGetSymbolAddress((void**)&drnfh, g_rnfh);
    cudaGetSymbolAddress((void**)&drnfl, g_rnfl);
    cudaGetSymbolAddress((void**)&dXfh,  g_Xfh);
    cudaGetSymbolAddress((void**)&dXfl,  g_Xfl);

    static int attr_set = 0;
    if (!attr_set) {
        cudaFuncSetAttribute(nt2, cudaFuncAttributeMaxDynamicSharedMemorySize,
                             NT_SMEM_BYTES);
        cudaFuncSetAttribute(mma_nn2,
                             cudaFuncAttributeMaxDynamicSharedMemorySize,
                             NN_SMEM_BYTES);
        cudaFuncSetAttribute(to_afrag,
                             cudaFuncAttributeMaxDynamicSharedMemorySize,
                             AF_SMEM_BYTES);
        attr_set = 1;
    }

    // W fragment layouts + A-frag conversions
    wf_nn<<<(8192 * 64 + 255) / 256, 256>>>(A);
    wf_nt<<<(128 * 4096 + 255) / 256, 256>>>(A);
    to_afrag<<<dim3(1, 64), 256, AF_SMEM_BYTES>>>(A, dWafh, dWafl);
    to_afrag<<<dim3(16, 64), 256, AF_SMEM_BYTES>>>(rn, drnfh, drnfl);

    // M = W W^T (32-way split), then S
    nt2<<<dim3(1, 32, 2), 256, NT_SMEM_BYTES>>>(dWafh, dWafl, dPart, 128, 2);
    reduce_nt<<<(4096 + 255) / 256, 256>>>((const float4*)dPart,
                                           (float4*)dM, 4096, 32);
    build_S<<<64, 256>>>(lrho);

    // Newton-Schulz inverse: X1 + 3 fused steps
    gersh_initX1<<<1, 128>>>();
    ns_step<<<64, 256>>>(dNSa, dNSb);
    ns_step<<<64, 256>>>(dNSb, dNSa);
    ns_step<<<64, 256>>>(dNSa, dNSb);
    const float* Sinv = dNSb;

    // rn projections (2048 rows, 8-way split), fused HT + d, then s iter 0
    nt2<<<dim3(16, 8, 2), 256, NT_SMEM_BYTES>>>(drnfh, drnfl, dPart, 2048, 8);
    HT_d<<<256, 128>>>(Sinv, lrho);
    s_init<<<128, 128>>>(y, u_in);

    for (int it = 0; it < 3; it++) {
        int fin = (it == 2);
        mma_nn2<<<dim3(128, 8), 256, NN_SMEM_BYTES>>>(rn, out, fin);
        nt2<<<dim3(8, NSPLIT, 2), 256, NT_SMEM_BYTES>>>(dXfh, dXfl, dPart,
                                                        BATCH, 64 / NSPLIT);
        zus<<<BATCH, 128>>>(y, leps, it < 2, out);
    }
}